// round 1
// baseline (speedup 1.0000x reference)
#include <cuda_runtime.h>
#include <cuda_bf16.h>
#include <cstdint>

#define N_NODES 20000
#define F_DIM   512
#define H_DIM   128
#define C_DIM   64
#define N_EDGES 640000

// Scratch (static device globals; no runtime allocation allowed)
__device__ float g_emb1[9 * N_NODES * H_DIM];   // 92.16 MB: layer-1 embeddings, 9 combos
__device__ float g_acc1[3 * N_NODES * H_DIM];   // 30.72 MB: layer-1 accumulators -> h (after relu)
__device__ float g_emb2[9 * N_NODES * C_DIM];   // 46.08 MB: layer-2 embeddings
__device__ float g_acc2[3 * N_NODES * C_DIM];   // 15.36 MB: layer-2 accumulators

// combo -> which x / adjacency feeds it. combo = gc*3 + role.
__constant__ int c_perm[9] = {0,1,2, 1,0,2, 2,0,1};

// ---------------------------------------------------------------------------
// GEMM 1: g_emb1[b] (20000x128) = X[perm[b]] (20000x512) @ W1[b] (512x128)
// Block tile 64x128, BK=32, 256 threads, per-thread 8x4.
// ---------------------------------------------------------------------------
__global__ void gemm1_kernel(const float* __restrict__ x1,
                             const float* __restrict__ x2,
                             const float* __restrict__ x3,
                             const float* __restrict__ W1) {
    const int b = blockIdx.z;
    const int p = c_perm[b];
    const float* __restrict__ X = (p == 0) ? x1 : (p == 1) ? x2 : x3;
    const float* __restrict__ W = W1 + (size_t)b * F_DIM * H_DIM;
    float* __restrict__ Cout = g_emb1 + (size_t)b * N_NODES * H_DIM;

    __shared__ float As[32][64];
    __shared__ float Bs[32][128];

    const int tid = threadIdx.x;
    const int rowBase = blockIdx.x * 64;

    const int tn = tid & 31;   // col group: tn*4
    const int tm = tid >> 5;   // row group: tm*8

    float acc[8][4];
#pragma unroll
    for (int i = 0; i < 8; i++)
#pragma unroll
        for (int j = 0; j < 4; j++) acc[i][j] = 0.f;

    const int lm  = tid & 63;  // A load: row within tile
    const int lkg = tid >> 6;  // A load: k-group of 8
    const int bk  = tid >> 3;  // B load: k row (0..31)
    const int bng = tid & 7;   // B load: col group of 16

    for (int k0 = 0; k0 < F_DIM; k0 += 32) {
        int gr = rowBase + lm;
        if (gr >= N_NODES) gr = N_NODES - 1;  // clamp; stores are guarded
        const float* xp = X + (size_t)gr * F_DIM + k0 + lkg * 8;
        float4 a0 = *(const float4*)(xp);
        float4 a1 = *(const float4*)(xp + 4);
        const int kk = lkg * 8;
        As[kk + 0][lm] = a0.x; As[kk + 1][lm] = a0.y;
        As[kk + 2][lm] = a0.z; As[kk + 3][lm] = a0.w;
        As[kk + 4][lm] = a1.x; As[kk + 5][lm] = a1.y;
        As[kk + 6][lm] = a1.z; As[kk + 7][lm] = a1.w;

        const float* wp = W + (size_t)(k0 + bk) * H_DIM + bng * 16;
        float4 b0 = *(const float4*)(wp);
        float4 b1 = *(const float4*)(wp + 4);
        float4 b2 = *(const float4*)(wp + 8);
        float4 b3 = *(const float4*)(wp + 12);
        *(float4*)&Bs[bk][bng * 16 + 0]  = b0;
        *(float4*)&Bs[bk][bng * 16 + 4]  = b1;
        *(float4*)&Bs[bk][bng * 16 + 8]  = b2;
        *(float4*)&Bs[bk][bng * 16 + 12] = b3;
        __syncthreads();

#pragma unroll
        for (int k = 0; k < 32; k++) {
            float4 bv = *(const float4*)&Bs[k][tn * 4];
            float ar[8];
#pragma unroll
            for (int i = 0; i < 8; i++) ar[i] = As[k][tm * 8 + i];
#pragma unroll
            for (int i = 0; i < 8; i++) {
                acc[i][0] += ar[i] * bv.x;
                acc[i][1] += ar[i] * bv.y;
                acc[i][2] += ar[i] * bv.z;
                acc[i][3] += ar[i] * bv.w;
            }
        }
        __syncthreads();
    }

#pragma unroll
    for (int i = 0; i < 8; i++) {
        int r = rowBase + tm * 8 + i;
        if (r < N_NODES) {
            float4 v = make_float4(acc[i][0], acc[i][1], acc[i][2], acc[i][3]);
            *(float4*)&Cout[(size_t)r * H_DIM + tn * 4] = v;
        }
    }
}

// ---------------------------------------------------------------------------
// GEMM 2: g_emb2[b] (20000x64) = h[perm[b]] (20000x128) @ W2[b] (128x64)
// Block tile 64x64, BK=32, 256 threads, per-thread 4x4.
// ---------------------------------------------------------------------------
__global__ void gemm2_kernel(const float* __restrict__ W2) {
    const int b = blockIdx.z;
    const float* __restrict__ Hx = g_acc1 + (size_t)c_perm[b] * N_NODES * H_DIM;
    const float* __restrict__ W  = W2 + (size_t)b * H_DIM * C_DIM;
    float* __restrict__ Cout = g_emb2 + (size_t)b * N_NODES * C_DIM;

    __shared__ float As[32][64];
    __shared__ float Bs[32][64];

    const int tid = threadIdx.x;
    const int rowBase = blockIdx.x * 64;
    const int tn = tid & 15;   // cols tn*4
    const int tm = tid >> 4;   // rows tm*4

    float acc[4][4];
#pragma unroll
    for (int i = 0; i < 4; i++)
#pragma unroll
        for (int j = 0; j < 4; j++) acc[i][j] = 0.f;

    const int lm  = tid & 63;
    const int lkg = tid >> 6;
    const int bk  = tid >> 3;
    const int bng = tid & 7;   // col group of 8

    for (int k0 = 0; k0 < H_DIM; k0 += 32) {
        int gr = rowBase + lm;
        if (gr >= N_NODES) gr = N_NODES - 1;
        const float* xp = Hx + (size_t)gr * H_DIM + k0 + lkg * 8;
        float4 a0 = *(const float4*)(xp);
        float4 a1 = *(const float4*)(xp + 4);
        const int kk = lkg * 8;
        As[kk + 0][lm] = a0.x; As[kk + 1][lm] = a0.y;
        As[kk + 2][lm] = a0.z; As[kk + 3][lm] = a0.w;
        As[kk + 4][lm] = a1.x; As[kk + 5][lm] = a1.y;
        As[kk + 6][lm] = a1.z; As[kk + 7][lm] = a1.w;

        const float* wp = W + (size_t)(k0 + bk) * C_DIM + bng * 8;
        float4 b0 = *(const float4*)(wp);
        float4 b1 = *(const float4*)(wp + 4);
        *(float4*)&Bs[bk][bng * 8 + 0] = b0;
        *(float4*)&Bs[bk][bng * 8 + 4] = b1;
        __syncthreads();

#pragma unroll
        for (int k = 0; k < 32; k++) {
            float4 bv = *(const float4*)&Bs[k][tn * 4];
            float4 av = *(const float4*)&As[k][tm * 4];
            acc[0][0] += av.x * bv.x; acc[0][1] += av.x * bv.y; acc[0][2] += av.x * bv.z; acc[0][3] += av.x * bv.w;
            acc[1][0] += av.y * bv.x; acc[1][1] += av.y * bv.y; acc[1][2] += av.y * bv.z; acc[1][3] += av.y * bv.w;
            acc[2][0] += av.z * bv.x; acc[2][1] += av.z * bv.y; acc[2][2] += av.z * bv.z; acc[2][3] += av.z * bv.w;
            acc[3][0] += av.w * bv.x; acc[3][1] += av.w * bv.y; acc[3][2] += av.w * bv.z; acc[3][3] += av.w * bv.w;
        }
        __syncthreads();
    }

#pragma unroll
    for (int i = 0; i < 4; i++) {
        int r = rowBase + tm * 4 + i;
        if (r < N_NODES) {
            float4 v = make_float4(acc[i][0], acc[i][1], acc[i][2], acc[i][3]);
            *(float4*)&Cout[(size_t)r * C_DIM + tn * 4] = v;
        }
    }
}

// ---------------------------------------------------------------------------
// acc init: self-term + bias
// ---------------------------------------------------------------------------
__global__ void init1_kernel(const float* __restrict__ b1) {
    int i = blockIdx.x * blockDim.x + threadIdx.x;
    const int tot = 3 * N_NODES * H_DIM;
    if (i >= tot) return;
    const int gc  = i / (N_NODES * H_DIM);
    const int rem = i - gc * (N_NODES * H_DIM);
    const int h   = rem & (H_DIM - 1);
    g_acc1[i] = g_emb1[(size_t)gc * 3 * N_NODES * H_DIM + rem] + b1[gc * H_DIM + h];
}

__global__ void init2_kernel(const float* __restrict__ b2) {
    int i = blockIdx.x * blockDim.x + threadIdx.x;
    const int tot = 3 * N_NODES * C_DIM;
    if (i >= tot) return;
    const int gc  = i / (N_NODES * C_DIM);
    const int rem = i - gc * (N_NODES * C_DIM);
    const int c   = rem & (C_DIM - 1);
    g_acc2[i] = g_emb2[(size_t)gc * 3 * N_NODES * C_DIM + rem] + b2[gc * C_DIM + c];
}

// ---------------------------------------------------------------------------
// SpMM scatter, layer 1 (128-wide): one warp per edge, float4 gather + red.v4
// out[src] += 1.01 * wv * val * emb[dst]
// ---------------------------------------------------------------------------
__global__ void scatter1_kernel(const int* __restrict__ src,
                                const int* __restrict__ dst,
                                const float* __restrict__ val,
                                const float* __restrict__ wv1,
                                int combo) {
    const int t = blockIdx.x * blockDim.x + threadIdx.x;
    const int e = t >> 5;
    const int lane = t & 31;
    if (e >= N_EDGES) return;
    const int gc = combo / 3;
    const float c = 1.01f * wv1[combo] * val[e];
    const float4* gp = (const float4*)(g_emb1 + (size_t)combo * N_NODES * H_DIM) +
                       (size_t)dst[e] * (H_DIM / 4) + lane;
    float4 v = *gp;
    float* p = g_acc1 + (size_t)gc * N_NODES * H_DIM + (size_t)src[e] * H_DIM + lane * 4;
    asm volatile("red.global.add.v4.f32 [%0], {%1, %2, %3, %4};"
                 :: "l"(p), "f"(c * v.x), "f"(c * v.y), "f"(c * v.z), "f"(c * v.w)
                 : "memory");
}

// SpMM scatter, layer 2 (64-wide): 16 lanes per edge
__global__ void scatter2_kernel(const int* __restrict__ src,
                                const int* __restrict__ dst,
                                const float* __restrict__ val,
                                const float* __restrict__ wv2,
                                int combo) {
    const int t = blockIdx.x * blockDim.x + threadIdx.x;
    const int e = t >> 4;
    const int lane = t & 15;
    if (e >= N_EDGES) return;
    const int gc = combo / 3;
    const float c = 1.01f * wv2[combo] * val[e];
    const float4* gp = (const float4*)(g_emb2 + (size_t)combo * N_NODES * C_DIM) +
                       (size_t)dst[e] * (C_DIM / 4) + lane;
    float4 v = *gp;
    float* p = g_acc2 + (size_t)gc * N_NODES * C_DIM + (size_t)src[e] * C_DIM + lane * 4;
    asm volatile("red.global.add.v4.f32 [%0], {%1, %2, %3, %4};"
                 :: "l"(p), "f"(c * v.x), "f"(c * v.y), "f"(c * v.z), "f"(c * v.w)
                 : "memory");
}

// relu in place on g_acc1 (produces h)
__global__ void relu1_kernel() {
    int i = blockIdx.x * blockDim.x + threadIdx.x;
    const int tot = 3 * N_NODES * H_DIM;
    if (i >= tot) return;
    g_acc1[i] = fmaxf(g_acc1[i], 0.f);
}

// out = abs((relu(y0)+relu(y1)+relu(y2)) / 3)
__global__ void final_kernel(float* __restrict__ out) {
    int i = blockIdx.x * blockDim.x + threadIdx.x;
    const int tot = N_NODES * C_DIM;
    if (i >= tot) return;
    float a = fmaxf(g_acc2[i], 0.f);
    float b = fmaxf(g_acc2[i + tot], 0.f);
    float c = fmaxf(g_acc2[i + 2 * tot], 0.f);
    out[i] = fabsf((a + b + c) * (1.f / 3.f));
}

// ---------------------------------------------------------------------------
extern "C" void kernel_launch(void* const* d_in, const int* in_sizes, int n_in,
                              void* d_out, int out_size) {
    const float* x1 = (const float*)d_in[0];
    const float* x2 = (const float*)d_in[1];
    const float* x3 = (const float*)d_in[2];
    const int*   src[3] = {(const int*)d_in[3], (const int*)d_in[6], (const int*)d_in[9]};
    const int*   dst[3] = {(const int*)d_in[4], (const int*)d_in[7], (const int*)d_in[10]};
    const float* val[3] = {(const float*)d_in[5], (const float*)d_in[8], (const float*)d_in[11]};
    const float* W1  = (const float*)d_in[12];
    const float* wv1 = (const float*)d_in[13];
    const float* b1  = (const float*)d_in[14];
    const float* W2  = (const float*)d_in[15];
    const float* wv2 = (const float*)d_in[16];
    const float* b2  = (const float*)d_in[17];
    float* out = (float*)d_out;

    static const int hperm[9] = {0,1,2, 1,0,2, 2,0,1};

    const int mblocks = (N_NODES + 63) / 64;  // 313

    // Layer 1
    gemm1_kernel<<<dim3(mblocks, 1, 9), 256>>>(x1, x2, x3, W1);
    {
        int tot = 3 * N_NODES * H_DIM;
        init1_kernel<<<(tot + 255) / 256, 256>>>(b1);
    }
    for (int combo = 0; combo < 9; combo++) {
        int a = hperm[combo];
        long long th = (long long)N_EDGES * 32;
        scatter1_kernel<<<(unsigned)((th + 255) / 256), 256>>>(src[a], dst[a], val[a], wv1, combo);
    }
    {
        int tot = 3 * N_NODES * H_DIM;
        relu1_kernel<<<(tot + 255) / 256, 256>>>();
    }

    // Layer 2
    gemm2_kernel<<<dim3(mblocks, 1, 9), 256>>>(W2);
    {
        int tot = 3 * N_NODES * C_DIM;
        init2_kernel<<<(tot + 255) / 256, 256>>>(b2);
    }
    for (int combo = 0; combo < 9; combo++) {
        int a = hperm[combo];
        long long th = (long long)N_EDGES * 16;
        scatter2_kernel<<<(unsigned)((th + 255) / 256), 256>>>(src[a], dst[a], val[a], wv2, combo);
    }
    {
        int tot = N_NODES * C_DIM;
        final_kernel<<<(tot + 255) / 256, 256>>>(out);
    }
}

// round 2
// speedup vs baseline: 1.4940x; 1.4940x over previous
#include <cuda_runtime.h>
#include <cuda_bf16.h>
#include <cstdint>

#define N_NODES 20000
#define F_DIM   512
#define H_DIM   128
#define C_DIM   64
#define N_EDGES 640000

// ---------------------------------------------------------------------------
// Scratch (static device globals; no runtime allocation allowed)
// ---------------------------------------------------------------------------
__device__ float g_emb1[9 * N_NODES * H_DIM];   // layer-1 embeddings per combo
__device__ float g_h[3 * N_NODES * H_DIM];      // h after relu (layer-1 output)
__device__ float g_emb2[9 * N_NODES * C_DIM];   // layer-2 embeddings per combo

// CSR scratch (built fresh every call; order inside rows may vary -> fp-tolerant)
__device__ int   g_rowptr[3 * (N_NODES + 1)];
__device__ int   g_cursor[3 * N_NODES];
__device__ int   g_col[3 * N_EDGES];
__device__ float g_wval[3 * N_EDGES];

// combo -> which x / adjacency feeds it. combo = gc*3 + role.
__constant__ int c_perm[9] = {0,1,2, 1,0,2, 2,0,1};

// ---------------------------------------------------------------------------
// f32x2 packed math helpers (FFMA2 — only reachable via PTX fma.rn.f32x2)
// ---------------------------------------------------------------------------
__device__ __forceinline__ unsigned long long pack_dup(float x) {
    unsigned long long r;
    asm("mov.b64 %0, {%1, %1};" : "=l"(r) : "f"(x));
    return r;
}
__device__ __forceinline__ void fma2(unsigned long long& acc,
                                     unsigned long long a,
                                     unsigned long long b) {
    asm("fma.rn.f32x2 %0, %1, %2, %3;" : "=l"(acc) : "l"(a), "l"(b), "l"(acc));
}
__device__ __forceinline__ float2 unpack2(unsigned long long v) {
    float2 f;
    asm("mov.b64 {%0, %1}, %2;" : "=f"(f.x), "=f"(f.y) : "l"(v));
    return f;
}

// ---------------------------------------------------------------------------
// CSR build
// ---------------------------------------------------------------------------
__global__ void csr_zero_kernel() {
    int i = blockIdx.x * blockDim.x + threadIdx.x;
    if (i < 3 * N_NODES) g_cursor[i] = 0;
}

__global__ void csr_hist_kernel(const int* __restrict__ s0,
                                const int* __restrict__ s1,
                                const int* __restrict__ s2) {
    int e = blockIdx.x * blockDim.x + threadIdx.x;
    int a = blockIdx.y;
    if (e >= N_EDGES) return;
    const int* s = (a == 0) ? s0 : (a == 1) ? s1 : s2;
    atomicAdd(&g_cursor[a * N_NODES + s[e]], 1);
}

__global__ void csr_scan_kernel() {
    const int a = blockIdx.x;
    __shared__ int sh[1024];
    int* cnt = g_cursor + a * N_NODES;
    int* rp  = g_rowptr + a * (N_NODES + 1);
    int carry = 0;
    for (int base = 0; base < N_NODES; base += 1024) {
        int i = base + threadIdx.x;
        int v = (i < N_NODES) ? cnt[i] : 0;
        sh[threadIdx.x] = v;
        __syncthreads();
        for (int off = 1; off < 1024; off <<= 1) {
            int t = (threadIdx.x >= off) ? sh[threadIdx.x - off] : 0;
            __syncthreads();
            sh[threadIdx.x] += t;
            __syncthreads();
        }
        int inc = sh[threadIdx.x];
        int exc = inc - v;
        if (i < N_NODES) {
            rp[i]  = carry + exc;
            cnt[i] = carry + exc;   // becomes the fill cursor
        }
        int tot = sh[1023];
        __syncthreads();
        carry += tot;
    }
    if (threadIdx.x == 0) rp[N_NODES] = carry;
}

__global__ void csr_fill_kernel(const int* __restrict__ s0,
                                const int* __restrict__ s1,
                                const int* __restrict__ s2,
                                const int* __restrict__ d0,
                                const int* __restrict__ d1,
                                const int* __restrict__ d2,
                                const float* __restrict__ v0,
                                const float* __restrict__ v1,
                                const float* __restrict__ v2) {
    int e = blockIdx.x * blockDim.x + threadIdx.x;
    int a = blockIdx.y;
    if (e >= N_EDGES) return;
    const int*   s = (a == 0) ? s0 : (a == 1) ? s1 : s2;
    const int*   d = (a == 0) ? d0 : (a == 1) ? d1 : d2;
    const float* v = (a == 0) ? v0 : (a == 1) ? v1 : v2;
    int pos = atomicAdd(&g_cursor[a * N_NODES + s[e]], 1);
    g_col[a * N_EDGES + pos]  = d[e];
    g_wval[a * N_EDGES + pos] = v[e];
}

// ---------------------------------------------------------------------------
// GEMM 1: g_emb1[b] (20000x128) = X[perm[b]] (20000x512) @ W1[b] (512x128)
// 64x128 block tile, BK=32, 256 threads, per-thread 8x4 via f32x2 pairs.
// ---------------------------------------------------------------------------
__global__ void gemm1_kernel(const float* __restrict__ x1,
                             const float* __restrict__ x2,
                             const float* __restrict__ x3,
                             const float* __restrict__ W1) {
    const int b = blockIdx.z;
    const int p = c_perm[b];
    const float* __restrict__ X = (p == 0) ? x1 : (p == 1) ? x2 : x3;
    const float* __restrict__ W = W1 + (size_t)b * F_DIM * H_DIM;
    float* __restrict__ Cout = g_emb1 + (size_t)b * N_NODES * H_DIM;

    __shared__ float As[32][64];
    __shared__ float Bs[32][128];

    const int tid = threadIdx.x;
    const int rowBase = blockIdx.x * 64;

    const int tn = tid & 31;   // col group: tn*4
    const int tm = tid >> 5;   // row group: tm*8 (uniform within a warp)

    // acc[r2][j]: packed (row tm*8+2*r2, row tm*8+2*r2+1) at col tn*4+j
    unsigned long long acc[4][4];
#pragma unroll
    for (int i = 0; i < 4; i++)
#pragma unroll
        for (int j = 0; j < 4; j++) acc[i][j] = 0ull;

    const int lm  = tid & 63;  // A load: row within tile
    const int lkg = tid >> 6;  // A load: k-group of 8
    const int bk  = tid >> 3;  // B load: k row (0..31)
    const int bng = tid & 7;   // B load: col group of 16

    for (int k0 = 0; k0 < F_DIM; k0 += 32) {
        int gr = rowBase + lm;
        if (gr >= N_NODES) gr = N_NODES - 1;  // clamp; stores are guarded
        const float* xp = X + (size_t)gr * F_DIM + k0 + lkg * 8;
        float4 a0 = *(const float4*)(xp);
        float4 a1 = *(const float4*)(xp + 4);
        const int kk = lkg * 8;
        As[kk + 0][lm] = a0.x; As[kk + 1][lm] = a0.y;
        As[kk + 2][lm] = a0.z; As[kk + 3][lm] = a0.w;
        As[kk + 4][lm] = a1.x; As[kk + 5][lm] = a1.y;
        As[kk + 6][lm] = a1.z; As[kk + 7][lm] = a1.w;

        const float* wp = W + (size_t)(k0 + bk) * H_DIM + bng * 16;
        float4 b0 = *(const float4*)(wp);
        float4 b1 = *(const float4*)(wp + 4);
        float4 b2 = *(const float4*)(wp + 8);
        float4 b3 = *(const float4*)(wp + 12);
        *(float4*)&Bs[bk][bng * 16 + 0]  = b0;
        *(float4*)&Bs[bk][bng * 16 + 4]  = b1;
        *(float4*)&Bs[bk][bng * 16 + 8]  = b2;
        *(float4*)&Bs[bk][bng * 16 + 12] = b3;
        __syncthreads();

#pragma unroll
        for (int k = 0; k < 32; k++) {
            float4 bvf = *(const float4*)&Bs[k][tn * 4];
            unsigned long long bd0 = pack_dup(bvf.x);
            unsigned long long bd1 = pack_dup(bvf.y);
            unsigned long long bd2 = pack_dup(bvf.z);
            unsigned long long bd3 = pack_dup(bvf.w);
            const unsigned long long* ap =
                (const unsigned long long*)&As[k][tm * 8];  // broadcast in warp
            unsigned long long ar[4];
#pragma unroll
            for (int r = 0; r < 4; r++) ar[r] = ap[r];
#pragma unroll
            for (int r = 0; r < 4; r++) {
                fma2(acc[r][0], ar[r], bd0);
                fma2(acc[r][1], ar[r], bd1);
                fma2(acc[r][2], ar[r], bd2);
                fma2(acc[r][3], ar[r], bd3);
            }
        }
        __syncthreads();
    }

#pragma unroll
    for (int r2 = 0; r2 < 4; r2++) {
        float2 c0 = unpack2(acc[r2][0]);
        float2 c1 = unpack2(acc[r2][1]);
        float2 c2 = unpack2(acc[r2][2]);
        float2 c3 = unpack2(acc[r2][3]);
        int r_even = rowBase + tm * 8 + 2 * r2;
        if (r_even < N_NODES) {
            float4 v = make_float4(c0.x, c1.x, c2.x, c3.x);
            *(float4*)&Cout[(size_t)r_even * H_DIM + tn * 4] = v;
        }
        if (r_even + 1 < N_NODES) {
            float4 v = make_float4(c0.y, c1.y, c2.y, c3.y);
            *(float4*)&Cout[(size_t)(r_even + 1) * H_DIM + tn * 4] = v;
        }
    }
}

// ---------------------------------------------------------------------------
// GEMM 2: g_emb2[b] (20000x64) = h[perm[b]] (20000x128) @ W2[b] (128x64)
// 64x64 block tile, BK=32, 256 threads, per-thread 4x4 via f32x2 pairs.
// ---------------------------------------------------------------------------
__global__ void gemm2_kernel(const float* __restrict__ W2) {
    const int b = blockIdx.z;
    const float* __restrict__ Hx = g_h + (size_t)c_perm[b] * N_NODES * H_DIM;
    const float* __restrict__ W  = W2 + (size_t)b * H_DIM * C_DIM;
    float* __restrict__ Cout = g_emb2 + (size_t)b * N_NODES * C_DIM;

    __shared__ float As[32][64];
    __shared__ float Bs[32][64];

    const int tid = threadIdx.x;
    const int rowBase = blockIdx.x * 64;
    const int tn = tid & 15;   // cols tn*4
    const int tm = tid >> 4;   // rows tm*4

    unsigned long long acc[2][4];
#pragma unroll
    for (int i = 0; i < 2; i++)
#pragma unroll
        for (int j = 0; j < 4; j++) acc[i][j] = 0ull;

    const int lm  = tid & 63;
    const int lkg = tid >> 6;
    const int bk  = tid >> 3;
    const int bng = tid & 7;   // col group of 8

    for (int k0 = 0; k0 < H_DIM; k0 += 32) {
        int gr = rowBase + lm;
        if (gr >= N_NODES) gr = N_NODES - 1;
        const float* xp = Hx + (size_t)gr * H_DIM + k0 + lkg * 8;
        float4 a0 = *(const float4*)(xp);
        float4 a1 = *(const float4*)(xp + 4);
        const int kk = lkg * 8;
        As[kk + 0][lm] = a0.x; As[kk + 1][lm] = a0.y;
        As[kk + 2][lm] = a0.z; As[kk + 3][lm] = a0.w;
        As[kk + 4][lm] = a1.x; As[kk + 5][lm] = a1.y;
        As[kk + 6][lm] = a1.z; As[kk + 7][lm] = a1.w;

        const float* wp = W + (size_t)(k0 + bk) * C_DIM + bng * 8;
        float4 b0 = *(const float4*)(wp);
        float4 b1 = *(const float4*)(wp + 4);
        *(float4*)&Bs[bk][bng * 8 + 0] = b0;
        *(float4*)&Bs[bk][bng * 8 + 4] = b1;
        __syncthreads();

#pragma unroll
        for (int k = 0; k < 32; k++) {
            float4 bvf = *(const float4*)&Bs[k][tn * 4];
            unsigned long long bd0 = pack_dup(bvf.x);
            unsigned long long bd1 = pack_dup(bvf.y);
            unsigned long long bd2 = pack_dup(bvf.z);
            unsigned long long bd3 = pack_dup(bvf.w);
            const unsigned long long* ap =
                (const unsigned long long*)&As[k][tm * 4];
            unsigned long long a0p = ap[0];
            unsigned long long a1p = ap[1];
            fma2(acc[0][0], a0p, bd0); fma2(acc[0][1], a0p, bd1);
            fma2(acc[0][2], a0p, bd2); fma2(acc[0][3], a0p, bd3);
            fma2(acc[1][0], a1p, bd0); fma2(acc[1][1], a1p, bd1);
            fma2(acc[1][2], a1p, bd2); fma2(acc[1][3], a1p, bd3);
        }
        __syncthreads();
    }

#pragma unroll
    for (int r2 = 0; r2 < 2; r2++) {
        float2 c0 = unpack2(acc[r2][0]);
        float2 c1 = unpack2(acc[r2][1]);
        float2 c2 = unpack2(acc[r2][2]);
        float2 c3 = unpack2(acc[r2][3]);
        int r_even = rowBase + tm * 4 + 2 * r2;
        if (r_even < N_NODES) {
            float4 v = make_float4(c0.x, c1.x, c2.x, c3.x);
            *(float4*)&Cout[(size_t)r_even * C_DIM + tn * 4] = v;
        }
        if (r_even + 1 < N_NODES) {
            float4 v = make_float4(c0.y, c1.y, c2.y, c3.y);
            *(float4*)&Cout[(size_t)(r_even + 1) * C_DIM + tn * 4] = v;
        }
    }
}

// ---------------------------------------------------------------------------
// Fused SpMM layer 1: block per node, 128 threads (one per H column).
// For each adjacency a, the 3 gc's that use it gather from their emb tables.
// Epilogue: h[gc] = relu(self + 1.01*agg + b1[gc]).
// comboOf[gc][a]: combo index (into g_emb1 / wv flat) for group gc, adjacency a
// ---------------------------------------------------------------------------
__global__ void spmm1_kernel(const float* __restrict__ wv1,
                             const float* __restrict__ b1) {
    const int i = blockIdx.x;
    const int tid = threadIdx.x;
    const int comboOf[3][3] = {{0, 1, 2}, {4, 3, 5}, {7, 8, 6}};

    float agg0 = 0.f, agg1 = 0.f, agg2 = 0.f;

#pragma unroll
    for (int a = 0; a < 3; a++) {
        const int start = g_rowptr[a * (N_NODES + 1) + i];
        const int end   = g_rowptr[a * (N_NODES + 1) + i + 1];
        const float* __restrict__ T0 = g_emb1 + (size_t)comboOf[0][a] * N_NODES * H_DIM;
        const float* __restrict__ T1 = g_emb1 + (size_t)comboOf[1][a] * N_NODES * H_DIM;
        const float* __restrict__ T2 = g_emb1 + (size_t)comboOf[2][a] * N_NODES * H_DIM;
        const int*   __restrict__ col = g_col  + (size_t)a * N_EDGES;
        const float* __restrict__ wv  = g_wval + (size_t)a * N_EDGES;

        float p0 = 0.f, p1 = 0.f, p2 = 0.f;
        for (int e = start; e < end; e++) {
            const int d = __ldg(col + e);
            const float w = __ldg(wv + e);
            const size_t o = (size_t)d * H_DIM + tid;
            p0 += w * __ldg(T0 + o);
            p1 += w * __ldg(T1 + o);
            p2 += w * __ldg(T2 + o);
        }
        agg0 += wv1[comboOf[0][a]] * p0;
        agg1 += wv1[comboOf[1][a]] * p1;
        agg2 += wv1[comboOf[2][a]] * p2;
    }

    const size_t NH = (size_t)N_NODES * H_DIM;
    const size_t oi = (size_t)i * H_DIM + tid;
    {
        float self = g_emb1[0 * NH + oi];
        g_h[0 * NH + oi] = fmaxf(self + 1.01f * agg0 + b1[0 * H_DIM + tid], 0.f);
    }
    {
        float self = g_emb1[3 * NH + oi];
        g_h[1 * NH + oi] = fmaxf(self + 1.01f * agg1 + b1[1 * H_DIM + tid], 0.f);
    }
    {
        float self = g_emb1[6 * NH + oi];
        g_h[2 * NH + oi] = fmaxf(self + 1.01f * agg2 + b1[2 * H_DIM + tid], 0.f);
    }
}

// ---------------------------------------------------------------------------
// Fused SpMM layer 2 + final: block per node, 64 threads (one per C column).
// Writes out[i] = abs((relu(y0)+relu(y1)+relu(y2))/3) directly.
// ---------------------------------------------------------------------------
__global__ void spmm2_kernel(const float* __restrict__ wv2,
                             const float* __restrict__ b2,
                             float* __restrict__ out) {
    const int i = blockIdx.x;
    const int tid = threadIdx.x;
    const int comboOf[3][3] = {{0, 1, 2}, {4, 3, 5}, {7, 8, 6}};

    float agg0 = 0.f, agg1 = 0.f, agg2 = 0.f;

#pragma unroll
    for (int a = 0; a < 3; a++) {
        const int start = g_rowptr[a * (N_NODES + 1) + i];
        const int end   = g_rowptr[a * (N_NODES + 1) + i + 1];
        const float* __restrict__ T0 = g_emb2 + (size_t)comboOf[0][a] * N_NODES * C_DIM;
        const float* __restrict__ T1 = g_emb2 + (size_t)comboOf[1][a] * N_NODES * C_DIM;
        const float* __restrict__ T2 = g_emb2 + (size_t)comboOf[2][a] * N_NODES * C_DIM;
        const int*   __restrict__ col = g_col  + (size_t)a * N_EDGES;
        const float* __restrict__ wv  = g_wval + (size_t)a * N_EDGES;

        float p0 = 0.f, p1 = 0.f, p2 = 0.f;
        for (int e = start; e < end; e++) {
            const int d = __ldg(col + e);
            const float w = __ldg(wv + e);
            const size_t o = (size_t)d * C_DIM + tid;
            p0 += w * __ldg(T0 + o);
            p1 += w * __ldg(T1 + o);
            p2 += w * __ldg(T2 + o);
        }
        agg0 += wv2[comboOf[0][a]] * p0;
        agg1 += wv2[comboOf[1][a]] * p1;
        agg2 += wv2[comboOf[2][a]] * p2;
    }

    const size_t NC = (size_t)N_NODES * C_DIM;
    const size_t oi = (size_t)i * C_DIM + tid;
    float y0 = fmaxf(g_emb2[0 * NC + oi] + 1.01f * agg0 + b2[0 * C_DIM + tid], 0.f);
    float y1 = fmaxf(g_emb2[3 * NC + oi] + 1.01f * agg1 + b2[1 * C_DIM + tid], 0.f);
    float y2 = fmaxf(g_emb2[6 * NC + oi] + 1.01f * agg2 + b2[2 * C_DIM + tid], 0.f);
    out[oi] = fabsf((y0 + y1 + y2) * (1.f / 3.f));
}

// ---------------------------------------------------------------------------
extern "C" void kernel_launch(void* const* d_in, const int* in_sizes, int n_in,
                              void* d_out, int out_size) {
    const float* x1 = (const float*)d_in[0];
    const float* x2 = (const float*)d_in[1];
    const float* x3 = (const float*)d_in[2];
    const int*   s0 = (const int*)d_in[3];
    const int*   d0 = (const int*)d_in[4];
    const float* v0 = (const float*)d_in[5];
    const int*   s1 = (const int*)d_in[6];
    const int*   d1 = (const int*)d_in[7];
    const float* v1 = (const float*)d_in[8];
    const int*   s2 = (const int*)d_in[9];
    const int*   d2 = (const int*)d_in[10];
    const float* v2 = (const float*)d_in[11];
    const float* W1  = (const float*)d_in[12];
    const float* wv1 = (const float*)d_in[13];
    const float* b1  = (const float*)d_in[14];
    const float* W2  = (const float*)d_in[15];
    const float* wv2 = (const float*)d_in[16];
    const float* b2  = (const float*)d_in[17];
    float* out = (float*)d_out;

    const int mblocks = (N_NODES + 63) / 64;  // 313
    const dim3 eg((N_EDGES + 255) / 256, 3);

    // CSR build (runs while nothing depends on it yet)
    csr_zero_kernel<<<(3 * N_NODES + 255) / 256, 256>>>();
    csr_hist_kernel<<<eg, 256>>>(s0, s1, s2);
    csr_scan_kernel<<<3, 1024>>>();
    csr_fill_kernel<<<eg, 256>>>(s0, s1, s2, d0, d1, d2, v0, v1, v2);

    // Layer 1
    gemm1_kernel<<<dim3(mblocks, 1, 9), 256>>>(x1, x2, x3, W1);
    spmm1_kernel<<<N_NODES, H_DIM>>>(wv1, b1);

    // Layer 2
    gemm2_kernel<<<dim3(mblocks, 1, 9), 256>>>(W2);
    spmm2_kernel<<<N_NODES, C_DIM>>>(wv2, b2, out);
}

// round 4
// speedup vs baseline: 2.1790x; 1.4585x over previous
#include <cuda_runtime.h>
#include <cuda_bf16.h>
#include <cstdint>

#define N_NODES 20000
#define F_DIM   512
#define H_DIM   128
#define C_DIM   64
#define N_EDGES 640000
#define PAD_ROWS 20096   // 157 * 128

// ---------------------------------------------------------------------------
// Scratch (static device globals; no runtime allocation allowed)
// ---------------------------------------------------------------------------
__device__ float g_emb1[9 * N_NODES * H_DIM];
__device__ float g_h[3 * N_NODES * H_DIM];
__device__ float g_emb2[9 * N_NODES * C_DIM];

// bf16 split operands for GEMM1
__device__ __nv_bfloat16 g_xsplit[6 * PAD_ROWS * F_DIM];  // [view*2+term][row][k]
__device__ __nv_bfloat16 g_wt[18 * H_DIM * F_DIM];        // [combo*2+term][n][k]

// CSR scratch
__device__ int   g_rowptr[3 * (N_NODES + 1)];
__device__ int   g_cursor[3 * N_NODES];
__device__ int   g_col[3 * N_EDGES];
__device__ float g_wval[3 * N_EDGES];

// combo -> which x / adjacency feeds it. combo = gc*3 + role.
__constant__ int c_perm[9] = {0,1,2, 1,0,2, 2,0,1};

// ---------------------------------------------------------------------------
// PTX helpers (base-target only: sm_80+ features)
// ---------------------------------------------------------------------------
__device__ __forceinline__ uint32_t smem_u32(const void* p) {
    uint32_t a;
    asm("{ .reg .u64 t; cvta.to.shared.u64 t, %1; cvt.u32.u64 %0, t; }"
        : "=r"(a) : "l"(p));
    return a;
}

__device__ __forceinline__ void cp_async16(uint32_t dst, const void* src) {
    asm volatile("cp.async.cg.shared.global [%0], [%1], 16;"
                 :: "r"(dst), "l"(src) : "memory");
}
#define CP_COMMIT() asm volatile("cp.async.commit_group;" ::: "memory")
#define CP_WAIT(n)  asm volatile("cp.async.wait_group %0;" :: "n"(n) : "memory")

__device__ __forceinline__ void ldsm_x4(uint32_t& r0, uint32_t& r1,
                                        uint32_t& r2, uint32_t& r3, uint32_t addr) {
    asm volatile("ldmatrix.sync.aligned.m8n8.x4.shared.b16 {%0,%1,%2,%3}, [%4];"
                 : "=r"(r0), "=r"(r1), "=r"(r2), "=r"(r3) : "r"(addr));
}

__device__ __forceinline__ void mma_bf16(float* d, const uint32_t* a,
                                         const uint32_t* b) {
    asm volatile(
        "mma.sync.aligned.m16n8k16.row.col.f32.bf16.bf16.f32 "
        "{%0,%1,%2,%3}, {%4,%5,%6,%7}, {%8,%9}, {%0,%1,%2,%3};"
        : "+f"(d[0]), "+f"(d[1]), "+f"(d[2]), "+f"(d[3])
        : "r"(a[0]), "r"(a[1]), "r"(a[2]), "r"(a[3]), "r"(b[0]), "r"(b[1]));
}

// f32x2 packed helpers (for gemm2)
__device__ __forceinline__ unsigned long long pack_dup(float x) {
    unsigned long long r;
    asm("mov.b64 %0, {%1, %1};" : "=l"(r) : "f"(x));
    return r;
}
__device__ __forceinline__ void fma2(unsigned long long& acc,
                                     unsigned long long a, unsigned long long b) {
    asm("fma.rn.f32x2 %0, %1, %2, %3;" : "=l"(acc) : "l"(a), "l"(b), "l"(acc));
}
__device__ __forceinline__ float2 unpack2(unsigned long long v) {
    float2 f;
    asm("mov.b64 {%0, %1}, %2;" : "=f"(f.x), "=f"(f.y) : "l"(v));
    return f;
}

// ---------------------------------------------------------------------------
// bf16 split kernels
// ---------------------------------------------------------------------------
__device__ __forceinline__ uint32_t pack_bf2(__nv_bfloat16 a, __nv_bfloat16 b) {
    return (uint32_t)__bfloat16_as_ushort(a) | ((uint32_t)__bfloat16_as_ushort(b) << 16);
}

__global__ void split_x_kernel(const float* __restrict__ x1,
                               const float* __restrict__ x2,
                               const float* __restrict__ x3) {
    int i = blockIdx.x * blockDim.x + threadIdx.x;   // one float4 each
    const int total = 3 * N_NODES * (F_DIM / 4);
    if (i >= total) return;
    const int per_view = N_NODES * (F_DIM / 4);
    const int view = i / per_view;
    const int rem  = i - view * per_view;
    const int row  = rem / (F_DIM / 4);
    const int kg   = rem - row * (F_DIM / 4);
    const float* X = (view == 0) ? x1 : (view == 1) ? x2 : x3;
    float4 f = ((const float4*)X)[rem];

    __nv_bfloat16 h0 = __float2bfloat16(f.x), h1 = __float2bfloat16(f.y);
    __nv_bfloat16 h2 = __float2bfloat16(f.z), h3 = __float2bfloat16(f.w);
    __nv_bfloat16 l0 = __float2bfloat16(f.x - __bfloat162float(h0));
    __nv_bfloat16 l1 = __float2bfloat16(f.y - __bfloat162float(h1));
    __nv_bfloat16 l2 = __float2bfloat16(f.z - __bfloat162float(h2));
    __nv_bfloat16 l3 = __float2bfloat16(f.w - __bfloat162float(h3));

    size_t off_hi = ((size_t)(view * 2 + 0) * PAD_ROWS + row) * F_DIM + kg * 4;
    size_t off_lo = ((size_t)(view * 2 + 1) * PAD_ROWS + row) * F_DIM + kg * 4;
    *(uint2*)&g_xsplit[off_hi] = make_uint2(pack_bf2(h0, h1), pack_bf2(h2, h3));
    *(uint2*)&g_xsplit[off_lo] = make_uint2(pack_bf2(l0, l1), pack_bf2(l2, l3));
}

__global__ void split_w_kernel(const float* __restrict__ W1) {
    int i = blockIdx.x * blockDim.x + threadIdx.x;  // over 9*512*128, n fastest
    const int total = 9 * F_DIM * H_DIM;
    if (i >= total) return;
    const int b = i / (F_DIM * H_DIM);
    const int rem = i - b * (F_DIM * H_DIM);
    const int k = rem / H_DIM;
    const int n = rem - k * H_DIM;
    float w = W1[i];
    __nv_bfloat16 hi = __float2bfloat16(w);
    __nv_bfloat16 lo = __float2bfloat16(w - __bfloat162float(hi));
    g_wt[((size_t)(b * 2 + 0) * H_DIM + n) * F_DIM + k] = hi;
    g_wt[((size_t)(b * 2 + 1) * H_DIM + n) * F_DIM + k] = lo;
}

// ---------------------------------------------------------------------------
// CSR build
// ---------------------------------------------------------------------------
__global__ void csr_zero_kernel() {
    int i = blockIdx.x * blockDim.x + threadIdx.x;
    if (i < 3 * N_NODES) g_cursor[i] = 0;
}

__global__ void csr_hist_kernel(const int* __restrict__ s0,
                                const int* __restrict__ s1,
                                const int* __restrict__ s2) {
    int e = blockIdx.x * blockDim.x + threadIdx.x;
    int a = blockIdx.y;
    if (e >= N_EDGES) return;
    const int* s = (a == 0) ? s0 : (a == 1) ? s1 : s2;
    atomicAdd(&g_cursor[a * N_NODES + s[e]], 1);
}

__global__ void csr_scan_kernel() {
    const int a = blockIdx.x;
    __shared__ int sh[1024];
    int* cnt = g_cursor + a * N_NODES;
    int* rp  = g_rowptr + a * (N_NODES + 1);
    int carry = 0;
    for (int base = 0; base < N_NODES; base += 1024) {
        int i = base + threadIdx.x;
        int v = (i < N_NODES) ? cnt[i] : 0;
        sh[threadIdx.x] = v;
        __syncthreads();
        for (int off = 1; off < 1024; off <<= 1) {
            int t = (threadIdx.x >= off) ? sh[threadIdx.x - off] : 0;
            __syncthreads();
            sh[threadIdx.x] += t;
            __syncthreads();
        }
        int inc = sh[threadIdx.x];
        int exc = inc - v;
        if (i < N_NODES) {
            rp[i]  = carry + exc;
            cnt[i] = carry + exc;
        }
        int tot = sh[1023];
        __syncthreads();
        carry += tot;
    }
    if (threadIdx.x == 0) rp[N_NODES] = carry;
}

__global__ void csr_fill_kernel(const int* __restrict__ s0,
                                const int* __restrict__ s1,
                                const int* __restrict__ s2,
                                const int* __restrict__ d0,
                                const int* __restrict__ d1,
                                const int* __restrict__ d2,
                                const float* __restrict__ v0,
                                const float* __restrict__ v1,
                                const float* __restrict__ v2) {
    int e = blockIdx.x * blockDim.x + threadIdx.x;
    int a = blockIdx.y;
    if (e >= N_EDGES) return;
    const int*   s = (a == 0) ? s0 : (a == 1) ? s1 : s2;
    const int*   d = (a == 0) ? d0 : (a == 1) ? d1 : d2;
    const float* v = (a == 0) ? v0 : (a == 1) ? v1 : v2;
    int pos = atomicAdd(&g_cursor[a * N_NODES + s[e]], 1);
    g_col[a * N_EDGES + pos]  = d[e];
    g_wval[a * N_EDGES + pos] = v[e];
}

// ---------------------------------------------------------------------------
// GEMM1 (mma.sync bf16x3): g_emb1[b] = X[perm[b]] @ W1[b], fp32 accumulate.
// grid (157, 9), 256 threads (8 warps, 4m x 2n). CTA tile 128x128, BK=64 bf16.
// Double-buffered cp.async; SW128 swizzle; 24 K-iters (3 terms x 8 chunks).
// ---------------------------------------------------------------------------
#define TILE_BYTES 16384                  // 128 rows x 128B
#define STAGE_BYTES (2 * TILE_BYTES)      // A + B
#define GSM_TOTAL (2 * STAGE_BYTES)       // double buffer = 64KB

__global__ void __launch_bounds__(256)
gemm1_mma_kernel() {
    extern __shared__ char smem[];
    const uint32_t sb = smem_u32(smem);
    const int tid = threadIdx.x;
    const int wid = tid >> 5;
    const int lane = tid & 31;
    const int tile = blockIdx.x;
    const int b = blockIdx.y;
    const int view = c_perm[b];
    const int rowBase = tile * 128;

    const int termA[3] = {0, 1, 0};
    const int termB[3] = {0, 0, 1};

    // G2S mapping: 4 x 16B chunks per thread per tile
    const int g_row = tid >> 1;          // base row (2 threads per row; 4 rows strided 64... )
    // simpler mapping: idx = tid + i*256 -> row = idx>>3, chunk = idx&7
    // (computed inline below)

    // warp layout: 4 (M) x 2 (N); warp tile 32 x 64
    const int wm = wid >> 1;
    const int wn = wid & 1;

    // ldmatrix lane addressing (fixed per lane)
    const int arow_l = (lane & 15);              // + wm*32 + mi*16
    const uint32_t akh = (uint32_t)(lane >> 4) * 16;
    const int brow_l = (lane & 7) + ((lane >> 4) << 3);  // + wn*64 + bj*16
    const uint32_t bkh = (uint32_t)((lane >> 3) & 1) * 16;

    float cfrag[2][8][4];
#pragma unroll
    for (int mi = 0; mi < 2; mi++)
#pragma unroll
        for (int nj = 0; nj < 8; nj++)
#pragma unroll
            for (int q = 0; q < 4; q++) cfrag[mi][nj][q] = 0.f;

    // -- prefetch helper (macro-ish via lambda) --
    auto prefetch = [&](int it, int bufi) {
        const int t = it >> 3;
        const int c = it & 7;
        const char* Asrc = (const char*)(g_xsplit +
            ((size_t)(view * 2 + termA[t]) * PAD_ROWS + rowBase) * F_DIM) + c * 128;
        const char* Bsrc = (const char*)(g_wt +
            (size_t)(b * 2 + termB[t]) * H_DIM * F_DIM) + c * 128;
        const uint32_t Ab = sb + bufi * STAGE_BYTES;
        const uint32_t Bb = Ab + TILE_BYTES;
#pragma unroll
        for (int i = 0; i < 4; i++) {
            int idx = tid + i * 256;
            int row = idx >> 3;
            int ch  = idx & 7;
            uint32_t off = row * 128 + ch * 16;
            uint32_t sw = off ^ ((off >> 3) & 0x70);
            cp_async16(Ab + sw, Asrc + (size_t)row * (F_DIM * 2) + ch * 16);
            cp_async16(Bb + sw, Bsrc + (size_t)row * (F_DIM * 2) + ch * 16);
        }
        CP_COMMIT();
    };

    prefetch(0, 0);

    for (int it = 0; it < 24; it++) {
        const int bufi = it & 1;
        if (it < 23) {
            prefetch(it + 1, (it + 1) & 1);
            CP_WAIT(1);
        } else {
            CP_WAIT(0);
        }
        __syncthreads();

        const uint32_t Ab = sb + bufi * STAGE_BYTES;
        const uint32_t Bb = Ab + TILE_BYTES;

#pragma unroll
        for (int k16 = 0; k16 < 4; k16++) {
            const uint32_t kb = k16 * 32;
            uint32_t afrag[2][4];
#pragma unroll
            for (int mi = 0; mi < 2; mi++) {
                const int row = wm * 32 + mi * 16 + arow_l;
                const uint32_t addr =
                    Ab + row * 128 + ((kb + akh) ^ (uint32_t)((row & 7) << 4));
                ldsm_x4(afrag[mi][0], afrag[mi][1], afrag[mi][2], afrag[mi][3], addr);
            }
            uint32_t bfrag[8][2];
#pragma unroll
            for (int bj = 0; bj < 4; bj++) {
                const int row = wn * 64 + bj * 16 + brow_l;
                const uint32_t addr =
                    Bb + row * 128 + ((kb + bkh) ^ (uint32_t)((row & 7) << 4));
                uint32_t r0, r1, r2, r3;
                ldsm_x4(r0, r1, r2, r3, addr);
                bfrag[bj * 2 + 0][0] = r0; bfrag[bj * 2 + 0][1] = r1;
                bfrag[bj * 2 + 1][0] = r2; bfrag[bj * 2 + 1][1] = r3;
            }
#pragma unroll
            for (int mi = 0; mi < 2; mi++)
#pragma unroll
                for (int nj = 0; nj < 8; nj++)
                    mma_bf16(cfrag[mi][nj], afrag[mi], bfrag[nj]);
        }
        __syncthreads();
    }

    // Epilogue
    float* __restrict__ Cout = g_emb1 + (size_t)b * N_NODES * H_DIM;
    const int mrow0 = rowBase + wm * 32;
    const int ncol0 = wn * 64;
    const int lr = lane >> 2;         // 0..7
    const int lc = (lane & 3) * 2;
#pragma unroll
    for (int mi = 0; mi < 2; mi++) {
#pragma unroll
        for (int nj = 0; nj < 8; nj++) {
            const int r0 = mrow0 + mi * 16 + lr;
            const int cc = ncol0 + nj * 8 + lc;
            if (r0 < N_NODES)
                *(float2*)&Cout[(size_t)r0 * H_DIM + cc] =
                    make_float2(cfrag[mi][nj][0], cfrag[mi][nj][1]);
            if (r0 + 8 < N_NODES)
                *(float2*)&Cout[(size_t)(r0 + 8) * H_DIM + cc] =
                    make_float2(cfrag[mi][nj][2], cfrag[mi][nj][3]);
        }
    }
}

// ---------------------------------------------------------------------------
// GEMM 2 (FFMA2): g_emb2[b] (20000x64) = h[perm[b]] (20000x128) @ W2[b]
// ---------------------------------------------------------------------------
__global__ void gemm2_kernel(const float* __restrict__ W2) {
    const int b = blockIdx.z;
    const float* __restrict__ Hx = g_h + (size_t)c_perm[b] * N_NODES * H_DIM;
    const float* __restrict__ W  = W2 + (size_t)b * H_DIM * C_DIM;
    float* __restrict__ Cout = g_emb2 + (size_t)b * N_NODES * C_DIM;

    __shared__ float As[32][64];
    __shared__ float Bs[32][64];

    const int tid = threadIdx.x;
    const int rowBase = blockIdx.x * 64;
    const int tn = tid & 15;
    const int tm = tid >> 4;

    unsigned long long acc[2][4];
#pragma unroll
    for (int i = 0; i < 2; i++)
#pragma unroll
        for (int jj = 0; jj < 4; jj++) acc[i][jj] = 0ull;

    const int lm  = tid & 63;
    const int lkg = tid >> 6;
    const int bk  = tid >> 3;
    const int bng = tid & 7;

    for (int k0 = 0; k0 < H_DIM; k0 += 32) {
        int gr = rowBase + lm;
        if (gr >= N_NODES) gr = N_NODES - 1;
        const float* xp = Hx + (size_t)gr * H_DIM + k0 + lkg * 8;
        float4 a0 = *(const float4*)(xp);
        float4 a1 = *(const float4*)(xp + 4);
        const int kk = lkg * 8;
        As[kk + 0][lm] = a0.x; As[kk + 1][lm] = a0.y;
        As[kk + 2][lm] = a0.z; As[kk + 3][lm] = a0.w;
        As[kk + 4][lm] = a1.x; As[kk + 5][lm] = a1.y;
        As[kk + 6][lm] = a1.z; As[kk + 7][lm] = a1.w;

        const float* wp = W + (size_t)(k0 + bk) * C_DIM + bng * 8;
        float4 b0 = *(const float4*)(wp);
        float4 b1 = *(const float4*)(wp + 4);
        *(float4*)&Bs[bk][bng * 8 + 0] = b0;
        *(float4*)&Bs[bk][bng * 8 + 4] = b1;
        __syncthreads();

#pragma unroll
        for (int k = 0; k < 32; k++) {
            float4 bvf = *(const float4*)&Bs[k][tn * 4];
            unsigned long long bd0 = pack_dup(bvf.x);
            unsigned long long bd1 = pack_dup(bvf.y);
            unsigned long long bd2 = pack_dup(bvf.z);
            unsigned long long bd3 = pack_dup(bvf.w);
            const unsigned long long* ap = (const unsigned long long*)&As[k][tm * 4];
            unsigned long long a0p = ap[0];
            unsigned long long a1p = ap[1];
            fma2(acc[0][0], a0p, bd0); fma2(acc[0][1], a0p, bd1);
            fma2(acc[0][2], a0p, bd2); fma2(acc[0][3], a0p, bd3);
            fma2(acc[1][0], a1p, bd0); fma2(acc[1][1], a1p, bd1);
            fma2(acc[1][2], a1p, bd2); fma2(acc[1][3], a1p, bd3);
        }
        __syncthreads();
    }

#pragma unroll
    for (int r2 = 0; r2 < 2; r2++) {
        float2 c0 = unpack2(acc[r2][0]);
        float2 c1 = unpack2(acc[r2][1]);
        float2 c2 = unpack2(acc[r2][2]);
        float2 c3 = unpack2(acc[r2][3]);
        int r_even = rowBase + tm * 4 + 2 * r2;
        if (r_even < N_NODES) {
            *(float4*)&Cout[(size_t)r_even * C_DIM + tn * 4] =
                make_float4(c0.x, c1.x, c2.x, c3.x);
        }
        if (r_even + 1 < N_NODES) {
            *(float4*)&Cout[(size_t)(r_even + 1) * C_DIM + tn * 4] =
                make_float4(c0.y, c1.y, c2.y, c3.y);
        }
    }
}

// ---------------------------------------------------------------------------
// Fused SpMM layer 1
// ---------------------------------------------------------------------------
__global__ void spmm1_kernel(const float* __restrict__ wv1,
                             const float* __restrict__ b1) {
    const int i = blockIdx.x;
    const int tid = threadIdx.x;
    const int comboOf[3][3] = {{0, 1, 2}, {4, 3, 5}, {7, 8, 6}};

    float agg0 = 0.f, agg1 = 0.f, agg2 = 0.f;

#pragma unroll
    for (int a = 0; a < 3; a++) {
        const int start = g_rowptr[a * (N_NODES + 1) + i];
        const int end   = g_rowptr[a * (N_NODES + 1) + i + 1];
        const float* __restrict__ T0 = g_emb1 + (size_t)comboOf[0][a] * N_NODES * H_DIM;
        const float* __restrict__ T1 = g_emb1 + (size_t)comboOf[1][a] * N_NODES * H_DIM;
        const float* __restrict__ T2 = g_emb1 + (size_t)comboOf[2][a] * N_NODES * H_DIM;
        const int*   __restrict__ col = g_col  + (size_t)a * N_EDGES;
        const float* __restrict__ wv  = g_wval + (size_t)a * N_EDGES;

        float p0 = 0.f, p1 = 0.f, p2 = 0.f;
        for (int e = start; e < end; e++) {
            const int d = __ldg(col + e);
            const float w = __ldg(wv + e);
            const size_t o = (size_t)d * H_DIM + tid;
            p0 += w * __ldg(T0 + o);
            p1 += w * __ldg(T1 + o);
            p2 += w * __ldg(T2 + o);
        }
        agg0 += wv1[comboOf[0][a]] * p0;
        agg1 += wv1[comboOf[1][a]] * p1;
        agg2 += wv1[comboOf[2][a]] * p2;
    }

    const size_t NH = (size_t)N_NODES * H_DIM;
    const size_t oi = (size_t)i * H_DIM + tid;
    g_h[0 * NH + oi] = fmaxf(g_emb1[0 * NH + oi] + 1.01f * agg0 + b1[0 * H_DIM + tid], 0.f);
    g_h[1 * NH + oi] = fmaxf(g_emb1[3 * NH + oi] + 1.01f * agg1 + b1[1 * H_DIM + tid], 0.f);
    g_h[2 * NH + oi] = fmaxf(g_emb1[6 * NH + oi] + 1.01f * agg2 + b1[2 * H_DIM + tid], 0.f);
}

// ---------------------------------------------------------------------------
// Fused SpMM layer 2 + final
// ---------------------------------------------------------------------------
__global__ void spmm2_kernel(const float* __restrict__ wv2,
                             const float* __restrict__ b2,
                             float* __restrict__ out) {
    const int i = blockIdx.x;
    const int tid = threadIdx.x;
    const int comboOf[3][3] = {{0, 1, 2}, {4, 3, 5}, {7, 8, 6}};

    float agg0 = 0.f, agg1 = 0.f, agg2 = 0.f;

#pragma unroll
    for (int a = 0; a < 3; a++) {
        const int start = g_rowptr[a * (N_NODES + 1) + i];
        const int end   = g_rowptr[a * (N_NODES + 1) + i + 1];
        const float* __restrict__ T0 = g_emb2 + (size_t)comboOf[0][a] * N_NODES * C_DIM;
        const float* __restrict__ T1 = g_emb2 + (size_t)comboOf[1][a] * N_NODES * C_DIM;
        const float* __restrict__ T2 = g_emb2 + (size_t)comboOf[2][a] * N_NODES * C_DIM;
        const int*   __restrict__ col = g_col  + (size_t)a * N_EDGES;
        const float* __restrict__ wv  = g_wval + (size_t)a * N_EDGES;

        float p0 = 0.f, p1 = 0.f, p2 = 0.f;
        for (int e = start; e < end; e++) {
            const int d = __ldg(col + e);
            const float w = __ldg(wv + e);
            const size_t o = (size_t)d * C_DIM + tid;
            p0 += w * __ldg(T0 + o);
            p1 += w * __ldg(T1 + o);
            p2 += w * __ldg(T2 + o);
        }
        agg0 += wv2[comboOf[0][a]] * p0;
        agg1 += wv2[comboOf[1][a]] * p1;
        agg2 += wv2[comboOf[2][a]] * p2;
    }

    const size_t NC = (size_t)N_NODES * C_DIM;
    const size_t oi = (size_t)i * C_DIM + tid;
    float y0 = fmaxf(g_emb2[0 * NC + oi] + 1.01f * agg0 + b2[0 * C_DIM + tid], 0.f);
    float y1 = fmaxf(g_emb2[3 * NC + oi] + 1.01f * agg1 + b2[1 * C_DIM + tid], 0.f);
    float y2 = fmaxf(g_emb2[6 * NC + oi] + 1.01f * agg2 + b2[2 * C_DIM + tid], 0.f);
    out[oi] = fabsf((y0 + y1 + y2) * (1.f / 3.f));
}

// ---------------------------------------------------------------------------
extern "C" void kernel_launch(void* const* d_in, const int* in_sizes, int n_in,
                              void* d_out, int out_size) {
    const float* x1 = (const float*)d_in[0];
    const float* x2 = (const float*)d_in[1];
    const float* x3 = (const float*)d_in[2];
    const int*   s0 = (const int*)d_in[3];
    const int*   d0 = (const int*)d_in[4];
    const float* v0 = (const float*)d_in[5];
    const int*   s1 = (const int*)d_in[6];
    const int*   d1 = (const int*)d_in[7];
    const float* v1 = (const float*)d_in[8];
    const int*   s2 = (const int*)d_in[9];
    const int*   d2 = (const int*)d_in[10];
    const float* v2 = (const float*)d_in[11];
    const float* W1  = (const float*)d_in[12];
    const float* wv1 = (const float*)d_in[13];
    const float* b1  = (const float*)d_in[14];
    const float* W2  = (const float*)d_in[15];
    const float* wv2 = (const float*)d_in[16];
    const float* b2  = (const float*)d_in[17];
    float* out = (float*)d_out;

    cudaFuncSetAttribute(gemm1_mma_kernel,
                         cudaFuncAttributeMaxDynamicSharedMemorySize, GSM_TOTAL);

    const dim3 eg((N_EDGES + 255) / 256, 3);

    // operand prep + CSR build
    {
        int tot = 3 * N_NODES * (F_DIM / 4);
        split_x_kernel<<<(tot + 255) / 256, 256>>>(x1, x2, x3);
    }
    {
        int tot = 9 * F_DIM * H_DIM;
        split_w_kernel<<<(tot + 255) / 256, 256>>>(W1);
    }
    csr_zero_kernel<<<(3 * N_NODES + 255) / 256, 256>>>();
    csr_hist_kernel<<<eg, 256>>>(s0, s1, s2);
    csr_scan_kernel<<<3, 1024>>>();
    csr_fill_kernel<<<eg, 256>>>(s0, s1, s2, d0, d1, d2, v0, v1, v2);

    // Layer 1
    gemm1_mma_kernel<<<dim3(157, 9), 256, GSM_TOTAL>>>();
    spmm1_kernel<<<N_NODES, H_DIM>>>(wv1, b1);

    // Layer 2
    const int mblocks = (N_NODES + 63) / 64;
    gemm2_kernel<<<dim3(mblocks, 1, 9), 256>>>(W2);
    spmm2_kernel<<<N_NODES, C_DIM>>>(wv2, b2, out);
}

// round 5
// speedup vs baseline: 2.6872x; 1.2332x over previous
#include <cuda_runtime.h>
#include <cuda_bf16.h>
#include <cuda_fp16.h>
#include <cstdint>

#define N_NODES 20000
#define F_DIM   512
#define H_DIM   128
#define C_DIM   64
#define N_EDGES 640000
#define PAD_ROWS 20096   // 157 * 128

// ---------------------------------------------------------------------------
// Scratch (static device globals; no runtime allocation allowed)
// ---------------------------------------------------------------------------
__device__ float  g_emb1f[3 * N_NODES * H_DIM];   // fp32 self-term tables (gc)
__device__ __half g_emb1h[9 * N_NODES * H_DIM];   // fp16 gather tables (combo)
__device__ float  g_h[3 * N_NODES * H_DIM];       // relu'd layer-1 output
__device__ float  g_emb2f[3 * N_NODES * C_DIM];
__device__ __half g_emb2h[9 * N_NODES * C_DIM];

// bf16 split operands for GEMM1
__device__ __nv_bfloat16 g_xsplit[6 * PAD_ROWS * F_DIM];  // [view*2+term][row][k]
__device__ __nv_bfloat16 g_wt[18 * H_DIM * F_DIM];        // [combo*2+term][n][k]

// CSR scratch
__device__ int  g_rowptr[3 * (N_NODES + 1)];
__device__ int  g_cursor[3 * N_NODES];
__device__ int2 g_edge[3 * N_EDGES];              // {col, w-as-int}

// combo -> which x / adjacency feeds it. combo = gc*3 + role.
__constant__ int c_perm[9] = {0,1,2, 1,0,2, 2,0,1};

// ---------------------------------------------------------------------------
// PTX helpers (base-target only: sm_80+ features)
// ---------------------------------------------------------------------------
__device__ __forceinline__ uint32_t smem_u32(const void* p) {
    uint32_t a;
    asm("{ .reg .u64 t; cvta.to.shared.u64 t, %1; cvt.u32.u64 %0, t; }"
        : "=r"(a) : "l"(p));
    return a;
}

__device__ __forceinline__ void cp_async16(uint32_t dst, const void* src) {
    asm volatile("cp.async.cg.shared.global [%0], [%1], 16;"
                 :: "r"(dst), "l"(src) : "memory");
}
#define CP_COMMIT() asm volatile("cp.async.commit_group;" ::: "memory")
#define CP_WAIT(n)  asm volatile("cp.async.wait_group %0;" :: "n"(n) : "memory")

__device__ __forceinline__ void ldsm_x4(uint32_t& r0, uint32_t& r1,
                                        uint32_t& r2, uint32_t& r3, uint32_t addr) {
    asm volatile("ldmatrix.sync.aligned.m8n8.x4.shared.b16 {%0,%1,%2,%3}, [%4];"
                 : "=r"(r0), "=r"(r1), "=r"(r2), "=r"(r3) : "r"(addr));
}

__device__ __forceinline__ void mma_bf16(float* d, const uint32_t* a,
                                         const uint32_t* b) {
    asm volatile(
        "mma.sync.aligned.m16n8k16.row.col.f32.bf16.bf16.f32 "
        "{%0,%1,%2,%3}, {%4,%5,%6,%7}, {%8,%9}, {%0,%1,%2,%3};"
        : "+f"(d[0]), "+f"(d[1]), "+f"(d[2]), "+f"(d[3])
        : "r"(a[0]), "r"(a[1]), "r"(a[2]), "r"(a[3]), "r"(b[0]), "r"(b[1]));
}

// f32x2 packed helpers (for gemm2)
__device__ __forceinline__ unsigned long long pack_dup(float x) {
    unsigned long long r;
    asm("mov.b64 %0, {%1, %1};" : "=l"(r) : "f"(x));
    return r;
}
__device__ __forceinline__ void fma2(unsigned long long& acc,
                                     unsigned long long a, unsigned long long b) {
    asm("fma.rn.f32x2 %0, %1, %2, %3;" : "=l"(acc) : "l"(a), "l"(b), "l"(acc));
}
__device__ __forceinline__ float2 unpack2(unsigned long long v) {
    float2 f;
    asm("mov.b64 {%0, %1}, %2;" : "=f"(f.x), "=f"(f.y) : "l"(v));
    return f;
}

// ---------------------------------------------------------------------------
// bf16 split kernels
// ---------------------------------------------------------------------------
__device__ __forceinline__ uint32_t pack_bf2(__nv_bfloat16 a, __nv_bfloat16 b) {
    return (uint32_t)__bfloat16_as_ushort(a) | ((uint32_t)__bfloat16_as_ushort(b) << 16);
}

__global__ void split_x_kernel(const float* __restrict__ x1,
                               const float* __restrict__ x2,
                               const float* __restrict__ x3) {
    int i = blockIdx.x * blockDim.x + threadIdx.x;   // one float4 each
    const int total = 3 * N_NODES * (F_DIM / 4);
    if (i >= total) return;
    const int per_view = N_NODES * (F_DIM / 4);
    const int view = i / per_view;
    const int rem  = i - view * per_view;
    const int row  = rem / (F_DIM / 4);
    const int kg   = rem - row * (F_DIM / 4);
    const float* X = (view == 0) ? x1 : (view == 1) ? x2 : x3;
    float4 f = ((const float4*)X)[rem];

    __nv_bfloat16 h0 = __float2bfloat16(f.x), h1 = __float2bfloat16(f.y);
    __nv_bfloat16 h2 = __float2bfloat16(f.z), h3 = __float2bfloat16(f.w);
    __nv_bfloat16 l0 = __float2bfloat16(f.x - __bfloat162float(h0));
    __nv_bfloat16 l1 = __float2bfloat16(f.y - __bfloat162float(h1));
    __nv_bfloat16 l2 = __float2bfloat16(f.z - __bfloat162float(h2));
    __nv_bfloat16 l3 = __float2bfloat16(f.w - __bfloat162float(h3));

    size_t off_hi = ((size_t)(view * 2 + 0) * PAD_ROWS + row) * F_DIM + kg * 4;
    size_t off_lo = ((size_t)(view * 2 + 1) * PAD_ROWS + row) * F_DIM + kg * 4;
    *(uint2*)&g_xsplit[off_hi] = make_uint2(pack_bf2(h0, h1), pack_bf2(h2, h3));
    *(uint2*)&g_xsplit[off_lo] = make_uint2(pack_bf2(l0, l1), pack_bf2(l2, l3));
}

__global__ void split_w_kernel(const float* __restrict__ W1) {
    int i = blockIdx.x * blockDim.x + threadIdx.x;  // over 9*512*128, n fastest
    const int total = 9 * F_DIM * H_DIM;
    if (i >= total) return;
    const int b = i / (F_DIM * H_DIM);
    const int rem = i - b * (F_DIM * H_DIM);
    const int k = rem / H_DIM;
    const int n = rem - k * H_DIM;
    float w = W1[i];
    __nv_bfloat16 hi = __float2bfloat16(w);
    __nv_bfloat16 lo = __float2bfloat16(w - __bfloat162float(hi));
    g_wt[((size_t)(b * 2 + 0) * H_DIM + n) * F_DIM + k] = hi;
    g_wt[((size_t)(b * 2 + 1) * H_DIM + n) * F_DIM + k] = lo;
}

// ---------------------------------------------------------------------------
// CSR build
// ---------------------------------------------------------------------------
__global__ void csr_zero_kernel() {
    int i = blockIdx.x * blockDim.x + threadIdx.x;
    if (i < 3 * N_NODES) g_cursor[i] = 0;
}

__global__ void csr_hist_kernel(const int* __restrict__ s0,
                                const int* __restrict__ s1,
                                const int* __restrict__ s2) {
    int e = blockIdx.x * blockDim.x + threadIdx.x;
    int a = blockIdx.y;
    if (e >= N_EDGES) return;
    const int* s = (a == 0) ? s0 : (a == 1) ? s1 : s2;
    atomicAdd(&g_cursor[a * N_NODES + s[e]], 1);
}

__global__ void csr_scan_kernel() {
    const int a = blockIdx.x;
    __shared__ int sh[1024];
    int* cnt = g_cursor + a * N_NODES;
    int* rp  = g_rowptr + a * (N_NODES + 1);
    int carry = 0;
    for (int base = 0; base < N_NODES; base += 1024) {
        int i = base + threadIdx.x;
        int v = (i < N_NODES) ? cnt[i] : 0;
        sh[threadIdx.x] = v;
        __syncthreads();
        for (int off = 1; off < 1024; off <<= 1) {
            int t = (threadIdx.x >= off) ? sh[threadIdx.x - off] : 0;
            __syncthreads();
            sh[threadIdx.x] += t;
            __syncthreads();
        }
        int inc = sh[threadIdx.x];
        int exc = inc - v;
        if (i < N_NODES) {
            rp[i]  = carry + exc;
            cnt[i] = carry + exc;
        }
        int tot = sh[1023];
        __syncthreads();
        carry += tot;
    }
    if (threadIdx.x == 0) rp[N_NODES] = carry;
}

__global__ void csr_fill_kernel(const int* __restrict__ s0,
                                const int* __restrict__ s1,
                                const int* __restrict__ s2,
                                const int* __restrict__ d0,
                                const int* __restrict__ d1,
                                const int* __restrict__ d2,
                                const float* __restrict__ v0,
                                const float* __restrict__ v1,
                                const float* __restrict__ v2) {
    int e = blockIdx.x * blockDim.x + threadIdx.x;
    int a = blockIdx.y;
    if (e >= N_EDGES) return;
    const int*   s = (a == 0) ? s0 : (a == 1) ? s1 : s2;
    const int*   d = (a == 0) ? d0 : (a == 1) ? d1 : d2;
    const float* v = (a == 0) ? v0 : (a == 1) ? v1 : v2;
    int pos = atomicAdd(&g_cursor[a * N_NODES + s[e]], 1);
    g_edge[a * N_EDGES + pos] = make_int2(d[e], __float_as_int(v[e]));
}

// ---------------------------------------------------------------------------
// GEMM1 (mma.sync bf16x3): emb1[b] = X[perm[b]] @ W1[b], fp32 accumulate.
// grid (157, 9), 256 threads (8 warps, 4m x 2n). CTA tile 128x128, BK=64 bf16.
// 3-stage cp.async pipeline; SW128 swizzle; 24 K-iters (3 terms x 8 chunks).
// Epilogue: half table for all combos, fp32 table for self combos (b%3==0).
// ---------------------------------------------------------------------------
#define TILE_BYTES 16384                  // 128 rows x 128B
#define STAGE_BYTES (2 * TILE_BYTES)      // A + B
#define GSM_TOTAL (3 * STAGE_BYTES)       // 3 stages = 96KB

__global__ void __launch_bounds__(256)
gemm1_mma_kernel() {
    extern __shared__ char smem[];
    const uint32_t sb = smem_u32(smem);
    const int tid = threadIdx.x;
    const int wid = tid >> 5;
    const int lane = tid & 31;
    const int tile = blockIdx.x;
    const int b = blockIdx.y;
    const int view = c_perm[b];
    const int rowBase = tile * 128;

    const int termA[3] = {0, 1, 0};
    const int termB[3] = {0, 0, 1};

    const int wm = wid >> 1;
    const int wn = wid & 1;

    const int arow_l = (lane & 15);
    const uint32_t akh = (uint32_t)(lane >> 4) * 16;
    const int brow_l = (lane & 7) + ((lane >> 4) << 3);
    const uint32_t bkh = (uint32_t)((lane >> 3) & 1) * 16;

    float cfrag[2][8][4];
#pragma unroll
    for (int mi = 0; mi < 2; mi++)
#pragma unroll
        for (int nj = 0; nj < 8; nj++)
#pragma unroll
            for (int q = 0; q < 4; q++) cfrag[mi][nj][q] = 0.f;

    auto prefetch = [&](int it, int bufi) {
        const int t = it >> 3;
        const int c = it & 7;
        const char* Asrc = (const char*)(g_xsplit +
            ((size_t)(view * 2 + termA[t]) * PAD_ROWS + rowBase) * F_DIM) + c * 128;
        const char* Bsrc = (const char*)(g_wt +
            (size_t)(b * 2 + termB[t]) * H_DIM * F_DIM) + c * 128;
        const uint32_t Ab = sb + bufi * STAGE_BYTES;
        const uint32_t Bb = Ab + TILE_BYTES;
#pragma unroll
        for (int i = 0; i < 4; i++) {
            int idx = tid + i * 256;
            int row = idx >> 3;
            int ch  = idx & 7;
            uint32_t off = row * 128 + ch * 16;
            uint32_t sw = off ^ ((off >> 3) & 0x70);
            cp_async16(Ab + sw, Asrc + (size_t)row * (F_DIM * 2) + ch * 16);
            cp_async16(Bb + sw, Bsrc + (size_t)row * (F_DIM * 2) + ch * 16);
        }
        CP_COMMIT();
    };

    prefetch(0, 0);
    prefetch(1, 1);

    for (int it = 0; it < 24; it++) {
        const int bufi = it % 3;
        if (it < 22) {
            prefetch(it + 2, (it + 2) % 3);
            CP_WAIT(2);
        } else {
            CP_WAIT(0);
        }
        __syncthreads();

        const uint32_t Ab = sb + bufi * STAGE_BYTES;
        const uint32_t Bb = Ab + TILE_BYTES;

#pragma unroll
        for (int k16 = 0; k16 < 4; k16++) {
            const uint32_t kb = k16 * 32;
            uint32_t afrag[2][4];
#pragma unroll
            for (int mi = 0; mi < 2; mi++) {
                const int row = wm * 32 + mi * 16 + arow_l;
                const uint32_t addr =
                    Ab + row * 128 + ((kb + akh) ^ (uint32_t)((row & 7) << 4));
                ldsm_x4(afrag[mi][0], afrag[mi][1], afrag[mi][2], afrag[mi][3], addr);
            }
            uint32_t bfrag[8][2];
#pragma unroll
            for (int bj = 0; bj < 4; bj++) {
                const int row = wn * 64 + bj * 16 + brow_l;
                const uint32_t addr =
                    Bb + row * 128 + ((kb + bkh) ^ (uint32_t)((row & 7) << 4));
                uint32_t r0, r1, r2, r3;
                ldsm_x4(r0, r1, r2, r3, addr);
                bfrag[bj * 2 + 0][0] = r0; bfrag[bj * 2 + 0][1] = r1;
                bfrag[bj * 2 + 1][0] = r2; bfrag[bj * 2 + 1][1] = r3;
            }
#pragma unroll
            for (int mi = 0; mi < 2; mi++)
#pragma unroll
                for (int nj = 0; nj < 8; nj++)
                    mma_bf16(cfrag[mi][nj], afrag[mi], bfrag[nj]);
        }
        __syncthreads();
    }

    // Epilogue
    __half* __restrict__ Couth = g_emb1h + (size_t)b * N_NODES * H_DIM;
    const bool self_combo = (b % 3 == 0);
    float* __restrict__ Coutf =
        g_emb1f + (size_t)(b / 3) * N_NODES * H_DIM;
    const int mrow0 = rowBase + wm * 32;
    const int ncol0 = wn * 64;
    const int lr = lane >> 2;
    const int lc = (lane & 3) * 2;
#pragma unroll
    for (int mi = 0; mi < 2; mi++) {
#pragma unroll
        for (int nj = 0; nj < 8; nj++) {
            const int r0 = mrow0 + mi * 16 + lr;
            const int cc = ncol0 + nj * 8 + lc;
            if (r0 < N_NODES) {
                *(__half2*)&Couth[(size_t)r0 * H_DIM + cc] =
                    __float22half2_rn(make_float2(cfrag[mi][nj][0], cfrag[mi][nj][1]));
                if (self_combo)
                    *(float2*)&Coutf[(size_t)r0 * H_DIM + cc] =
                        make_float2(cfrag[mi][nj][0], cfrag[mi][nj][1]);
            }
            if (r0 + 8 < N_NODES) {
                *(__half2*)&Couth[(size_t)(r0 + 8) * H_DIM + cc] =
                    __float22half2_rn(make_float2(cfrag[mi][nj][2], cfrag[mi][nj][3]));
                if (self_combo)
                    *(float2*)&Coutf[(size_t)(r0 + 8) * H_DIM + cc] =
                        make_float2(cfrag[mi][nj][2], cfrag[mi][nj][3]);
            }
        }
    }
}

// ---------------------------------------------------------------------------
// GEMM 2 (FFMA2): emb2[b] (20000x64) = h[perm[b]] (20000x128) @ W2[b]
// Epilogue: half table (all 9 combos) + fp32 table (self combos).
// ---------------------------------------------------------------------------
__global__ void gemm2_kernel(const float* __restrict__ W2) {
    const int b = blockIdx.z;
    const float* __restrict__ Hx = g_h + (size_t)c_perm[b] * N_NODES * H_DIM;
    const float* __restrict__ W  = W2 + (size_t)b * H_DIM * C_DIM;
    __half* __restrict__ Couth = g_emb2h + (size_t)b * N_NODES * C_DIM;
    const bool self_combo = (b % 3 == 0);
    float* __restrict__ Coutf = g_emb2f + (size_t)(b / 3) * N_NODES * C_DIM;

    __shared__ float As[32][64];
    __shared__ float Bs[32][64];

    const int tid = threadIdx.x;
    const int rowBase = blockIdx.x * 64;
    const int tn = tid & 15;
    const int tm = tid >> 4;

    unsigned long long acc[2][4];
#pragma unroll
    for (int i = 0; i < 2; i++)
#pragma unroll
        for (int jj = 0; jj < 4; jj++) acc[i][jj] = 0ull;

    const int lm  = tid & 63;
    const int lkg = tid >> 6;
    const int bk  = tid >> 3;
    const int bng = tid & 7;

    for (int k0 = 0; k0 < H_DIM; k0 += 32) {
        int gr = rowBase + lm;
        if (gr >= N_NODES) gr = N_NODES - 1;
        const float* xp = Hx + (size_t)gr * H_DIM + k0 + lkg * 8;
        float4 a0 = *(const float4*)(xp);
        float4 a1 = *(const float4*)(xp + 4);
        const int kk = lkg * 8;
        As[kk + 0][lm] = a0.x; As[kk + 1][lm] = a0.y;
        As[kk + 2][lm] = a0.z; As[kk + 3][lm] = a0.w;
        As[kk + 4][lm] = a1.x; As[kk + 5][lm] = a1.y;
        As[kk + 6][lm] = a1.z; As[kk + 7][lm] = a1.w;

        const float* wp = W + (size_t)(k0 + bk) * C_DIM + bng * 8;
        float4 b0 = *(const float4*)(wp);
        float4 b1 = *(const float4*)(wp + 4);
        *(float4*)&Bs[bk][bng * 8 + 0] = b0;
        *(float4*)&Bs[bk][bng * 8 + 4] = b1;
        __syncthreads();

#pragma unroll
        for (int k = 0; k < 32; k++) {
            float4 bvf = *(const float4*)&Bs[k][tn * 4];
            unsigned long long bd0 = pack_dup(bvf.x);
            unsigned long long bd1 = pack_dup(bvf.y);
            unsigned long long bd2 = pack_dup(bvf.z);
            unsigned long long bd3 = pack_dup(bvf.w);
            const unsigned long long* ap = (const unsigned long long*)&As[k][tm * 4];
            unsigned long long a0p = ap[0];
            unsigned long long a1p = ap[1];
            fma2(acc[0][0], a0p, bd0); fma2(acc[0][1], a0p, bd1);
            fma2(acc[0][2], a0p, bd2); fma2(acc[0][3], a0p, bd3);
            fma2(acc[1][0], a1p, bd0); fma2(acc[1][1], a1p, bd1);
            fma2(acc[1][2], a1p, bd2); fma2(acc[1][3], a1p, bd3);
        }
        __syncthreads();
    }

#pragma unroll
    for (int r2 = 0; r2 < 2; r2++) {
        float2 c0 = unpack2(acc[r2][0]);
        float2 c1 = unpack2(acc[r2][1]);
        float2 c2 = unpack2(acc[r2][2]);
        float2 c3 = unpack2(acc[r2][3]);
        int r_even = rowBase + tm * 4 + 2 * r2;
        if (r_even < N_NODES) {
            float4 v = make_float4(c0.x, c1.x, c2.x, c3.x);
            __half2 hlo = __float22half2_rn(make_float2(v.x, v.y));
            __half2 hhi = __float22half2_rn(make_float2(v.z, v.w));
            *(uint2*)&Couth[(size_t)r_even * C_DIM + tn * 4] =
                make_uint2(*(uint32_t*)&hlo, *(uint32_t*)&hhi);
            if (self_combo)
                *(float4*)&Coutf[(size_t)r_even * C_DIM + tn * 4] = v;
        }
        if (r_even + 1 < N_NODES) {
            float4 v = make_float4(c0.y, c1.y, c2.y, c3.y);
            __half2 hlo = __float22half2_rn(make_float2(v.x, v.y));
            __half2 hhi = __float22half2_rn(make_float2(v.z, v.w));
            *(uint2*)&Couth[(size_t)(r_even + 1) * C_DIM + tn * 4] =
                make_uint2(*(uint32_t*)&hlo, *(uint32_t*)&hhi);
            if (self_combo)
                *(float4*)&Coutf[(size_t)(r_even + 1) * C_DIM + tn * 4] = v;
        }
    }
}

// ---------------------------------------------------------------------------
// Fused SpMM layer 1: block per node, 64 threads (half2 column pair each).
// ---------------------------------------------------------------------------
__global__ void __launch_bounds__(64) spmm1_kernel(const float* __restrict__ wv1,
                                                   const float* __restrict__ b1) {
    const int i = blockIdx.x;
    const int t = threadIdx.x;
    const int comboOf[3][3] = {{0, 1, 2}, {4, 3, 5}, {7, 8, 6}};

    float2 agg[3] = {{0.f, 0.f}, {0.f, 0.f}, {0.f, 0.f}};

#pragma unroll
    for (int a = 0; a < 3; a++) {
        const int start = g_rowptr[a * (N_NODES + 1) + i];
        const int end   = g_rowptr[a * (N_NODES + 1) + i + 1];
        const __half2* __restrict__ T0 =
            (const __half2*)g_emb1h + (size_t)comboOf[0][a] * N_NODES * (H_DIM / 2);
        const __half2* __restrict__ T1 =
            (const __half2*)g_emb1h + (size_t)comboOf[1][a] * N_NODES * (H_DIM / 2);
        const __half2* __restrict__ T2 =
            (const __half2*)g_emb1h + (size_t)comboOf[2][a] * N_NODES * (H_DIM / 2);
        const int2* __restrict__ ew = g_edge + (size_t)a * N_EDGES;

        float2 p0 = {0.f, 0.f}, p1 = {0.f, 0.f}, p2 = {0.f, 0.f};
        for (int e = start; e < end; e++) {
            const int2 cw = __ldg(&ew[e]);
            const float w = __int_as_float(cw.y);
            const size_t o = (size_t)cw.x * (H_DIM / 2) + t;
            float2 v0 = __half22float2(__ldg(&T0[o]));
            float2 v1 = __half22float2(__ldg(&T1[o]));
            float2 v2 = __half22float2(__ldg(&T2[o]));
            p0.x += w * v0.x; p0.y += w * v0.y;
            p1.x += w * v1.x; p1.y += w * v1.y;
            p2.x += w * v2.x; p2.y += w * v2.y;
        }
        float w0 = wv1[comboOf[0][a]], w1 = wv1[comboOf[1][a]], w2 = wv1[comboOf[2][a]];
        agg[0].x += w0 * p0.x; agg[0].y += w0 * p0.y;
        agg[1].x += w1 * p1.x; agg[1].y += w1 * p1.y;
        agg[2].x += w2 * p2.x; agg[2].y += w2 * p2.y;
    }

    const size_t NH = (size_t)N_NODES * H_DIM;
    const size_t oi = (size_t)i * H_DIM + 2 * t;
#pragma unroll
    for (int gc = 0; gc < 3; gc++) {
        float2 self = *(const float2*)&g_emb1f[gc * NH + oi];
        float2 bias = *(const float2*)&b1[gc * H_DIM + 2 * t];
        float2 hv;
        hv.x = fmaxf(self.x + 1.01f * agg[gc].x + bias.x, 0.f);
        hv.y = fmaxf(self.y + 1.01f * agg[gc].y + bias.y, 0.f);
        *(float2*)&g_h[gc * NH + oi] = hv;
    }
}

// ---------------------------------------------------------------------------
// Fused SpMM layer 2 + final: block per node, 32 threads.
// ---------------------------------------------------------------------------
__global__ void __launch_bounds__(32) spmm2_kernel(const float* __restrict__ wv2,
                                                   const float* __restrict__ b2,
                                                   float* __restrict__ out) {
    const int i = blockIdx.x;
    const int t = threadIdx.x;
    const int comboOf[3][3] = {{0, 1, 2}, {4, 3, 5}, {7, 8, 6}};

    float2 agg[3] = {{0.f, 0.f}, {0.f, 0.f}, {0.f, 0.f}};

#pragma unroll
    for (int a = 0; a < 3; a++) {
        const int start = g_rowptr[a * (N_NODES + 1) + i];
        const int end   = g_rowptr[a * (N_NODES + 1) + i + 1];
        const __half2* __restrict__ T0 =
            (const __half2*)g_emb2h + (size_t)comboOf[0][a] * N_NODES * (C_DIM / 2);
        const __half2* __restrict__ T1 =
            (const __half2*)g_emb2h + (size_t)comboOf[1][a] * N_NODES * (C_DIM / 2);
        const __half2* __restrict__ T2 =
            (const __half2*)g_emb2h + (size_t)comboOf[2][a] * N_NODES * (C_DIM / 2);
        const int2* __restrict__ ew = g_edge + (size_t)a * N_EDGES;

        float2 p0 = {0.f, 0.f}, p1 = {0.f, 0.f}, p2 = {0.f, 0.f};
        for (int e = start; e < end; e++) {
            const int2 cw = __ldg(&ew[e]);
            const float w = __int_as_float(cw.y);
            const size_t o = (size_t)cw.x * (C_DIM / 2) + t;
            float2 v0 = __half22float2(__ldg(&T0[o]));
            float2 v1 = __half22float2(__ldg(&T1[o]));
            float2 v2 = __half22float2(__ldg(&T2[o]));
            p0.x += w * v0.x; p0.y += w * v0.y;
            p1.x += w * v1.x; p1.y += w * v1.y;
            p2.x += w * v2.x; p2.y += w * v2.y;
        }
        float w0 = wv2[comboOf[0][a]], w1 = wv2[comboOf[1][a]], w2 = wv2[comboOf[2][a]];
        agg[0].x += w0 * p0.x; agg[0].y += w0 * p0.y;
        agg[1].x += w1 * p1.x; agg[1].y += w1 * p1.y;
        agg[2].x += w2 * p2.x; agg[2].y += w2 * p2.y;
    }

    const size_t NC = (size_t)N_NODES * C_DIM;
    const size_t oi = (size_t)i * C_DIM + 2 * t;
    float2 ysum = {0.f, 0.f};
#pragma unroll
    for (int gc = 0; gc < 3; gc++) {
        float2 self = *(const float2*)&g_emb2f[gc * NC + oi];
        float2 bias = *(const float2*)&b2[gc * C_DIM + 2 * t];
        ysum.x += fmaxf(self.x + 1.01f * agg[gc].x + bias.x, 0.f);
        ysum.y += fmaxf(self.y + 1.01f * agg[gc].y + bias.y, 0.f);
    }
    *(float2*)&out[oi] = make_float2(fabsf(ysum.x * (1.f / 3.f)),
                                     fabsf(ysum.y * (1.f / 3.f)));
}

// ---------------------------------------------------------------------------
extern "C" void kernel_launch(void* const* d_in, const int* in_sizes, int n_in,
                              void* d_out, int out_size) {
    const float* x1 = (const float*)d_in[0];
    const float* x2 = (const float*)d_in[1];
    const float* x3 = (const float*)d_in[2];
    const int*   s0 = (const int*)d_in[3];
    const int*   d0 = (const int*)d_in[4];
    const float* v0 = (const float*)d_in[5];
    const int*   s1 = (const int*)d_in[6];
    const int*   d1 = (const int*)d_in[7];
    const float* v1 = (const float*)d_in[8];
    const int*   s2 = (const int*)d_in[9];
    const int*   d2 = (const int*)d_in[10];
    const float* v2 = (const float*)d_in[11];
    const float* W1  = (const float*)d_in[12];
    const float* wv1 = (const float*)d_in[13];
    const float* b1  = (const float*)d_in[14];
    const float* W2  = (const float*)d_in[15];
    const float* wv2 = (const float*)d_in[16];
    const float* b2  = (const float*)d_in[17];
    float* out = (float*)d_out;

    cudaFuncSetAttribute(gemm1_mma_kernel,
                         cudaFuncAttributeMaxDynamicSharedMemorySize, GSM_TOTAL);

    const dim3 eg((N_EDGES + 255) / 256, 3);

    // operand prep + CSR build
    {
        int tot = 3 * N_NODES * (F_DIM / 4);
        split_x_kernel<<<(tot + 255) / 256, 256>>>(x1, x2, x3);
    }
    {
        int tot = 9 * F_DIM * H_DIM;
        split_w_kernel<<<(tot + 255) / 256, 256>>>(W1);
    }
    csr_zero_kernel<<<(3 * N_NODES + 255) / 256, 256>>>();
    csr_hist_kernel<<<eg, 256>>>(s0, s1, s2);
    csr_scan_kernel<<<3, 1024>>>();
    csr_fill_kernel<<<eg, 256>>>(s0, s1, s2, d0, d1, d2, v0, v1, v2);

    // Layer 1
    gemm1_mma_kernel<<<dim3(157, 9), 256, GSM_TOTAL>>>();
    spmm1_kernel<<<N_NODES, 64>>>(wv1, b1);

    // Layer 2
    const int mblocks = (N_NODES + 63) / 64;
    gemm2_kernel<<<dim3(mblocks, 1, 9), 256>>>(W2);
    spmm2_kernel<<<N_NODES, 32>>>(wv2, b2, out);
}

// round 6
// speedup vs baseline: 2.9431x; 1.0952x over previous
#include <cuda_runtime.h>
#include <cuda_bf16.h>
#include <cuda_fp16.h>
#include <cstdint>

#define N_NODES 20000
#define F_DIM   512
#define H_DIM   128
#define C_DIM   64
#define N_EDGES 640000
#define PAD_ROWS 20096   // 157 * 128

// ---------------------------------------------------------------------------
// Scratch (static device globals; no runtime allocation allowed)
// ---------------------------------------------------------------------------
__device__ float  g_emb1f[3 * N_NODES * H_DIM];   // fp32 self-term tables (gc)
__device__ __half g_emb1h[9 * N_NODES * H_DIM];   // fp16 gather tables (combo)
__device__ float  g_emb2f[3 * N_NODES * C_DIM];
__device__ __half g_emb2h[9 * N_NODES * C_DIM];

// bf16 split operands
__device__ __nv_bfloat16 g_xsplit[6 * PAD_ROWS * F_DIM];   // [view*2+term][row][k]
__device__ __nv_bfloat16 g_wt[18 * H_DIM * F_DIM];         // [combo*2+term][n][k]
__device__ __nv_bfloat16 g_hsplit[6 * PAD_ROWS * H_DIM];   // [gc*2+term][row][k]
__device__ __nv_bfloat16 g_wt2[18 * C_DIM * H_DIM];        // [combo*2+term][n][k]

// CSR scratch
__device__ int  g_rowptr[3 * (N_NODES + 1)];
__device__ int  g_cursor[3 * N_NODES];
__device__ int2 g_edge[3 * N_EDGES];              // {col, w-as-int}

// combo -> which x / adjacency feeds it. combo = gc*3 + role.
__constant__ int c_perm[9] = {0,1,2, 1,0,2, 2,0,1};

// ---------------------------------------------------------------------------
// PTX helpers (base-target only: sm_80+ features)
// ---------------------------------------------------------------------------
__device__ __forceinline__ uint32_t smem_u32(const void* p) {
    uint32_t a;
    asm("{ .reg .u64 t; cvta.to.shared.u64 t, %1; cvt.u32.u64 %0, t; }"
        : "=r"(a) : "l"(p));
    return a;
}

__device__ __forceinline__ void cp_async16(uint32_t dst, const void* src) {
    asm volatile("cp.async.cg.shared.global [%0], [%1], 16;"
                 :: "r"(dst), "l"(src) : "memory");
}
#define CP_COMMIT() asm volatile("cp.async.commit_group;" ::: "memory")
#define CP_WAIT(n)  asm volatile("cp.async.wait_group %0;" :: "n"(n) : "memory")

__device__ __forceinline__ void ldsm_x4(uint32_t& r0, uint32_t& r1,
                                        uint32_t& r2, uint32_t& r3, uint32_t addr) {
    asm volatile("ldmatrix.sync.aligned.m8n8.x4.shared.b16 {%0,%1,%2,%3}, [%4];"
                 : "=r"(r0), "=r"(r1), "=r"(r2), "=r"(r3) : "r"(addr));
}

__device__ __forceinline__ void mma_bf16(float* d, const uint32_t* a,
                                         const uint32_t* b) {
    asm volatile(
        "mma.sync.aligned.m16n8k16.row.col.f32.bf16.bf16.f32 "
        "{%0,%1,%2,%3}, {%4,%5,%6,%7}, {%8,%9}, {%0,%1,%2,%3};"
        : "+f"(d[0]), "+f"(d[1]), "+f"(d[2]), "+f"(d[3])
        : "r"(a[0]), "r"(a[1]), "r"(a[2]), "r"(a[3]), "r"(b[0]), "r"(b[1]));
}

// ---------------------------------------------------------------------------
// bf16 split kernels
// ---------------------------------------------------------------------------
__device__ __forceinline__ uint32_t pack_bf2(__nv_bfloat16 a, __nv_bfloat16 b) {
    return (uint32_t)__bfloat16_as_ushort(a) | ((uint32_t)__bfloat16_as_ushort(b) << 16);
}

__global__ void split_x_kernel(const float* __restrict__ x1,
                               const float* __restrict__ x2,
                               const float* __restrict__ x3) {
    int i = blockIdx.x * blockDim.x + threadIdx.x;   // one float4 each
    const int total = 3 * N_NODES * (F_DIM / 4);
    if (i >= total) return;
    const int per_view = N_NODES * (F_DIM / 4);
    const int view = i / per_view;
    const int rem  = i - view * per_view;
    const int row  = rem / (F_DIM / 4);
    const int kg   = rem - row * (F_DIM / 4);
    const float* X = (view == 0) ? x1 : (view == 1) ? x2 : x3;
    float4 f = ((const float4*)X)[rem];

    __nv_bfloat16 h0 = __float2bfloat16(f.x), h1 = __float2bfloat16(f.y);
    __nv_bfloat16 h2 = __float2bfloat16(f.z), h3 = __float2bfloat16(f.w);
    __nv_bfloat16 l0 = __float2bfloat16(f.x - __bfloat162float(h0));
    __nv_bfloat16 l1 = __float2bfloat16(f.y - __bfloat162float(h1));
    __nv_bfloat16 l2 = __float2bfloat16(f.z - __bfloat162float(h2));
    __nv_bfloat16 l3 = __float2bfloat16(f.w - __bfloat162float(h3));

    size_t off_hi = ((size_t)(view * 2 + 0) * PAD_ROWS + row) * F_DIM + kg * 4;
    size_t off_lo = ((size_t)(view * 2 + 1) * PAD_ROWS + row) * F_DIM + kg * 4;
    *(uint2*)&g_xsplit[off_hi] = make_uint2(pack_bf2(h0, h1), pack_bf2(h2, h3));
    *(uint2*)&g_xsplit[off_lo] = make_uint2(pack_bf2(l0, l1), pack_bf2(l2, l3));
}

__global__ void split_w_kernel(const float* __restrict__ W1) {
    int i = blockIdx.x * blockDim.x + threadIdx.x;  // over 9*512*128, n fastest
    const int total = 9 * F_DIM * H_DIM;
    if (i >= total) return;
    const int b = i / (F_DIM * H_DIM);
    const int rem = i - b * (F_DIM * H_DIM);
    const int k = rem / H_DIM;
    const int n = rem - k * H_DIM;
    float w = W1[i];
    __nv_bfloat16 hi = __float2bfloat16(w);
    __nv_bfloat16 lo = __float2bfloat16(w - __bfloat162float(hi));
    g_wt[((size_t)(b * 2 + 0) * H_DIM + n) * F_DIM + k] = hi;
    g_wt[((size_t)(b * 2 + 1) * H_DIM + n) * F_DIM + k] = lo;
}

__global__ void split_w2_kernel(const float* __restrict__ W2) {
    int i = blockIdx.x * blockDim.x + threadIdx.x;  // over 9*128*64, n fastest
    const int total = 9 * H_DIM * C_DIM;
    if (i >= total) return;
    const int b = i / (H_DIM * C_DIM);
    const int rem = i - b * (H_DIM * C_DIM);
    const int k = rem / C_DIM;
    const int n = rem - k * C_DIM;
    float w = W2[i];
    __nv_bfloat16 hi = __float2bfloat16(w);
    __nv_bfloat16 lo = __float2bfloat16(w - __bfloat162float(hi));
    g_wt2[((size_t)(b * 2 + 0) * C_DIM + n) * H_DIM + k] = hi;
    g_wt2[((size_t)(b * 2 + 1) * C_DIM + n) * H_DIM + k] = lo;
}

// ---------------------------------------------------------------------------
// CSR build
// ---------------------------------------------------------------------------
__global__ void csr_zero_kernel() {
    int i = blockIdx.x * blockDim.x + threadIdx.x;
    if (i < 3 * N_NODES) g_cursor[i] = 0;
}

__global__ void csr_hist_kernel(const int* __restrict__ s0,
                                const int* __restrict__ s1,
                                const int* __restrict__ s2) {
    int e = blockIdx.x * blockDim.x + threadIdx.x;
    int a = blockIdx.y;
    if (e >= N_EDGES) return;
    const int* s = (a == 0) ? s0 : (a == 1) ? s1 : s2;
    atomicAdd(&g_cursor[a * N_NODES + s[e]], 1);
}

__global__ void csr_scan_kernel() {
    const int a = blockIdx.x;
    __shared__ int sh[1024];
    int* cnt = g_cursor + a * N_NODES;
    int* rp  = g_rowptr + a * (N_NODES + 1);
    int carry = 0;
    for (int base = 0; base < N_NODES; base += 1024) {
        int i = base + threadIdx.x;
        int v = (i < N_NODES) ? cnt[i] : 0;
        sh[threadIdx.x] = v;
        __syncthreads();
        for (int off = 1; off < 1024; off <<= 1) {
            int t = (threadIdx.x >= off) ? sh[threadIdx.x - off] : 0;
            __syncthreads();
            sh[threadIdx.x] += t;
            __syncthreads();
        }
        int inc = sh[threadIdx.x];
        int exc = inc - v;
        if (i < N_NODES) {
            rp[i]  = carry + exc;
            cnt[i] = carry + exc;
        }
        int tot = sh[1023];
        __syncthreads();
        carry += tot;
    }
    if (threadIdx.x == 0) rp[N_NODES] = carry;
}

__global__ void csr_fill_kernel(const int* __restrict__ s0,
                                const int* __restrict__ s1,
                                const int* __restrict__ s2,
                                const int* __restrict__ d0,
                                const int* __restrict__ d1,
                                const int* __restrict__ d2,
                                const float* __restrict__ v0,
                                const float* __restrict__ v1,
                                const float* __restrict__ v2) {
    int e = blockIdx.x * blockDim.x + threadIdx.x;
    int a = blockIdx.y;
    if (e >= N_EDGES) return;
    const int*   s = (a == 0) ? s0 : (a == 1) ? s1 : s2;
    const int*   d = (a == 0) ? d0 : (a == 1) ? d1 : d2;
    const float* v = (a == 0) ? v0 : (a == 1) ? v1 : v2;
    int pos = atomicAdd(&g_cursor[a * N_NODES + s[e]], 1);
    g_edge[a * N_EDGES + pos] = make_int2(d[e], __float_as_int(v[e]));
}

// ---------------------------------------------------------------------------
// GEMM1 (mma.sync bf16x3): emb1[b] = X[perm[b]] @ W1[b], fp32 accumulate.
// grid (157, 9), 256 threads (8 warps, 4m x 2n). CTA tile 128x128, BK=64 bf16.
// 3-stage cp.async pipeline; SW128 swizzle; 24 K-iters (3 terms x 8 chunks).
// ---------------------------------------------------------------------------
#define TILE_BYTES 16384                  // 128 rows x 128B
#define STAGE_BYTES (2 * TILE_BYTES)      // A + B
#define GSM_TOTAL (3 * STAGE_BYTES)       // 3 stages = 96KB

__global__ void __launch_bounds__(256)
gemm1_mma_kernel() {
    extern __shared__ char smem[];
    const uint32_t sb = smem_u32(smem);
    const int tid = threadIdx.x;
    const int wid = tid >> 5;
    const int lane = tid & 31;
    const int tile = blockIdx.x;
    const int b = blockIdx.y;
    const int view = c_perm[b];
    const int rowBase = tile * 128;

    const int termA[3] = {0, 1, 0};
    const int termB[3] = {0, 0, 1};

    const int wm = wid >> 1;
    const int wn = wid & 1;

    const int arow_l = (lane & 15);
    const uint32_t akh = (uint32_t)(lane >> 4) * 16;
    const int brow_l = (lane & 7) + ((lane >> 4) << 3);
    const uint32_t bkh = (uint32_t)((lane >> 3) & 1) * 16;

    float cfrag[2][8][4];
#pragma unroll
    for (int mi = 0; mi < 2; mi++)
#pragma unroll
        for (int nj = 0; nj < 8; nj++)
#pragma unroll
            for (int q = 0; q < 4; q++) cfrag[mi][nj][q] = 0.f;

    auto prefetch = [&](int it, int bufi) {
        const int t = it >> 3;
        const int c = it & 7;
        const char* Asrc = (const char*)(g_xsplit +
            ((size_t)(view * 2 + termA[t]) * PAD_ROWS + rowBase) * F_DIM) + c * 128;
        const char* Bsrc = (const char*)(g_wt +
            (size_t)(b * 2 + termB[t]) * H_DIM * F_DIM) + c * 128;
        const uint32_t Ab = sb + bufi * STAGE_BYTES;
        const uint32_t Bb = Ab + TILE_BYTES;
#pragma unroll
        for (int i = 0; i < 4; i++) {
            int idx = tid + i * 256;
            int row = idx >> 3;
            int ch  = idx & 7;
            uint32_t off = row * 128 + ch * 16;
            uint32_t sw = off ^ ((off >> 3) & 0x70);
            cp_async16(Ab + sw, Asrc + (size_t)row * (F_DIM * 2) + ch * 16);
            cp_async16(Bb + sw, Bsrc + (size_t)row * (F_DIM * 2) + ch * 16);
        }
        CP_COMMIT();
    };

    prefetch(0, 0);
    prefetch(1, 1);

    for (int it = 0; it < 24; it++) {
        const int bufi = it % 3;
        if (it < 22) {
            prefetch(it + 2, (it + 2) % 3);
            CP_WAIT(2);
        } else {
            CP_WAIT(0);
        }
        __syncthreads();

        const uint32_t Ab = sb + bufi * STAGE_BYTES;
        const uint32_t Bb = Ab + TILE_BYTES;

#pragma unroll
        for (int k16 = 0; k16 < 4; k16++) {
            const uint32_t kb = k16 * 32;
            uint32_t afrag[2][4];
#pragma unroll
            for (int mi = 0; mi < 2; mi++) {
                const int row = wm * 32 + mi * 16 + arow_l;
                const uint32_t addr =
                    Ab + row * 128 + ((kb + akh) ^ (uint32_t)((row & 7) << 4));
                ldsm_x4(afrag[mi][0], afrag[mi][1], afrag[mi][2], afrag[mi][3], addr);
            }
            uint32_t bfrag[8][2];
#pragma unroll
            for (int bj = 0; bj < 4; bj++) {
                const int row = wn * 64 + bj * 16 + brow_l;
                const uint32_t addr =
                    Bb + row * 128 + ((kb + bkh) ^ (uint32_t)((row & 7) << 4));
                uint32_t r0, r1, r2, r3;
                ldsm_x4(r0, r1, r2, r3, addr);
                bfrag[bj * 2 + 0][0] = r0; bfrag[bj * 2 + 0][1] = r1;
                bfrag[bj * 2 + 1][0] = r2; bfrag[bj * 2 + 1][1] = r3;
            }
#pragma unroll
            for (int mi = 0; mi < 2; mi++)
#pragma unroll
                for (int nj = 0; nj < 8; nj++)
                    mma_bf16(cfrag[mi][nj], afrag[mi], bfrag[nj]);
        }
        __syncthreads();
    }

    // Epilogue
    __half* __restrict__ Couth = g_emb1h + (size_t)b * N_NODES * H_DIM;
    const bool self_combo = (b % 3 == 0);
    float* __restrict__ Coutf = g_emb1f + (size_t)(b / 3) * N_NODES * H_DIM;
    const int mrow0 = rowBase + wm * 32;
    const int ncol0 = wn * 64;
    const int lr = lane >> 2;
    const int lc = (lane & 3) * 2;
#pragma unroll
    for (int mi = 0; mi < 2; mi++) {
#pragma unroll
        for (int nj = 0; nj < 8; nj++) {
            const int r0 = mrow0 + mi * 16 + lr;
            const int cc = ncol0 + nj * 8 + lc;
            if (r0 < N_NODES) {
                *(__half2*)&Couth[(size_t)r0 * H_DIM + cc] =
                    __float22half2_rn(make_float2(cfrag[mi][nj][0], cfrag[mi][nj][1]));
                if (self_combo)
                    *(float2*)&Coutf[(size_t)r0 * H_DIM + cc] =
                        make_float2(cfrag[mi][nj][0], cfrag[mi][nj][1]);
            }
            if (r0 + 8 < N_NODES) {
                *(__half2*)&Couth[(size_t)(r0 + 8) * H_DIM + cc] =
                    __float22half2_rn(make_float2(cfrag[mi][nj][2], cfrag[mi][nj][3]));
                if (self_combo)
                    *(float2*)&Coutf[(size_t)(r0 + 8) * H_DIM + cc] =
                        make_float2(cfrag[mi][nj][2], cfrag[mi][nj][3]);
            }
        }
    }
}

// ---------------------------------------------------------------------------
// GEMM2 (mma.sync bf16x3): emb2[b] = h[perm[b]] @ W2[b], fp32 accumulate.
// grid (157, 9), 256 threads. CTA tile 128x64, BK=64. 6 K-iters (3 terms x 2).
// A = g_hsplit (bf16 hi/lo written by spmm1), B = g_wt2.
// ---------------------------------------------------------------------------
#define T2_ABYTES 16384                   // 128 rows x 128B
#define T2_BBYTES 8192                    // 64 rows x 128B
#define T2_STAGE  (T2_ABYTES + T2_BBYTES)
#define G2SM_TOTAL (3 * T2_STAGE)         // 72KB

__global__ void __launch_bounds__(256)
gemm2_mma_kernel() {
    extern __shared__ char smem[];
    const uint32_t sb = smem_u32(smem);
    const int tid = threadIdx.x;
    const int wid = tid >> 5;
    const int lane = tid & 31;
    const int tile = blockIdx.x;
    const int b = blockIdx.y;
    const int view = c_perm[b];
    const int rowBase = tile * 128;

    const int termA[3] = {0, 1, 0};
    const int termB[3] = {0, 0, 1};

    const int wm = wid >> 1;
    const int wn = wid & 1;

    const int arow_l = (lane & 15);
    const uint32_t akh = (uint32_t)(lane >> 4) * 16;
    const int brow_l = (lane & 7) + ((lane >> 4) << 3);
    const uint32_t bkh = (uint32_t)((lane >> 3) & 1) * 16;

    float cfrag[2][4][4];
#pragma unroll
    for (int mi = 0; mi < 2; mi++)
#pragma unroll
        for (int nj = 0; nj < 4; nj++)
#pragma unroll
            for (int q = 0; q < 4; q++) cfrag[mi][nj][q] = 0.f;

    auto prefetch = [&](int it, int bufi) {
        const int t = it >> 1;        // term 0..2
        const int c = it & 1;         // k-chunk 0..1
        const char* Asrc = (const char*)(g_hsplit +
            ((size_t)(view * 2 + termA[t]) * PAD_ROWS + rowBase) * H_DIM) + c * 128;
        const char* Bsrc = (const char*)(g_wt2 +
            (size_t)(b * 2 + termB[t]) * C_DIM * H_DIM) + c * 128;
        const uint32_t Ab = sb + bufi * T2_STAGE;
        const uint32_t Bb = Ab + T2_ABYTES;
#pragma unroll
        for (int i = 0; i < 4; i++) {
            int idx = tid + i * 256;
            int row = idx >> 3;
            int ch  = idx & 7;
            uint32_t off = row * 128 + ch * 16;
            uint32_t sw = off ^ ((off >> 3) & 0x70);
            cp_async16(Ab + sw, Asrc + (size_t)row * (H_DIM * 2) + ch * 16);
        }
#pragma unroll
        for (int i = 0; i < 2; i++) {
            int idx = tid + i * 256;
            int row = idx >> 3;       // 0..63
            int ch  = idx & 7;
            uint32_t off = row * 128 + ch * 16;
            uint32_t sw = off ^ ((off >> 3) & 0x70);
            cp_async16(Bb + sw, Bsrc + (size_t)row * (H_DIM * 2) + ch * 16);
        }
        CP_COMMIT();
    };

    prefetch(0, 0);
    prefetch(1, 1);

    for (int it = 0; it < 6; it++) {
        const int bufi = it % 3;
        if (it < 4) {
            prefetch(it + 2, (it + 2) % 3);
            CP_WAIT(2);
        } else {
            CP_WAIT(0);
        }
        __syncthreads();

        const uint32_t Ab = sb + bufi * T2_STAGE;
        const uint32_t Bb = Ab + T2_ABYTES;

#pragma unroll
        for (int k16 = 0; k16 < 4; k16++) {
            const uint32_t kb = k16 * 32;
            uint32_t afrag[2][4];
#pragma unroll
            for (int mi = 0; mi < 2; mi++) {
                const int row = wm * 32 + mi * 16 + arow_l;
                const uint32_t addr =
                    Ab + row * 128 + ((kb + akh) ^ (uint32_t)((row & 7) << 4));
                ldsm_x4(afrag[mi][0], afrag[mi][1], afrag[mi][2], afrag[mi][3], addr);
            }
            uint32_t bfrag[4][2];
#pragma unroll
            for (int bj = 0; bj < 2; bj++) {
                const int row = wn * 32 + bj * 16 + brow_l;
                const uint32_t addr =
                    Bb + row * 128 + ((kb + bkh) ^ (uint32_t)((row & 7) << 4));
                uint32_t r0, r1, r2, r3;
                ldsm_x4(r0, r1, r2, r3, addr);
                bfrag[bj * 2 + 0][0] = r0; bfrag[bj * 2 + 0][1] = r1;
                bfrag[bj * 2 + 1][0] = r2; bfrag[bj * 2 + 1][1] = r3;
            }
#pragma unroll
            for (int mi = 0; mi < 2; mi++)
#pragma unroll
                for (int nj = 0; nj < 4; nj++)
                    mma_bf16(cfrag[mi][nj], afrag[mi], bfrag[nj]);
        }
        __syncthreads();
    }

    // Epilogue
    __half* __restrict__ Couth = g_emb2h + (size_t)b * N_NODES * C_DIM;
    const bool self_combo = (b % 3 == 0);
    float* __restrict__ Coutf = g_emb2f + (size_t)(b / 3) * N_NODES * C_DIM;
    const int mrow0 = rowBase + wm * 32;
    const int ncol0 = wn * 32;
    const int lr = lane >> 2;
    const int lc = (lane & 3) * 2;
#pragma unroll
    for (int mi = 0; mi < 2; mi++) {
#pragma unroll
        for (int nj = 0; nj < 4; nj++) {
            const int r0 = mrow0 + mi * 16 + lr;
            const int cc = ncol0 + nj * 8 + lc;
            if (r0 < N_NODES) {
                *(__half2*)&Couth[(size_t)r0 * C_DIM + cc] =
                    __float22half2_rn(make_float2(cfrag[mi][nj][0], cfrag[mi][nj][1]));
                if (self_combo)
                    *(float2*)&Coutf[(size_t)r0 * C_DIM + cc] =
                        make_float2(cfrag[mi][nj][0], cfrag[mi][nj][1]);
            }
            if (r0 + 8 < N_NODES) {
                *(__half2*)&Couth[(size_t)(r0 + 8) * C_DIM + cc] =
                    __float22half2_rn(make_float2(cfrag[mi][nj][2], cfrag[mi][nj][3]));
                if (self_combo)
                    *(float2*)&Coutf[(size_t)(r0 + 8) * C_DIM + cc] =
                        make_float2(cfrag[mi][nj][2], cfrag[mi][nj][3]);
            }
        }
    }
}

// ---------------------------------------------------------------------------
// Fused SpMM layer 1: block per node, 64 threads (half2 column pair each).
// Epilogue emits h as bf16 hi/lo planes for gemm2's tensor-core path.
// ---------------------------------------------------------------------------
__global__ void __launch_bounds__(64) spmm1_kernel(const float* __restrict__ wv1,
                                                   const float* __restrict__ b1) {
    const int i = blockIdx.x;
    const int t = threadIdx.x;
    const int comboOf[3][3] = {{0, 1, 2}, {4, 3, 5}, {7, 8, 6}};

    float2 agg[3] = {{0.f, 0.f}, {0.f, 0.f}, {0.f, 0.f}};

#pragma unroll
    for (int a = 0; a < 3; a++) {
        const int start = g_rowptr[a * (N_NODES + 1) + i];
        const int end   = g_rowptr[a * (N_NODES + 1) + i + 1];
        const __half2* __restrict__ T0 =
            (const __half2*)g_emb1h + (size_t)comboOf[0][a] * N_NODES * (H_DIM / 2);
        const __half2* __restrict__ T1 =
            (const __half2*)g_emb1h + (size_t)comboOf[1][a] * N_NODES * (H_DIM / 2);
        const __half2* __restrict__ T2 =
            (const __half2*)g_emb1h + (size_t)comboOf[2][a] * N_NODES * (H_DIM / 2);
        const int2* __restrict__ ew = g_edge + (size_t)a * N_EDGES;

        float2 p0 = {0.f, 0.f}, p1 = {0.f, 0.f}, p2 = {0.f, 0.f};
        for (int e = start; e < end; e++) {
            const int2 cw = __ldg(&ew[e]);
            const float w = __int_as_float(cw.y);
            const size_t o = (size_t)cw.x * (H_DIM / 2) + t;
            float2 v0 = __half22float2(__ldg(&T0[o]));
            float2 v1 = __half22float2(__ldg(&T1[o]));
            float2 v2 = __half22float2(__ldg(&T2[o]));
            p0.x += w * v0.x; p0.y += w * v0.y;
            p1.x += w * v1.x; p1.y += w * v1.y;
            p2.x += w * v2.x; p2.y += w * v2.y;
        }
        float w0 = wv1[comboOf[0][a]], w1 = wv1[comboOf[1][a]], w2 = wv1[comboOf[2][a]];
        agg[0].x += w0 * p0.x; agg[0].y += w0 * p0.y;
        agg[1].x += w1 * p1.x; agg[1].y += w1 * p1.y;
        agg[2].x += w2 * p2.x; agg[2].y += w2 * p2.y;
    }

    const size_t NH = (size_t)N_NODES * H_DIM;
    const size_t PH = (size_t)PAD_ROWS * H_DIM;
#pragma unroll
    for (int gc = 0; gc < 3; gc++) {
        float2 self = *(const float2*)&g_emb1f[gc * NH + (size_t)i * H_DIM + 2 * t];
        float2 bias = *(const float2*)&b1[gc * H_DIM + 2 * t];
        float hx = fmaxf(self.x + 1.01f * agg[gc].x + bias.x, 0.f);
        float hy = fmaxf(self.y + 1.01f * agg[gc].y + bias.y, 0.f);
        __nv_bfloat16 hix = __float2bfloat16(hx);
        __nv_bfloat16 hiy = __float2bfloat16(hy);
        __nv_bfloat16 lox = __float2bfloat16(hx - __bfloat162float(hix));
        __nv_bfloat16 loy = __float2bfloat16(hy - __bfloat162float(hiy));
        const size_t base = (size_t)(gc * 2) * PH + (size_t)i * H_DIM + 2 * t;
        *(uint32_t*)&g_hsplit[base]      = pack_bf2(hix, hiy);
        *(uint32_t*)&g_hsplit[base + PH] = pack_bf2(lox, loy);
    }
}

// ---------------------------------------------------------------------------
// Fused SpMM layer 2 + final: block per node, 32 threads.
// ---------------------------------------------------------------------------
__global__ void __launch_bounds__(32) spmm2_kernel(const float* __restrict__ wv2,
                                                   const float* __restrict__ b2,
                                                   float* __restrict__ out) {
    const int i = blockIdx.x;
    const int t = threadIdx.x;
    const int comboOf[3][3] = {{0, 1, 2}, {4, 3, 5}, {7, 8, 6}};

    float2 agg[3] = {{0.f, 0.f}, {0.f, 0.f}, {0.f, 0.f}};

#pragma unroll
    for (int a = 0; a < 3; a++) {
        const int start = g_rowptr[a * (N_NODES + 1) + i];
        const int end   = g_rowptr[a * (N_NODES + 1) + i + 1];
        const __half2* __restrict__ T0 =
            (const __half2*)g_emb2h + (size_t)comboOf[0][a] * N_NODES * (C_DIM / 2);
        const __half2* __restrict__ T1 =
            (const __half2*)g_emb2h + (size_t)comboOf[1][a] * N_NODES * (C_DIM / 2);
        const __half2* __restrict__ T2 =
            (const __half2*)g_emb2h + (size_t)comboOf[2][a] * N_NODES * (C_DIM / 2);
        const int2* __restrict__ ew = g_edge + (size_t)a * N_EDGES;

        float2 p0 = {0.f, 0.f}, p1 = {0.f, 0.f}, p2 = {0.f, 0.f};
        for (int e = start; e < end; e++) {
            const int2 cw = __ldg(&ew[e]);
            const float w = __int_as_float(cw.y);
            const size_t o = (size_t)cw.x * (C_DIM / 2) + t;
            float2 v0 = __half22float2(__ldg(&T0[o]));
            float2 v1 = __half22float2(__ldg(&T1[o]));
            float2 v2 = __half22float2(__ldg(&T2[o]));
            p0.x += w * v0.x; p0.y += w * v0.y;
            p1.x += w * v1.x; p1.y += w * v1.y;
            p2.x += w * v2.x; p2.y += w * v2.y;
        }
        float w0 = wv2[comboOf[0][a]], w1 = wv2[comboOf[1][a]], w2 = wv2[comboOf[2][a]];
        agg[0].x += w0 * p0.x; agg[0].y += w0 * p0.y;
        agg[1].x += w1 * p1.x; agg[1].y += w1 * p1.y;
        agg[2].x += w2 * p2.x; agg[2].y += w2 * p2.y;
    }

    const size_t NC = (size_t)N_NODES * C_DIM;
    const size_t oi = (size_t)i * C_DIM + 2 * t;
    float2 ysum = {0.f, 0.f};
#pragma unroll
    for (int gc = 0; gc < 3; gc++) {
        float2 self = *(const float2*)&g_emb2f[gc * NC + oi];
        float2 bias = *(const float2*)&b2[gc * C_DIM + 2 * t];
        ysum.x += fmaxf(self.x + 1.01f * agg[gc].x + bias.x, 0.f);
        ysum.y += fmaxf(self.y + 1.01f * agg[gc].y + bias.y, 0.f);
    }
    *(float2*)&out[oi] = make_float2(fabsf(ysum.x * (1.f / 3.f)),
                                     fabsf(ysum.y * (1.f / 3.f)));
}

// ---------------------------------------------------------------------------
extern "C" void kernel_launch(void* const* d_in, const int* in_sizes, int n_in,
                              void* d_out, int out_size) {
    const float* x1 = (const float*)d_in[0];
    const float* x2 = (const float*)d_in[1];
    const float* x3 = (const float*)d_in[2];
    const int*   s0 = (const int*)d_in[3];
    const int*   d0 = (const int*)d_in[4];
    const float* v0 = (const float*)d_in[5];
    const int*   s1 = (const int*)d_in[6];
    const int*   d1 = (const int*)d_in[7];
    const float* v1 = (const float*)d_in[8];
    const int*   s2 = (const int*)d_in[9];
    const int*   d2 = (const int*)d_in[10];
    const float* v2 = (const float*)d_in[11];
    const float* W1  = (const float*)d_in[12];
    const float* wv1 = (const float*)d_in[13];
    const float* b1  = (const float*)d_in[14];
    const float* W2  = (const float*)d_in[15];
    const float* wv2 = (const float*)d_in[16];
    const float* b2  = (const float*)d_in[17];
    float* out = (float*)d_out;

    cudaFuncSetAttribute(gemm1_mma_kernel,
                         cudaFuncAttributeMaxDynamicSharedMemorySize, GSM_TOTAL);
    cudaFuncSetAttribute(gemm2_mma_kernel,
                         cudaFuncAttributeMaxDynamicSharedMemorySize, G2SM_TOTAL);

    const dim3 eg((N_EDGES + 255) / 256, 3);

    // operand prep + CSR build
    {
        int tot = 3 * N_NODES * (F_DIM / 4);
        split_x_kernel<<<(tot + 255) / 256, 256>>>(x1, x2, x3);
    }
    {
        int tot = 9 * F_DIM * H_DIM;
        split_w_kernel<<<(tot + 255) / 256, 256>>>(W1);
    }
    {
        int tot = 9 * H_DIM * C_DIM;
        split_w2_kernel<<<(tot + 255) / 256, 256>>>(W2);
    }
    csr_zero_kernel<<<(3 * N_NODES + 255) / 256, 256>>>();
    csr_hist_kernel<<<eg, 256>>>(s0, s1, s2);
    csr_scan_kernel<<<3, 1024>>>();
    csr_fill_kernel<<<eg, 256>>>(s0, s1, s2, d0, d1, d2, v0, v1, v2);

    // Layer 1
    gemm1_mma_kernel<<<dim3(157, 9), 256, GSM_TOTAL>>>();
    spmm1_kernel<<<N_NODES, 64>>>(wv1, b1);

    // Layer 2
    gemm2_mma_kernel<<<dim3(157, 9), 256, G2SM_TOTAL>>>();
    spmm2_kernel<<<N_NODES, 32>>>(wv2, b2, out);
}

// round 8
// speedup vs baseline: 3.0344x; 1.0310x over previous
#include <cuda_runtime.h>
#include <cuda_bf16.h>
#include <cuda_fp16.h>
#include <cstdint>

#define N_NODES 20000
#define F_DIM   512
#define H_DIM   128
#define C_DIM   64
#define N_EDGES 640000
#define PAD_ROWS 20096       // 157 * 128
#define RP_STRIDE 20004      // N_NODES+1 padded to 4-int alignment

// ---------------------------------------------------------------------------
// Scratch (static device globals; no runtime allocation allowed)
// ---------------------------------------------------------------------------
__device__ float  g_emb1f[3 * N_NODES * H_DIM];   // fp32 self-term tables (gc)
__device__ __half g_emb1h[9 * N_NODES * H_DIM];   // fp16 gather tables (combo)
__device__ float  g_emb2f[3 * N_NODES * C_DIM];
__device__ __half g_emb2h[9 * N_NODES * C_DIM];

// bf16 split operands
__device__ __nv_bfloat16 g_xsplit[6 * PAD_ROWS * F_DIM];   // [view*2+term][row][k]
__device__ __nv_bfloat16 g_wt[18 * H_DIM * F_DIM];         // [combo*2+term][n][k]
__device__ __nv_bfloat16 g_hsplit[6 * PAD_ROWS * H_DIM];   // [gc*2+term][row][k]
__device__ __nv_bfloat16 g_wt2[18 * C_DIM * H_DIM];        // [combo*2+term][n][k]

// CSR scratch
__device__ int  g_rowptr[3 * RP_STRIDE];
__device__ int  g_cursor[3 * N_NODES];
__device__ int2 g_edge[3 * N_EDGES];              // {col, w-as-int}

// combo -> which x / adjacency feeds it. combo = gc*3 + role.
__constant__ int c_perm[9] = {0,1,2, 1,0,2, 2,0,1};

// ---------------------------------------------------------------------------
// PTX helpers (base-target only: sm_80+ features)
// ---------------------------------------------------------------------------
__device__ __forceinline__ uint32_t smem_u32(const void* p) {
    uint32_t a;
    asm("{ .reg .u64 t; cvta.to.shared.u64 t, %1; cvt.u32.u64 %0, t; }"
        : "=r"(a) : "l"(p));
    return a;
}

__device__ __forceinline__ void cp_async16(uint32_t dst, const void* src) {
    asm volatile("cp.async.cg.shared.global [%0], [%1], 16;"
                 :: "r"(dst), "l"(src) : "memory");
}
#define CP_COMMIT() asm volatile("cp.async.commit_group;" ::: "memory")
#define CP_WAIT(n)  asm volatile("cp.async.wait_group %0;" :: "n"(n) : "memory")

__device__ __forceinline__ void ldsm_x4(uint32_t& r0, uint32_t& r1,
                                        uint32_t& r2, uint32_t& r3, uint32_t addr) {
    asm volatile("ldmatrix.sync.aligned.m8n8.x4.shared.b16 {%0,%1,%2,%3}, [%4];"
                 : "=r"(r0), "=r"(r1), "=r"(r2), "=r"(r3) : "r"(addr));
}

__device__ __forceinline__ void mma_bf16(float* d, const uint32_t* a,
                                         const uint32_t* b) {
    asm volatile(
        "mma.sync.aligned.m16n8k16.row.col.f32.bf16.bf16.f32 "
        "{%0,%1,%2,%3}, {%4,%5,%6,%7}, {%8,%9}, {%0,%1,%2,%3};"
        : "+f"(d[0]), "+f"(d[1]), "+f"(d[2]), "+f"(d[3])
        : "r"(a[0]), "r"(a[1]), "r"(a[2]), "r"(a[3]), "r"(b[0]), "r"(b[1]));
}

__device__ __forceinline__ uint32_t pack_bf2(__nv_bfloat16 a, __nv_bfloat16 b) {
    return (uint32_t)__bfloat16_as_ushort(a) | ((uint32_t)__bfloat16_as_ushort(b) << 16);
}

// ---------------------------------------------------------------------------
// K0: csr_zero — MUST be its own kernel: every g_cursor write must be globally
// visible before ANY histogram atomic. (R7 bug: zeroing inside prep raced.)
// ---------------------------------------------------------------------------
__global__ void csr_zero_kernel() {
    int i = blockIdx.x * blockDim.x + threadIdx.x;
    if (i < 3 * N_NODES) g_cursor[i] = 0;
}

// ---------------------------------------------------------------------------
// K1: fused prep — split_x | split_w | split_w2 | csr_hist (NO zeroing here)
// Block ranges (256 threads each):
//   [0, 30000)            split_x  (3*20000*512/4 f4 elems / 256)
//   [30000, 32304)        split_w  (9*512*128 / 256)
//   [32304, 32592)        split_w2 (9*128*64 / 256)
//   [32592, 34467)        csr_hist (3 adjacencies x 625 blocks, 4 edges/thr)
// ---------------------------------------------------------------------------
#define NB_SPLITX 30000
#define NB_SPLITW 2304
#define NB_SPLITW2 288
#define NB_HIST_PER 625
#define B_SPLITW  (NB_SPLITX)
#define B_SPLITW2 (B_SPLITW + NB_SPLITW)
#define B_HIST    (B_SPLITW2 + NB_SPLITW2)
#define NB_PREP   (B_HIST + 3 * NB_HIST_PER)

__global__ void __launch_bounds__(256)
prep_kernel(const float* __restrict__ x1, const float* __restrict__ x2,
            const float* __restrict__ x3, const float* __restrict__ W1,
            const float* __restrict__ W2,
            const int* __restrict__ s0, const int* __restrict__ s1,
            const int* __restrict__ s2) {
    const int bid = blockIdx.x;
    const int tid = threadIdx.x;

    if (bid < NB_SPLITX) {
        int i = bid * 256 + tid;  // one float4 each
        const int per_view = N_NODES * (F_DIM / 4);
        const int view = i / per_view;
        const int rem  = i - view * per_view;
        const int row  = rem / (F_DIM / 4);
        const int kg   = rem - row * (F_DIM / 4);
        const float* X = (view == 0) ? x1 : (view == 1) ? x2 : x3;
        float4 f = ((const float4*)X)[rem];

        __nv_bfloat16 h0 = __float2bfloat16(f.x), h1 = __float2bfloat16(f.y);
        __nv_bfloat16 h2 = __float2bfloat16(f.z), h3 = __float2bfloat16(f.w);
        __nv_bfloat16 l0 = __float2bfloat16(f.x - __bfloat162float(h0));
        __nv_bfloat16 l1 = __float2bfloat16(f.y - __bfloat162float(h1));
        __nv_bfloat16 l2 = __float2bfloat16(f.z - __bfloat162float(h2));
        __nv_bfloat16 l3 = __float2bfloat16(f.w - __bfloat162float(h3));

        size_t off_hi = ((size_t)(view * 2 + 0) * PAD_ROWS + row) * F_DIM + kg * 4;
        size_t off_lo = ((size_t)(view * 2 + 1) * PAD_ROWS + row) * F_DIM + kg * 4;
        *(uint2*)&g_xsplit[off_hi] = make_uint2(pack_bf2(h0, h1), pack_bf2(h2, h3));
        *(uint2*)&g_xsplit[off_lo] = make_uint2(pack_bf2(l0, l1), pack_bf2(l2, l3));
    } else if (bid < B_SPLITW2) {
        int i = (bid - B_SPLITW) * 256 + tid;   // over 9*512*128, n fastest
        const int b = i / (F_DIM * H_DIM);
        const int rem = i - b * (F_DIM * H_DIM);
        const int k = rem / H_DIM;
        const int n = rem - k * H_DIM;
        float w = W1[i];
        __nv_bfloat16 hi = __float2bfloat16(w);
        __nv_bfloat16 lo = __float2bfloat16(w - __bfloat162float(hi));
        g_wt[((size_t)(b * 2 + 0) * H_DIM + n) * F_DIM + k] = hi;
        g_wt[((size_t)(b * 2 + 1) * H_DIM + n) * F_DIM + k] = lo;
    } else if (bid < B_HIST) {
        int i = (bid - B_SPLITW2) * 256 + tid;  // over 9*128*64
        const int b = i / (H_DIM * C_DIM);
        const int rem = i - b * (H_DIM * C_DIM);
        const int k = rem / C_DIM;
        const int n = rem - k * C_DIM;
        float w = W2[i];
        __nv_bfloat16 hi = __float2bfloat16(w);
        __nv_bfloat16 lo = __float2bfloat16(w - __bfloat162float(hi));
        g_wt2[((size_t)(b * 2 + 0) * C_DIM + n) * H_DIM + k] = hi;
        g_wt2[((size_t)(b * 2 + 1) * C_DIM + n) * H_DIM + k] = lo;
    } else {
        const int rel = bid - B_HIST;
        const int a = rel / NB_HIST_PER;
        const int blk = rel - a * NB_HIST_PER;
        const int* __restrict__ s = (a == 0) ? s0 : (a == 1) ? s1 : s2;
        int* __restrict__ cur = g_cursor + a * N_NODES;
        const int base = blk * 1024 + tid;
#pragma unroll
        for (int k = 0; k < 4; k++)
            atomicAdd(&cur[__ldg(&s[base + k * 256])], 1);
    }
}

// ---------------------------------------------------------------------------
// K3: csr_fill — 4 edges per thread (MLP), grid (625, 3)
// ---------------------------------------------------------------------------
__global__ void __launch_bounds__(256)
csr_fill_kernel(const int* __restrict__ s0, const int* __restrict__ s1,
                const int* __restrict__ s2, const int* __restrict__ d0,
                const int* __restrict__ d1, const int* __restrict__ d2,
                const float* __restrict__ v0, const float* __restrict__ v1,
                const float* __restrict__ v2) {
    const int a = blockIdx.y;
    const int*   __restrict__ s = (a == 0) ? s0 : (a == 1) ? s1 : s2;
    const int*   __restrict__ d = (a == 0) ? d0 : (a == 1) ? d1 : d2;
    const float* __restrict__ v = (a == 0) ? v0 : (a == 1) ? v1 : v2;
    int* __restrict__ cur = g_cursor + a * N_NODES;
    int2* __restrict__ eo = g_edge + (size_t)a * N_EDGES;
    const int base = blockIdx.x * 1024 + threadIdx.x;
#pragma unroll
    for (int k = 0; k < 4; k++) {
        const int e = base + k * 256;
        const int ss = __ldg(&s[e]);
        const int dd = __ldg(&d[e]);
        const float vv = __ldg(&v[e]);
        int pos = atomicAdd(&cur[ss], 1);
        eo[pos] = make_int2(dd, __float_as_int(vv));
    }
}

// ---------------------------------------------------------------------------
// K2: GEMM1 (mma.sync bf16x3) + piggybacked csr_scan.
// grid: 1413 gemm blocks (tile-major) + 3 scan blocks. 256 threads.
// ---------------------------------------------------------------------------
#define TILE_BYTES 16384                  // 128 rows x 128B
#define STAGE_BYTES (2 * TILE_BYTES)      // A + B
#define GSM_TOTAL (3 * STAGE_BYTES)       // 3 stages = 96KB
#define NB_GEMM1 (157 * 9)

__device__ __forceinline__ void csr_scan_block(int a) {
    __shared__ int s_warp[9];
    int* cnt = g_cursor + a * N_NODES;
    int* rp  = g_rowptr + a * RP_STRIDE;
    const int tid = threadIdx.x;
    const int lane = tid & 31;
    const int w = tid >> 5;
    int carry = 0;
    for (int base = 0; base < N_NODES; base += 1024) {
        const int idx = base + tid * 4;
        int v0 = 0, v1 = 0, v2 = 0, v3 = 0;
        if (idx + 3 < N_NODES) {
            int4 t = *(const int4*)&cnt[idx];
            v0 = t.x; v1 = t.y; v2 = t.z; v3 = t.w;
        } else {
            if (idx + 0 < N_NODES) v0 = cnt[idx + 0];
            if (idx + 1 < N_NODES) v1 = cnt[idx + 1];
            if (idx + 2 < N_NODES) v2 = cnt[idx + 2];
            if (idx + 3 < N_NODES) v3 = cnt[idx + 3];
        }
        const int tsum = v0 + v1 + v2 + v3;
        int sc = tsum;
#pragma unroll
        for (int o = 1; o < 32; o <<= 1) {
            int n = __shfl_up_sync(0xffffffff, sc, o);
            if (lane >= o) sc += n;
        }
        if (lane == 31) s_warp[w] = sc;
        __syncthreads();
        if (w == 0) {
            int x = (lane < 8) ? s_warp[lane] : 0;
#pragma unroll
            for (int o = 1; o < 8; o <<= 1) {
                int n = __shfl_up_sync(0xffffffff, x, o);
                if (lane >= o) x += n;
            }
            if (lane < 8) s_warp[lane] = x;
            if (lane == 7) s_warp[8] = x;
        }
        __syncthreads();
        const int warp_off = (w == 0) ? 0 : s_warp[w - 1];
        const int excl = carry + warp_off + (sc - tsum);
        const int p0 = excl, p1 = p0 + v0, p2 = p1 + v1, p3 = p2 + v2;
        if (idx + 3 < N_NODES) {
            *(int4*)&rp[idx]  = make_int4(p0, p1, p2, p3);
            *(int4*)&cnt[idx] = make_int4(p0, p1, p2, p3);
        } else {
            if (idx + 0 < N_NODES) { rp[idx + 0] = p0; cnt[idx + 0] = p0; }
            if (idx + 1 < N_NODES) { rp[idx + 1] = p1; cnt[idx + 1] = p1; }
            if (idx + 2 < N_NODES) { rp[idx + 2] = p2; cnt[idx + 2] = p2; }
            if (idx + 3 < N_NODES) { rp[idx + 3] = p3; cnt[idx + 3] = p3; }
        }
        carry += s_warp[8];
        __syncthreads();
    }
    if (tid == 0) rp[N_NODES] = carry;
}

__global__ void __launch_bounds__(256)
gemm1_mma_kernel() {
    if (blockIdx.x >= NB_GEMM1) {       // piggybacked scan blocks
        csr_scan_block(blockIdx.x - NB_GEMM1);
        return;
    }
    extern __shared__ char smem[];
    const uint32_t sb = smem_u32(smem);
    const int tid = threadIdx.x;
    const int wid = tid >> 5;
    const int lane = tid & 31;
    const int tile = blockIdx.x % 157;
    const int b = blockIdx.x / 157;
    const int view = c_perm[b];
    const int rowBase = tile * 128;

    const int termA[3] = {0, 1, 0};
    const int termB[3] = {0, 0, 1};

    const int wm = wid >> 1;
    const int wn = wid & 1;

    const int arow_l = (lane & 15);
    const uint32_t akh = (uint32_t)(lane >> 4) * 16;
    const int brow_l = (lane & 7) + ((lane >> 4) << 3);
    const uint32_t bkh = (uint32_t)((lane >> 3) & 1) * 16;

    float cfrag[2][8][4];
#pragma unroll
    for (int mi = 0; mi < 2; mi++)
#pragma unroll
        for (int nj = 0; nj < 8; nj++)
#pragma unroll
            for (int q = 0; q < 4; q++) cfrag[mi][nj][q] = 0.f;

    auto prefetch = [&](int it, int bufi) {
        const int t = it >> 3;
        const int c = it & 7;
        const char* Asrc = (const char*)(g_xsplit +
            ((size_t)(view * 2 + termA[t]) * PAD_ROWS + rowBase) * F_DIM) + c * 128;
        const char* Bsrc = (const char*)(g_wt +
            (size_t)(b * 2 + termB[t]) * H_DIM * F_DIM) + c * 128;
        const uint32_t Ab = sb + bufi * STAGE_BYTES;
        const uint32_t Bb = Ab + TILE_BYTES;
#pragma unroll
        for (int i = 0; i < 4; i++) {
            int idx = tid + i * 256;
            int row = idx >> 3;
            int ch  = idx & 7;
            uint32_t off = row * 128 + ch * 16;
            uint32_t sw = off ^ ((off >> 3) & 0x70);
            cp_async16(Ab + sw, Asrc + (size_t)row * (F_DIM * 2) + ch * 16);
            cp_async16(Bb + sw, Bsrc + (size_t)row * (F_DIM * 2) + ch * 16);
        }
        CP_COMMIT();
    };

    prefetch(0, 0);
    prefetch(1, 1);

    for (int it = 0; it < 24; it++) {
        const int bufi = it % 3;
        if (it < 22) {
            prefetch(it + 2, (it + 2) % 3);
            CP_WAIT(2);
        } else {
            CP_WAIT(0);
        }
        __syncthreads();

        const uint32_t Ab = sb + bufi * STAGE_BYTES;
        const uint32_t Bb = Ab + TILE_BYTES;

#pragma unroll
        for (int k16 = 0; k16 < 4; k16++) {
            const uint32_t kb = k16 * 32;
            uint32_t afrag[2][4];
#pragma unroll
            for (int mi = 0; mi < 2; mi++) {
                const int row = wm * 32 + mi * 16 + arow_l;
                const uint32_t addr =
                    Ab + row * 128 + ((kb + akh) ^ (uint32_t)((row & 7) << 4));
                ldsm_x4(afrag[mi][0], afrag[mi][1], afrag[mi][2], afrag[mi][3], addr);
            }
            uint32_t bfrag[8][2];
#pragma unroll
            for (int bj = 0; bj < 4; bj++) {
                const int row = wn * 64 + bj * 16 + brow_l;
                const uint32_t addr =
                    Bb + row * 128 + ((kb + bkh) ^ (uint32_t)((row & 7) << 4));
                uint32_t r0, r1, r2, r3;
                ldsm_x4(r0, r1, r2, r3, addr);
                bfrag[bj * 2 + 0][0] = r0; bfrag[bj * 2 + 0][1] = r1;
                bfrag[bj * 2 + 1][0] = r2; bfrag[bj * 2 + 1][1] = r3;
            }
#pragma unroll
            for (int mi = 0; mi < 2; mi++)
#pragma unroll
                for (int nj = 0; nj < 8; nj++)
                    mma_bf16(cfrag[mi][nj], afrag[mi], bfrag[nj]);
        }
        __syncthreads();
    }

    // Epilogue
    __half* __restrict__ Couth = g_emb1h + (size_t)b * N_NODES * H_DIM;
    const bool self_combo = (b % 3 == 0);
    float* __restrict__ Coutf = g_emb1f + (size_t)(b / 3) * N_NODES * H_DIM;
    const int mrow0 = rowBase + wm * 32;
    const int ncol0 = wn * 64;
    const int lr = lane >> 2;
    const int lc = (lane & 3) * 2;
#pragma unroll
    for (int mi = 0; mi < 2; mi++) {
#pragma unroll
        for (int nj = 0; nj < 8; nj++) {
            const int r0 = mrow0 + mi * 16 + lr;
            const int cc = ncol0 + nj * 8 + lc;
            if (r0 < N_NODES) {
                *(__half2*)&Couth[(size_t)r0 * H_DIM + cc] =
                    __float22half2_rn(make_float2(cfrag[mi][nj][0], cfrag[mi][nj][1]));
                if (self_combo)
                    *(float2*)&Coutf[(size_t)r0 * H_DIM + cc] =
                        make_float2(cfrag[mi][nj][0], cfrag[mi][nj][1]);
            }
            if (r0 + 8 < N_NODES) {
                *(__half2*)&Couth[(size_t)(r0 + 8) * H_DIM + cc] =
                    __float22half2_rn(make_float2(cfrag[mi][nj][2], cfrag[mi][nj][3]));
                if (self_combo)
                    *(float2*)&Coutf[(size_t)(r0 + 8) * H_DIM + cc] =
                        make_float2(cfrag[mi][nj][2], cfrag[mi][nj][3]);
            }
        }
    }
}

// ---------------------------------------------------------------------------
// GEMM2 (mma.sync bf16x3): emb2[b] = h[perm[b]] @ W2[b], fp32 accumulate.
// ---------------------------------------------------------------------------
#define T2_ABYTES 16384                   // 128 rows x 128B
#define T2_BBYTES 8192                    // 64 rows x 128B
#define T2_STAGE  (T2_ABYTES + T2_BBYTES)
#define G2SM_TOTAL (3 * T2_STAGE)         // 72KB

__global__ void __launch_bounds__(256)
gemm2_mma_kernel() {
    extern __shared__ char smem[];
    const uint32_t sb = smem_u32(smem);
    const int tid = threadIdx.x;
    const int wid = tid >> 5;
    const int lane = tid & 31;
    const int tile = blockIdx.x;
    const int b = blockIdx.y;
    const int view = c_perm[b];
    const int rowBase = tile * 128;

    const int termA[3] = {0, 1, 0};
    const int termB[3] = {0, 0, 1};

    const int wm = wid >> 1;
    const int wn = wid & 1;

    const int arow_l = (lane & 15);
    const uint32_t akh = (uint32_t)(lane >> 4) * 16;
    const int brow_l = (lane & 7) + ((lane >> 4) << 3);
    const uint32_t bkh = (uint32_t)((lane >> 3) & 1) * 16;

    float cfrag[2][4][4];
#pragma unroll
    for (int mi = 0; mi < 2; mi++)
#pragma unroll
        for (int nj = 0; nj < 4; nj++)
#pragma unroll
            for (int q = 0; q < 4; q++) cfrag[mi][nj][q] = 0.f;

    auto prefetch = [&](int it, int bufi) {
        const int t = it >> 1;
        const int c = it & 1;
        const char* Asrc = (const char*)(g_hsplit +
            ((size_t)(view * 2 + termA[t]) * PAD_ROWS + rowBase) * H_DIM) + c * 128;
        const char* Bsrc = (const char*)(g_wt2 +
            (size_t)(b * 2 + termB[t]) * C_DIM * H_DIM) + c * 128;
        const uint32_t Ab = sb + bufi * T2_STAGE;
        const uint32_t Bb = Ab + T2_ABYTES;
#pragma unroll
        for (int i = 0; i < 4; i++) {
            int idx = tid + i * 256;
            int row = idx >> 3;
            int ch  = idx & 7;
            uint32_t off = row * 128 + ch * 16;
            uint32_t sw = off ^ ((off >> 3) & 0x70);
            cp_async16(Ab + sw, Asrc + (size_t)row * (H_DIM * 2) + ch * 16);
        }
#pragma unroll
        for (int i = 0; i < 2; i++) {
            int idx = tid + i * 256;
            int row = idx >> 3;
            int ch  = idx & 7;
            uint32_t off = row * 128 + ch * 16;
            uint32_t sw = off ^ ((off >> 3) & 0x70);
            cp_async16(Bb + sw, Bsrc + (size_t)row * (H_DIM * 2) + ch * 16);
        }
        CP_COMMIT();
    };

    prefetch(0, 0);
    prefetch(1, 1);

    for (int it = 0; it < 6; it++) {
        const int bufi = it % 3;
        if (it < 4) {
            prefetch(it + 2, (it + 2) % 3);
            CP_WAIT(2);
        } else {
            CP_WAIT(0);
        }
        __syncthreads();

        const uint32_t Ab = sb + bufi * T2_STAGE;
        const uint32_t Bb = Ab + T2_ABYTES;

#pragma unroll
        for (int k16 = 0; k16 < 4; k16++) {
            const uint32_t kb = k16 * 32;
            uint32_t afrag[2][4];
#pragma unroll
            for (int mi = 0; mi < 2; mi++) {
                const int row = wm * 32 + mi * 16 + arow_l;
                const uint32_t addr =
                    Ab + row * 128 + ((kb + akh) ^ (uint32_t)((row & 7) << 4));
                ldsm_x4(afrag[mi][0], afrag[mi][1], afrag[mi][2], afrag[mi][3], addr);
            }
            uint32_t bfrag[4][2];
#pragma unroll
            for (int bj = 0; bj < 2; bj++) {
                const int row = wn * 32 + bj * 16 + brow_l;
                const uint32_t addr =
                    Bb + row * 128 + ((kb + bkh) ^ (uint32_t)((row & 7) << 4));
                uint32_t r0, r1, r2, r3;
                ldsm_x4(r0, r1, r2, r3, addr);
                bfrag[bj * 2 + 0][0] = r0; bfrag[bj * 2 + 0][1] = r1;
                bfrag[bj * 2 + 1][0] = r2; bfrag[bj * 2 + 1][1] = r3;
            }
#pragma unroll
            for (int mi = 0; mi < 2; mi++)
#pragma unroll
                for (int nj = 0; nj < 4; nj++)
                    mma_bf16(cfrag[mi][nj], afrag[mi], bfrag[nj]);
        }
        __syncthreads();
    }

    __half* __restrict__ Couth = g_emb2h + (size_t)b * N_NODES * C_DIM;
    const bool self_combo = (b % 3 == 0);
    float* __restrict__ Coutf = g_emb2f + (size_t)(b / 3) * N_NODES * C_DIM;
    const int mrow0 = rowBase + wm * 32;
    const int ncol0 = wn * 32;
    const int lr = lane >> 2;
    const int lc = (lane & 3) * 2;
#pragma unroll
    for (int mi = 0; mi < 2; mi++) {
#pragma unroll
        for (int nj = 0; nj < 4; nj++) {
            const int r0 = mrow0 + mi * 16 + lr;
            const int cc = ncol0 + nj * 8 + lc;
            if (r0 < N_NODES) {
                *(__half2*)&Couth[(size_t)r0 * C_DIM + cc] =
                    __float22half2_rn(make_float2(cfrag[mi][nj][0], cfrag[mi][nj][1]));
                if (self_combo)
                    *(float2*)&Coutf[(size_t)r0 * C_DIM + cc] =
                        make_float2(cfrag[mi][nj][0], cfrag[mi][nj][1]);
            }
            if (r0 + 8 < N_NODES) {
                *(__half2*)&Couth[(size_t)(r0 + 8) * C_DIM + cc] =
                    __float22half2_rn(make_float2(cfrag[mi][nj][2], cfrag[mi][nj][3]));
                if (self_combo)
                    *(float2*)&Coutf[(size_t)(r0 + 8) * C_DIM + cc] =
                        make_float2(cfrag[mi][nj][2], cfrag[mi][nj][3]);
            }
        }
    }
}

// ---------------------------------------------------------------------------
// Fused SpMM layer 1: block per node, 64 threads (half2 column pair each).
// Epilogue emits h as bf16 hi/lo planes for gemm2's tensor-core path.
// ---------------------------------------------------------------------------
__global__ void __launch_bounds__(64) spmm1_kernel(const float* __restrict__ wv1,
                                                   const float* __restrict__ b1) {
    const int i = blockIdx.x;
    const int t = threadIdx.x;
    const int comboOf[3][3] = {{0, 1, 2}, {4, 3, 5}, {7, 8, 6}};

    float2 agg[3] = {{0.f, 0.f}, {0.f, 0.f}, {0.f, 0.f}};

#pragma unroll
    for (int a = 0; a < 3; a++) {
        const int start = g_rowptr[a * RP_STRIDE + i];
        const int end   = g_rowptr[a * RP_STRIDE + i + 1];
        const __half2* __restrict__ T0 =
            (const __half2*)g_emb1h + (size_t)comboOf[0][a] * N_NODES * (H_DIM / 2);
        const __half2* __restrict__ T1 =
            (const __half2*)g_emb1h + (size_t)comboOf[1][a] * N_NODES * (H_DIM / 2);
        const __half2* __restrict__ T2 =
            (const __half2*)g_emb1h + (size_t)comboOf[2][a] * N_NODES * (H_DIM / 2);
        const int2* __restrict__ ew = g_edge + (size_t)a * N_EDGES;

        float2 p0 = {0.f, 0.f}, p1 = {0.f, 0.f}, p2 = {0.f, 0.f};
        for (int e = start; e < end; e++) {
            const int2 cw = __ldg(&ew[e]);
            const float w = __int_as_float(cw.y);
            const size_t o = (size_t)cw.x * (H_DIM / 2) + t;
            float2 v0 = __half22float2(__ldg(&T0[o]));
            float2 v1 = __half22float2(__ldg(&T1[o]));
            float2 v2 = __half22float2(__ldg(&T2[o]));
            p0.x += w * v0.x; p0.y += w * v0.y;
            p1.x += w * v1.x; p1.y += w * v1.y;
            p2.x += w * v2.x; p2.y += w * v2.y;
        }
        float w0 = wv1[comboOf[0][a]], w1 = wv1[comboOf[1][a]], w2 = wv1[comboOf[2][a]];
        agg[0].x += w0 * p0.x; agg[0].y += w0 * p0.y;
        agg[1].x += w1 * p1.x; agg[1].y += w1 * p1.y;
        agg[2].x += w2 * p2.x; agg[2].y += w2 * p2.y;
    }

    const size_t NH = (size_t)N_NODES * H_DIM;
    const size_t PH = (size_t)PAD_ROWS * H_DIM;
#pragma unroll
    for (int gc = 0; gc < 3; gc++) {
        float2 self = *(const float2*)&g_emb1f[gc * NH + (size_t)i * H_DIM + 2 * t];
        float2 bias = *(const float2*)&b1[gc * H_DIM + 2 * t];
        float hx = fmaxf(self.x + 1.01f * agg[gc].x + bias.x, 0.f);
        float hy = fmaxf(self.y + 1.01f * agg[gc].y + bias.y, 0.f);
        __nv_bfloat16 hix = __float2bfloat16(hx);
        __nv_bfloat16 hiy = __float2bfloat16(hy);
        __nv_bfloat16 lox = __float2bfloat16(hx - __bfloat162float(hix));
        __nv_bfloat16 loy = __float2bfloat16(hy - __bfloat162float(hiy));
        const size_t base = (size_t)(gc * 2) * PH + (size_t)i * H_DIM + 2 * t;
        *(uint32_t*)&g_hsplit[base]      = pack_bf2(hix, hiy);
        *(uint32_t*)&g_hsplit[base + PH] = pack_bf2(lox, loy);
    }
}

// ---------------------------------------------------------------------------
// Fused SpMM layer 2 + final: block per node, 32 threads.
// ---------------------------------------------------------------------------
__global__ void __launch_bounds__(32) spmm2_kernel(const float* __restrict__ wv2,
                                                   const float* __restrict__ b2,
                                                   float* __restrict__ out) {
    const int i = blockIdx.x;
    const int t = threadIdx.x;
    const int comboOf[3][3] = {{0, 1, 2}, {4, 3, 5}, {7, 8, 6}};

    float2 agg[3] = {{0.f, 0.f}, {0.f, 0.f}, {0.f, 0.f}};

#pragma unroll
    for (int a = 0; a < 3; a++) {
        const int start = g_rowptr[a * RP_STRIDE + i];
        const int end   = g_rowptr[a * RP_STRIDE + i + 1];
        const __half2* __restrict__ T0 =
            (const __half2*)g_emb2h + (size_t)comboOf[0][a] * N_NODES * (C_DIM / 2);
        const __half2* __restrict__ T1 =
            (const __half2*)g_emb2h + (size_t)comboOf[1][a] * N_NODES * (C_DIM / 2);
        const __half2* __restrict__ T2 =
            (const __half2*)g_emb2h + (size_t)comboOf[2][a] * N_NODES * (C_DIM / 2);
        const int2* __restrict__ ew = g_edge + (size_t)a * N_EDGES;

        float2 p0 = {0.f, 0.f}, p1 = {0.f, 0.f}, p2 = {0.f, 0.f};
        for (int e = start; e < end; e++) {
            const int2 cw = __ldg(&ew[e]);
            const float w = __int_as_float(cw.y);
            const size_t o = (size_t)cw.x * (C_DIM / 2) + t;
            float2 v0 = __half22float2(__ldg(&T0[o]));
            float2 v1 = __half22float2(__ldg(&T1[o]));
            float2 v2 = __half22float2(__ldg(&T2[o]));
            p0.x += w * v0.x; p0.y += w * v0.y;
            p1.x += w * v1.x; p1.y += w * v1.y;
            p2.x += w * v2.x; p2.y += w * v2.y;
        }
        float w0 = wv2[comboOf[0][a]], w1 = wv2[comboOf[1][a]], w2 = wv2[comboOf[2][a]];
        agg[0].x += w0 * p0.x; agg[0].y += w0 * p0.y;
        agg[1].x += w1 * p1.x; agg[1].y += w1 * p1.y;
        agg[2].x += w2 * p2.x; agg[2].y += w2 * p2.y;
    }

    const size_t NC = (size_t)N_NODES * C_DIM;
    const size_t oi = (size_t)i * C_DIM + 2 * t;
    float2 ysum = {0.f, 0.f};
#pragma unroll
    for (int gc = 0; gc < 3; gc++) {
        float2 self = *(const float2*)&g_emb2f[gc * NC + oi];
        float2 bias = *(const float2*)&b2[gc * C_DIM + 2 * t];
        ysum.x += fmaxf(self.x + 1.01f * agg[gc].x + bias.x, 0.f);
        ysum.y += fmaxf(self.y + 1.01f * agg[gc].y + bias.y, 0.f);
    }
    *(float2*)&out[oi] = make_float2(fabsf(ysum.x * (1.f / 3.f)),
                                     fabsf(ysum.y * (1.f / 3.f)));
}

// ---------------------------------------------------------------------------
extern "C" void kernel_launch(void* const* d_in, const int* in_sizes, int n_in,
                              void* d_out, int out_size) {
    const float* x1 = (const float*)d_in[0];
    const float* x2 = (const float*)d_in[1];
    const float* x3 = (const float*)d_in[2];
    const int*   s0 = (const int*)d_in[3];
    const int*   d0 = (const int*)d_in[4];
    const float* v0 = (const float*)d_in[5];
    const int*   s1 = (const int*)d_in[6];
    const int*   d1 = (const int*)d_in[7];
    const float* v1 = (const float*)d_in[8];
    const int*   s2 = (const int*)d_in[9];
    const int*   d2 = (const int*)d_in[10];
    const float* v2 = (const float*)d_in[11];
    const float* W1  = (const float*)d_in[12];
    const float* wv1 = (const float*)d_in[13];
    const float* b1  = (const float*)d_in[14];
    const float* W2  = (const float*)d_in[15];
    const float* wv2 = (const float*)d_in[16];
    const float* b2  = (const float*)d_in[17];
    float* out = (float*)d_out;

    cudaFuncSetAttribute(gemm1_mma_kernel,
                         cudaFuncAttributeMaxDynamicSharedMemorySize, GSM_TOTAL);
    cudaFuncSetAttribute(gemm2_mma_kernel,
                         cudaFuncAttributeMaxDynamicSharedMemorySize, G2SM_TOTAL);

    // K0: zero cursors — separate launch, MUST complete before hist atomics
    csr_zero_kernel<<<(3 * N_NODES + 255) / 256, 256>>>();
    // K1: fused splits + histogram (no zeroing inside)
    prep_kernel<<<NB_PREP, 256>>>(x1, x2, x3, W1, W2, s0, s1, s2);
    // K2: gemm1 + piggybacked scan
    gemm1_mma_kernel<<<NB_GEMM1 + 3, 256, GSM_TOTAL>>>();
    // K3: fill
    csr_fill_kernel<<<dim3(NB_HIST_PER, 3), 256>>>(s0, s1, s2, d0, d1, d2, v0, v1, v2);
    // K4-K6
    spmm1_kernel<<<N_NODES, 64>>>(wv1, b1);
    gemm2_mma_kernel<<<dim3(157, 9), 256, G2SM_TOTAL>>>();
    spmm2_kernel<<<N_NODES, 32>>>(wv2, b2, out);
}

// round 9
// speedup vs baseline: 3.4120x; 1.1244x over previous
#include <cuda_runtime.h>
#include <cuda_bf16.h>
#include <cuda_fp16.h>
#include <cstdint>

#define N_NODES 20000
#define F_DIM   512
#define H_DIM   128
#define C_DIM   64
#define N_EDGES 640000
#define PAD_ROWS 20096       // 157 * 128
#define RP_STRIDE 20004      // N_NODES+1 padded to 4-int alignment

// ---------------------------------------------------------------------------
// Scratch (static device globals; no runtime allocation allowed)
// ---------------------------------------------------------------------------
__device__ __half g_emb1h[9 * N_NODES * H_DIM];   // fp16 tables (combo); self = combo gc*3
__device__ __half g_emb2h[9 * N_NODES * C_DIM];

// bf16 split operands
__device__ __nv_bfloat16 g_xsplit[6 * PAD_ROWS * F_DIM];   // [view*2+term][row][k]
__device__ __nv_bfloat16 g_wt[18 * H_DIM * F_DIM];         // [combo*2+term][n][k]
__device__ __nv_bfloat16 g_hsplit[6 * PAD_ROWS * H_DIM];   // [gc*2+term][row][k]
__device__ __nv_bfloat16 g_wt2[18 * C_DIM * H_DIM];        // [combo*2+term][n][k]

// CSR scratch
__device__ int  g_rowptr[3 * RP_STRIDE];
__device__ int  g_cursor[3 * N_NODES];
__device__ int2 g_edge[3 * N_EDGES];              // {col, w-as-int}

// combo -> which x / adjacency feeds it. combo = gc*3 + role.
__constant__ int c_perm[9] = {0,1,2, 1,0,2, 2,0,1};

// ---------------------------------------------------------------------------
// PTX helpers (base-target only: sm_80+ features)
// ---------------------------------------------------------------------------
__device__ __forceinline__ uint32_t smem_u32(const void* p) {
    uint32_t a;
    asm("{ .reg .u64 t; cvta.to.shared.u64 t, %1; cvt.u32.u64 %0, t; }"
        : "=r"(a) : "l"(p));
    return a;
}

__device__ __forceinline__ void cp_async16(uint32_t dst, const void* src) {
    asm volatile("cp.async.cg.shared.global [%0], [%1], 16;"
                 :: "r"(dst), "l"(src) : "memory");
}
#define CP_COMMIT() asm volatile("cp.async.commit_group;" ::: "memory")
#define CP_WAIT(n)  asm volatile("cp.async.wait_group %0;" :: "n"(n) : "memory")

__device__ __forceinline__ void ldsm_x4(uint32_t& r0, uint32_t& r1,
                                        uint32_t& r2, uint32_t& r3, uint32_t addr) {
    asm volatile("ldmatrix.sync.aligned.m8n8.x4.shared.b16 {%0,%1,%2,%3}, [%4];"
                 : "=r"(r0), "=r"(r1), "=r"(r2), "=r"(r3) : "r"(addr));
}

__device__ __forceinline__ void mma_bf16(float* d, const uint32_t* a,
                                         const uint32_t* b) {
    asm volatile(
        "mma.sync.aligned.m16n8k16.row.col.f32.bf16.bf16.f32 "
        "{%0,%1,%2,%3}, {%4,%5,%6,%7}, {%8,%9}, {%0,%1,%2,%3};"
        : "+f"(d[0]), "+f"(d[1]), "+f"(d[2]), "+f"(d[3])
        : "r"(a[0]), "r"(a[1]), "r"(a[2]), "r"(a[3]), "r"(b[0]), "r"(b[1]));
}

__device__ __forceinline__ uint32_t pack_bf2(__nv_bfloat16 a, __nv_bfloat16 b) {
    return (uint32_t)__bfloat16_as_ushort(a) | ((uint32_t)__bfloat16_as_ushort(b) << 16);
}

// ---------------------------------------------------------------------------
// K0: csr_zero — own kernel: all cursor zeroes visible before hist atomics.
// ---------------------------------------------------------------------------
__global__ void csr_zero_kernel() {
    int i = blockIdx.x * blockDim.x + threadIdx.x;
    if (i < 3 * N_NODES) g_cursor[i] = 0;
}

// ---------------------------------------------------------------------------
// K1: fused prep — split_x | split_w | split_w2 | csr_hist (NO zeroing here)
// ---------------------------------------------------------------------------
#define NB_SPLITX 30000
#define NB_SPLITW 2304
#define NB_SPLITW2 288
#define NB_HIST_PER 625
#define B_SPLITW  (NB_SPLITX)
#define B_SPLITW2 (B_SPLITW + NB_SPLITW)
#define B_HIST    (B_SPLITW2 + NB_SPLITW2)
#define NB_PREP   (B_HIST + 3 * NB_HIST_PER)

__global__ void __launch_bounds__(256)
prep_kernel(const float* __restrict__ x1, const float* __restrict__ x2,
            const float* __restrict__ x3, const float* __restrict__ W1,
            const float* __restrict__ W2,
            const int* __restrict__ s0, const int* __restrict__ s1,
            const int* __restrict__ s2) {
    const int bid = blockIdx.x;
    const int tid = threadIdx.x;

    if (bid < NB_SPLITX) {
        int i = bid * 256 + tid;  // one float4 each
        const int per_view = N_NODES * (F_DIM / 4);
        const int view = i / per_view;
        const int rem  = i - view * per_view;
        const int row  = rem / (F_DIM / 4);
        const int kg   = rem - row * (F_DIM / 4);
        const float* X = (view == 0) ? x1 : (view == 1) ? x2 : x3;
        float4 f = ((const float4*)X)[rem];

        __nv_bfloat16 h0 = __float2bfloat16(f.x), h1 = __float2bfloat16(f.y);
        __nv_bfloat16 h2 = __float2bfloat16(f.z), h3 = __float2bfloat16(f.w);
        __nv_bfloat16 l0 = __float2bfloat16(f.x - __bfloat162float(h0));
        __nv_bfloat16 l1 = __float2bfloat16(f.y - __bfloat162float(h1));
        __nv_bfloat16 l2 = __float2bfloat16(f.z - __bfloat162float(h2));
        __nv_bfloat16 l3 = __float2bfloat16(f.w - __bfloat162float(h3));

        size_t off_hi = ((size_t)(view * 2 + 0) * PAD_ROWS + row) * F_DIM + kg * 4;
        size_t off_lo = ((size_t)(view * 2 + 1) * PAD_ROWS + row) * F_DIM + kg * 4;
        *(uint2*)&g_xsplit[off_hi] = make_uint2(pack_bf2(h0, h1), pack_bf2(h2, h3));
        *(uint2*)&g_xsplit[off_lo] = make_uint2(pack_bf2(l0, l1), pack_bf2(l2, l3));
    } else if (bid < B_SPLITW2) {
        int i = (bid - B_SPLITW) * 256 + tid;   // over 9*512*128, n fastest
        const int b = i / (F_DIM * H_DIM);
        const int rem = i - b * (F_DIM * H_DIM);
        const int k = rem / H_DIM;
        const int n = rem - k * H_DIM;
        float w = W1[i];
        __nv_bfloat16 hi = __float2bfloat16(w);
        __nv_bfloat16 lo = __float2bfloat16(w - __bfloat162float(hi));
        g_wt[((size_t)(b * 2 + 0) * H_DIM + n) * F_DIM + k] = hi;
        g_wt[((size_t)(b * 2 + 1) * H_DIM + n) * F_DIM + k] = lo;
    } else if (bid < B_HIST) {
        int i = (bid - B_SPLITW2) * 256 + tid;  // over 9*128*64
        const int b = i / (H_DIM * C_DIM);
        const int rem = i - b * (H_DIM * C_DIM);
        const int k = rem / C_DIM;
        const int n = rem - k * C_DIM;
        float w = W2[i];
        __nv_bfloat16 hi = __float2bfloat16(w);
        __nv_bfloat16 lo = __float2bfloat16(w - __bfloat162float(hi));
        g_wt2[((size_t)(b * 2 + 0) * C_DIM + n) * H_DIM + k] = hi;
        g_wt2[((size_t)(b * 2 + 1) * C_DIM + n) * H_DIM + k] = lo;
    } else {
        const int rel = bid - B_HIST;
        const int a = rel / NB_HIST_PER;
        const int blk = rel - a * NB_HIST_PER;
        const int* __restrict__ s = (a == 0) ? s0 : (a == 1) ? s1 : s2;
        int* __restrict__ cur = g_cursor + a * N_NODES;
        const int base = blk * 1024 + tid;
#pragma unroll
        for (int k = 0; k < 4; k++)
            atomicAdd(&cur[__ldg(&s[base + k * 256])], 1);
    }
}

// ---------------------------------------------------------------------------
// K2: csr_scan — own kernel (3 blocks, 256 threads). Must follow hist,
// precede the fill blocks piggybacked in gemm1.
// ---------------------------------------------------------------------------
__global__ void __launch_bounds__(256) csr_scan_kernel() {
    const int a = blockIdx.x;
    __shared__ int s_warp[9];
    int* cnt = g_cursor + a * N_NODES;
    int* rp  = g_rowptr + a * RP_STRIDE;
    const int tid = threadIdx.x;
    const int lane = tid & 31;
    const int w = tid >> 5;
    int carry = 0;
    for (int base = 0; base < N_NODES; base += 1024) {
        const int idx = base + tid * 4;
        int v0 = 0, v1 = 0, v2 = 0, v3 = 0;
        if (idx + 3 < N_NODES) {
            int4 t = *(const int4*)&cnt[idx];
            v0 = t.x; v1 = t.y; v2 = t.z; v3 = t.w;
        } else {
            if (idx + 0 < N_NODES) v0 = cnt[idx + 0];
            if (idx + 1 < N_NODES) v1 = cnt[idx + 1];
            if (idx + 2 < N_NODES) v2 = cnt[idx + 2];
            if (idx + 3 < N_NODES) v3 = cnt[idx + 3];
        }
        const int tsum = v0 + v1 + v2 + v3;
        int sc = tsum;
#pragma unroll
        for (int o = 1; o < 32; o <<= 1) {
            int n = __shfl_up_sync(0xffffffff, sc, o);
            if (lane >= o) sc += n;
        }
        if (lane == 31) s_warp[w] = sc;
        __syncthreads();
        if (w == 0) {
            int x = (lane < 8) ? s_warp[lane] : 0;
#pragma unroll
            for (int o = 1; o < 8; o <<= 1) {
                int n = __shfl_up_sync(0xffffffff, x, o);
                if (lane >= o) x += n;
            }
            if (lane < 8) s_warp[lane] = x;
            if (lane == 7) s_warp[8] = x;
        }
        __syncthreads();
        const int warp_off = (w == 0) ? 0 : s_warp[w - 1];
        const int excl = carry + warp_off + (sc - tsum);
        const int p0 = excl, p1 = p0 + v0, p2 = p1 + v1, p3 = p2 + v2;
        if (idx + 3 < N_NODES) {
            *(int4*)&rp[idx]  = make_int4(p0, p1, p2, p3);
            *(int4*)&cnt[idx] = make_int4(p0, p1, p2, p3);
        } else {
            if (idx + 0 < N_NODES) { rp[idx + 0] = p0; cnt[idx + 0] = p0; }
            if (idx + 1 < N_NODES) { rp[idx + 1] = p1; cnt[idx + 1] = p1; }
            if (idx + 2 < N_NODES) { rp[idx + 2] = p2; cnt[idx + 2] = p2; }
            if (idx + 3 < N_NODES) { rp[idx + 3] = p3; cnt[idx + 3] = p3; }
        }
        carry += s_warp[8];
        __syncthreads();
    }
    if (tid == 0) rp[N_NODES] = carry;
}

// ---------------------------------------------------------------------------
// K3: GEMM1 (mma.sync bf16x3) with csr_fill piggybacked at the FRONT of the
// grid. grid: 1875 fill blocks + 1413 gemm blocks. 256 threads.
// ---------------------------------------------------------------------------
#define TILE_BYTES 16384                  // 128 rows x 128B
#define STAGE_BYTES (2 * TILE_BYTES)      // A + B
#define GSM_TOTAL (3 * STAGE_BYTES)       // 3 stages = 96KB
#define NB_GEMM1 (157 * 9)
#define NB_FILL (3 * NB_HIST_PER)

__global__ void __launch_bounds__(256)
gemm1_mma_kernel(const int* __restrict__ s0, const int* __restrict__ s1,
                 const int* __restrict__ s2, const int* __restrict__ d0,
                 const int* __restrict__ d1, const int* __restrict__ d2,
                 const float* __restrict__ v0, const float* __restrict__ v1,
                 const float* __restrict__ v2) {
    if (blockIdx.x < NB_FILL) {           // piggybacked fill blocks (run early)
        const int rel = blockIdx.x;
        const int a = rel / NB_HIST_PER;
        const int blk = rel - a * NB_HIST_PER;
        const int*   __restrict__ s = (a == 0) ? s0 : (a == 1) ? s1 : s2;
        const int*   __restrict__ d = (a == 0) ? d0 : (a == 1) ? d1 : d2;
        const float* __restrict__ v = (a == 0) ? v0 : (a == 1) ? v1 : v2;
        int* __restrict__ cur = g_cursor + a * N_NODES;
        int2* __restrict__ eo = g_edge + (size_t)a * N_EDGES;
        const int base = blk * 1024 + threadIdx.x;
#pragma unroll
        for (int k = 0; k < 4; k++) {
            const int e = base + k * 256;
            const int ss = __ldg(&s[e]);
            const int dd = __ldg(&d[e]);
            const float vv = __ldg(&v[e]);
            int pos = atomicAdd(&cur[ss], 1);
            eo[pos] = make_int2(dd, __float_as_int(vv));
        }
        return;
    }
    extern __shared__ char smem[];
    const uint32_t sb = smem_u32(smem);
    const int tid = threadIdx.x;
    const int wid = tid >> 5;
    const int lane = tid & 31;
    const int gbid = blockIdx.x - NB_FILL;
    const int tile = gbid % 157;
    const int b = gbid / 157;
    const int view = c_perm[b];
    const int rowBase = tile * 128;

    const int termA[3] = {0, 1, 0};
    const int termB[3] = {0, 0, 1};

    const int wm = wid >> 1;
    const int wn = wid & 1;

    const int arow_l = (lane & 15);
    const uint32_t akh = (uint32_t)(lane >> 4) * 16;
    const int brow_l = (lane & 7) + ((lane >> 4) << 3);
    const uint32_t bkh = (uint32_t)((lane >> 3) & 1) * 16;

    float cfrag[2][8][4];
#pragma unroll
    for (int mi = 0; mi < 2; mi++)
#pragma unroll
        for (int nj = 0; nj < 8; nj++)
#pragma unroll
            for (int q = 0; q < 4; q++) cfrag[mi][nj][q] = 0.f;

    auto prefetch = [&](int it, int bufi) {
        const int t = it >> 3;
        const int c = it & 7;
        const char* Asrc = (const char*)(g_xsplit +
            ((size_t)(view * 2 + termA[t]) * PAD_ROWS + rowBase) * F_DIM) + c * 128;
        const char* Bsrc = (const char*)(g_wt +
            (size_t)(b * 2 + termB[t]) * H_DIM * F_DIM) + c * 128;
        const uint32_t Ab = sb + bufi * STAGE_BYTES;
        const uint32_t Bb = Ab + TILE_BYTES;
#pragma unroll
        for (int i = 0; i < 4; i++) {
            int idx = tid + i * 256;
            int row = idx >> 3;
            int ch  = idx & 7;
            uint32_t off = row * 128 + ch * 16;
            uint32_t sw = off ^ ((off >> 3) & 0x70);
            cp_async16(Ab + sw, Asrc + (size_t)row * (F_DIM * 2) + ch * 16);
            cp_async16(Bb + sw, Bsrc + (size_t)row * (F_DIM * 2) + ch * 16);
        }
        CP_COMMIT();
    };

    prefetch(0, 0);
    prefetch(1, 1);

    for (int it = 0; it < 24; it++) {
        const int bufi = it % 3;
        if (it < 22) {
            prefetch(it + 2, (it + 2) % 3);
            CP_WAIT(2);
        } else {
            CP_WAIT(0);
        }
        __syncthreads();

        const uint32_t Ab = sb + bufi * STAGE_BYTES;
        const uint32_t Bb = Ab + TILE_BYTES;

#pragma unroll
        for (int k16 = 0; k16 < 4; k16++) {
            const uint32_t kb = k16 * 32;
            uint32_t afrag[2][4];
#pragma unroll
            for (int mi = 0; mi < 2; mi++) {
                const int row = wm * 32 + mi * 16 + arow_l;
                const uint32_t addr =
                    Ab + row * 128 + ((kb + akh) ^ (uint32_t)((row & 7) << 4));
                ldsm_x4(afrag[mi][0], afrag[mi][1], afrag[mi][2], afrag[mi][3], addr);
            }
            uint32_t bfrag[8][2];
#pragma unroll
            for (int bj = 0; bj < 4; bj++) {
                const int row = wn * 64 + bj * 16 + brow_l;
                const uint32_t addr =
                    Bb + row * 128 + ((kb + bkh) ^ (uint32_t)((row & 7) << 4));
                uint32_t r0, r1, r2, r3;
                ldsm_x4(r0, r1, r2, r3, addr);
                bfrag[bj * 2 + 0][0] = r0; bfrag[bj * 2 + 0][1] = r1;
                bfrag[bj * 2 + 1][0] = r2; bfrag[bj * 2 + 1][1] = r3;
            }
#pragma unroll
            for (int mi = 0; mi < 2; mi++)
#pragma unroll
                for (int nj = 0; nj < 8; nj++)
                    mma_bf16(cfrag[mi][nj], afrag[mi], bfrag[nj]);
        }
        __syncthreads();
    }

    // Epilogue: half table only (self-term read from combo gc*3 in spmm1)
    __half* __restrict__ Couth = g_emb1h + (size_t)b * N_NODES * H_DIM;
    const int mrow0 = rowBase + wm * 32;
    const int ncol0 = wn * 64;
    const int lr = lane >> 2;
    const int lc = (lane & 3) * 2;
#pragma unroll
    for (int mi = 0; mi < 2; mi++) {
#pragma unroll
        for (int nj = 0; nj < 8; nj++) {
            const int r0 = mrow0 + mi * 16 + lr;
            const int cc = ncol0 + nj * 8 + lc;
            if (r0 < N_NODES)
                *(__half2*)&Couth[(size_t)r0 * H_DIM + cc] =
                    __float22half2_rn(make_float2(cfrag[mi][nj][0], cfrag[mi][nj][1]));
            if (r0 + 8 < N_NODES)
                *(__half2*)&Couth[(size_t)(r0 + 8) * H_DIM + cc] =
                    __float22half2_rn(make_float2(cfrag[mi][nj][2], cfrag[mi][nj][3]));
        }
    }
}

// ---------------------------------------------------------------------------
// GEMM2 (mma.sync bf16x3): emb2[b] = h[perm[b]] @ W2[b], fp32 accumulate.
// ---------------------------------------------------------------------------
#define T2_ABYTES 16384                   // 128 rows x 128B
#define T2_BBYTES 8192                    // 64 rows x 128B
#define T2_STAGE  (T2_ABYTES + T2_BBYTES)
#define G2SM_TOTAL (3 * T2_STAGE)         // 72KB

__global__ void __launch_bounds__(256)
gemm2_mma_kernel() {
    extern __shared__ char smem[];
    const uint32_t sb = smem_u32(smem);
    const int tid = threadIdx.x;
    const int wid = tid >> 5;
    const int lane = tid & 31;
    const int tile = blockIdx.x;
    const int b = blockIdx.y;
    const int view = c_perm[b];
    const int rowBase = tile * 128;

    const int termA[3] = {0, 1, 0};
    const int termB[3] = {0, 0, 1};

    const int wm = wid >> 1;
    const int wn = wid & 1;

    const int arow_l = (lane & 15);
    const uint32_t akh = (uint32_t)(lane >> 4) * 16;
    const int brow_l = (lane & 7) + ((lane >> 4) << 3);
    const uint32_t bkh = (uint32_t)((lane >> 3) & 1) * 16;

    float cfrag[2][4][4];
#pragma unroll
    for (int mi = 0; mi < 2; mi++)
#pragma unroll
        for (int nj = 0; nj < 4; nj++)
#pragma unroll
            for (int q = 0; q < 4; q++) cfrag[mi][nj][q] = 0.f;

    auto prefetch = [&](int it, int bufi) {
        const int t = it >> 1;
        const int c = it & 1;
        const char* Asrc = (const char*)(g_hsplit +
            ((size_t)(view * 2 + termA[t]) * PAD_ROWS + rowBase) * H_DIM) + c * 128;
        const char* Bsrc = (const char*)(g_wt2 +
            (size_t)(b * 2 + termB[t]) * C_DIM * H_DIM) + c * 128;
        const uint32_t Ab = sb + bufi * T2_STAGE;
        const uint32_t Bb = Ab + T2_ABYTES;
#pragma unroll
        for (int i = 0; i < 4; i++) {
            int idx = tid + i * 256;
            int row = idx >> 3;
            int ch  = idx & 7;
            uint32_t off = row * 128 + ch * 16;
            uint32_t sw = off ^ ((off >> 3) & 0x70);
            cp_async16(Ab + sw, Asrc + (size_t)row * (H_DIM * 2) + ch * 16);
        }
#pragma unroll
        for (int i = 0; i < 2; i++) {
            int idx = tid + i * 256;
            int row = idx >> 3;
            int ch  = idx & 7;
            uint32_t off = row * 128 + ch * 16;
            uint32_t sw = off ^ ((off >> 3) & 0x70);
            cp_async16(Bb + sw, Bsrc + (size_t)row * (H_DIM * 2) + ch * 16);
        }
        CP_COMMIT();
    };

    prefetch(0, 0);
    prefetch(1, 1);

    for (int it = 0; it < 6; it++) {
        const int bufi = it % 3;
        if (it < 4) {
            prefetch(it + 2, (it + 2) % 3);
            CP_WAIT(2);
        } else {
            CP_WAIT(0);
        }
        __syncthreads();

        const uint32_t Ab = sb + bufi * T2_STAGE;
        const uint32_t Bb = Ab + T2_ABYTES;

#pragma unroll
        for (int k16 = 0; k16 < 4; k16++) {
            const uint32_t kb = k16 * 32;
            uint32_t afrag[2][4];
#pragma unroll
            for (int mi = 0; mi < 2; mi++) {
                const int row = wm * 32 + mi * 16 + arow_l;
                const uint32_t addr =
                    Ab + row * 128 + ((kb + akh) ^ (uint32_t)((row & 7) << 4));
                ldsm_x4(afrag[mi][0], afrag[mi][1], afrag[mi][2], afrag[mi][3], addr);
            }
            uint32_t bfrag[4][2];
#pragma unroll
            for (int bj = 0; bj < 2; bj++) {
                const int row = wn * 32 + bj * 16 + brow_l;
                const uint32_t addr =
                    Bb + row * 128 + ((kb + bkh) ^ (uint32_t)((row & 7) << 4));
                uint32_t r0, r1, r2, r3;
                ldsm_x4(r0, r1, r2, r3, addr);
                bfrag[bj * 2 + 0][0] = r0; bfrag[bj * 2 + 0][1] = r1;
                bfrag[bj * 2 + 1][0] = r2; bfrag[bj * 2 + 1][1] = r3;
            }
#pragma unroll
            for (int mi = 0; mi < 2; mi++)
#pragma unroll
                for (int nj = 0; nj < 4; nj++)
                    mma_bf16(cfrag[mi][nj], afrag[mi], bfrag[nj]);
        }
        __syncthreads();
    }

    __half* __restrict__ Couth = g_emb2h + (size_t)b * N_NODES * C_DIM;
    const int mrow0 = rowBase + wm * 32;
    const int ncol0 = wn * 32;
    const int lr = lane >> 2;
    const int lc = (lane & 3) * 2;
#pragma unroll
    for (int mi = 0; mi < 2; mi++) {
#pragma unroll
        for (int nj = 0; nj < 4; nj++) {
            const int r0 = mrow0 + mi * 16 + lr;
            const int cc = ncol0 + nj * 8 + lc;
            if (r0 < N_NODES)
                *(__half2*)&Couth[(size_t)r0 * C_DIM + cc] =
                    __float22half2_rn(make_float2(cfrag[mi][nj][0], cfrag[mi][nj][1]));
            if (r0 + 8 < N_NODES)
                *(__half2*)&Couth[(size_t)(r0 + 8) * C_DIM + cc] =
                    __float22half2_rn(make_float2(cfrag[mi][nj][2], cfrag[mi][nj][3]));
        }
    }
}

// ---------------------------------------------------------------------------
// Fused SpMM layer 1: block per node, 64 threads (half2 column pair each).
// Self-term read from the fp16 combo table (gc*3): adds ~4e-6 at output.
// ---------------------------------------------------------------------------
__global__ void __launch_bounds__(64) spmm1_kernel(const float* __restrict__ wv1,
                                                   const float* __restrict__ b1) {
    const int i = blockIdx.x;
    const int t = threadIdx.x;
    const int comboOf[3][3] = {{0, 1, 2}, {4, 3, 5}, {7, 8, 6}};

    float2 agg[3] = {{0.f, 0.f}, {0.f, 0.f}, {0.f, 0.f}};

#pragma unroll
    for (int a = 0; a < 3; a++) {
        const int start = g_rowptr[a * RP_STRIDE + i];
        const int end   = g_rowptr[a * RP_STRIDE + i + 1];
        const __half2* __restrict__ T0 =
            (const __half2*)g_emb1h + (size_t)comboOf[0][a] * N_NODES * (H_DIM / 2);
        const __half2* __restrict__ T1 =
            (const __half2*)g_emb1h + (size_t)comboOf[1][a] * N_NODES * (H_DIM / 2);
        const __half2* __restrict__ T2 =
            (const __half2*)g_emb1h + (size_t)comboOf[2][a] * N_NODES * (H_DIM / 2);
        const int2* __restrict__ ew = g_edge + (size_t)a * N_EDGES;

        float2 p0 = {0.f, 0.f}, p1 = {0.f, 0.f}, p2 = {0.f, 0.f};
        for (int e = start; e < end; e++) {
            const int2 cw = __ldg(&ew[e]);
            const float w = __int_as_float(cw.y);
            const size_t o = (size_t)cw.x * (H_DIM / 2) + t;
            float2 v0 = __half22float2(__ldg(&T0[o]));
            float2 v1 = __half22float2(__ldg(&T1[o]));
            float2 v2 = __half22float2(__ldg(&T2[o]));
            p0.x += w * v0.x; p0.y += w * v0.y;
            p1.x += w * v1.x; p1.y += w * v1.y;
            p2.x += w * v2.x; p2.y += w * v2.y;
        }
        float w0 = wv1[comboOf[0][a]], w1 = wv1[comboOf[1][a]], w2 = wv1[comboOf[2][a]];
        agg[0].x += w0 * p0.x; agg[0].y += w0 * p0.y;
        agg[1].x += w1 * p1.x; agg[1].y += w1 * p1.y;
        agg[2].x += w2 * p2.x; agg[2].y += w2 * p2.y;
    }

    const size_t NH2 = (size_t)N_NODES * (H_DIM / 2);
    const size_t PH = (size_t)PAD_ROWS * H_DIM;
    const size_t so = (size_t)i * (H_DIM / 2) + t;
#pragma unroll
    for (int gc = 0; gc < 3; gc++) {
        float2 self = __half22float2(
            __ldg((const __half2*)g_emb1h + (size_t)(gc * 3) * NH2 + so));
        float2 bias = *(const float2*)&b1[gc * H_DIM + 2 * t];
        float hx = fmaxf(self.x + 1.01f * agg[gc].x + bias.x, 0.f);
        float hy = fmaxf(self.y + 1.01f * agg[gc].y + bias.y, 0.f);
        __nv_bfloat16 hix = __float2bfloat16(hx);
        __nv_bfloat16 hiy = __float2bfloat16(hy);
        __nv_bfloat16 lox = __float2bfloat16(hx - __bfloat162float(hix));
        __nv_bfloat16 loy = __float2bfloat16(hy - __bfloat162float(hiy));
        const size_t base = (size_t)(gc * 2) * PH + (size_t)i * H_DIM + 2 * t;
        *(uint32_t*)&g_hsplit[base]      = pack_bf2(hix, hiy);
        *(uint32_t*)&g_hsplit[base + PH] = pack_bf2(lox, loy);
    }
}

// ---------------------------------------------------------------------------
// Fused SpMM layer 2 + final: block per node, 32 threads.
// ---------------------------------------------------------------------------
__global__ void __launch_bounds__(32) spmm2_kernel(const float* __restrict__ wv2,
                                                   const float* __restrict__ b2,
                                                   float* __restrict__ out) {
    const int i = blockIdx.x;
    const int t = threadIdx.x;
    const int comboOf[3][3] = {{0, 1, 2}, {4, 3, 5}, {7, 8, 6}};

    float2 agg[3] = {{0.f, 0.f}, {0.f, 0.f}, {0.f, 0.f}};

#pragma unroll
    for (int a = 0; a < 3; a++) {
        const int start = g_rowptr[a * RP_STRIDE + i];
        const int end   = g_rowptr[a * RP_STRIDE + i + 1];
        const __half2* __restrict__ T0 =
            (const __half2*)g_emb2h + (size_t)comboOf[0][a] * N_NODES * (C_DIM / 2);
        const __half2* __restrict__ T1 =
            (const __half2*)g_emb2h + (size_t)comboOf[1][a] * N_NODES * (C_DIM / 2);
        const __half2* __restrict__ T2 =
            (const __half2*)g_emb2h + (size_t)comboOf[2][a] * N_NODES * (C_DIM / 2);
        const int2* __restrict__ ew = g_edge + (size_t)a * N_EDGES;

        float2 p0 = {0.f, 0.f}, p1 = {0.f, 0.f}, p2 = {0.f, 0.f};
        for (int e = start; e < end; e++) {
            const int2 cw = __ldg(&ew[e]);
            const float w = __int_as_float(cw.y);
            const size_t o = (size_t)cw.x * (C_DIM / 2) + t;
            float2 v0 = __half22float2(__ldg(&T0[o]));
            float2 v1 = __half22float2(__ldg(&T1[o]));
            float2 v2 = __half22float2(__ldg(&T2[o]));
            p0.x += w * v0.x; p0.y += w * v0.y;
            p1.x += w * v1.x; p1.y += w * v1.y;
            p2.x += w * v2.x; p2.y += w * v2.y;
        }
        float w0 = wv2[comboOf[0][a]], w1 = wv2[comboOf[1][a]], w2 = wv2[comboOf[2][a]];
        agg[0].x += w0 * p0.x; agg[0].y += w0 * p0.y;
        agg[1].x += w1 * p1.x; agg[1].y += w1 * p1.y;
        agg[2].x += w2 * p2.x; agg[2].y += w2 * p2.y;
    }

    const size_t NC2 = (size_t)N_NODES * (C_DIM / 2);
    const size_t so = (size_t)i * (C_DIM / 2) + t;
    float2 ysum = {0.f, 0.f};
#pragma unroll
    for (int gc = 0; gc < 3; gc++) {
        float2 self = __half22float2(
            __ldg((const __half2*)g_emb2h + (size_t)(gc * 3) * NC2 + so));
        float2 bias = *(const float2*)&b2[gc * C_DIM + 2 * t];
        ysum.x += fmaxf(self.x + 1.01f * agg[gc].x + bias.x, 0.f);
        ysum.y += fmaxf(self.y + 1.01f * agg[gc].y + bias.y, 0.f);
    }
    const size_t oi = (size_t)i * C_DIM + 2 * t;
    *(float2*)&out[oi] = make_float2(fabsf(ysum.x * (1.f / 3.f)),
                                     fabsf(ysum.y * (1.f / 3.f)));
}

// ---------------------------------------------------------------------------
extern "C" void kernel_launch(void* const* d_in, const int* in_sizes, int n_in,
                              void* d_out, int out_size) {
    const float* x1 = (const float*)d_in[0];
    const float* x2 = (const float*)d_in[1];
    const float* x3 = (const float*)d_in[2];
    const int*   s0 = (const int*)d_in[3];
    const int*   d0 = (const int*)d_in[4];
    const float* v0 = (const float*)d_in[5];
    const int*   s1 = (const int*)d_in[6];
    const int*   d1 = (const int*)d_in[7];
    const float* v1 = (const float*)d_in[8];
    const int*   s2 = (const int*)d_in[9];
    const int*   d2 = (const int*)d_in[10];
    const float* v2 = (const float*)d_in[11];
    const float* W1  = (const float*)d_in[12];
    const float* wv1 = (const float*)d_in[13];
    const float* b1  = (const float*)d_in[14];
    const float* W2  = (const float*)d_in[15];
    const float* wv2 = (const float*)d_in[16];
    const float* b2  = (const float*)d_in[17];
    float* out = (float*)d_out;

    cudaFuncSetAttribute(gemm1_mma_kernel,
                         cudaFuncAttributeMaxDynamicSharedMemorySize, GSM_TOTAL);
    cudaFuncSetAttribute(gemm2_mma_kernel,
                         cudaFuncAttributeMaxDynamicSharedMemorySize, G2SM_TOTAL);

    // K0: zero cursors — separate launch, MUST complete before hist atomics
    csr_zero_kernel<<<(3 * N_NODES + 255) / 256, 256>>>();
    // K1: fused splits + histogram
    prep_kernel<<<NB_PREP, 256>>>(x1, x2, x3, W1, W2, s0, s1, s2);
    // K2: scan — own kernel (must precede the fill blocks in gemm1)
    csr_scan_kernel<<<3, 256>>>();
    // K3: gemm1 with fill blocks piggybacked at grid front
    gemm1_mma_kernel<<<NB_FILL + NB_GEMM1, 256, GSM_TOTAL>>>(
        s0, s1, s2, d0, d1, d2, v0, v1, v2);
    // K4-K6
    spmm1_kernel<<<N_NODES, 64>>>(wv1, b1);
    gemm2_mma_kernel<<<dim3(157, 9), 256, G2SM_TOTAL>>>();
    spmm2_kernel<<<N_NODES, 32>>>(wv2, b2, out);
}

// round 10
// speedup vs baseline: 4.2770x; 1.2535x over previous
#include <cuda_runtime.h>
#include <cuda_bf16.h>
#include <cuda_fp16.h>
#include <cstdint>

#define N_NODES 20000
#define F_DIM   512
#define H_DIM   128
#define C_DIM   64
#define N_EDGES 640000
#define PAD_ROWS 20096       // 157 * 128
#define RP_STRIDE 20004      // N_NODES+1 padded to 4-int alignment

// ---------------------------------------------------------------------------
// Scratch (static device globals; no runtime allocation allowed)
// ---------------------------------------------------------------------------
__device__ __half g_emb1h[9 * N_NODES * H_DIM];   // fp16 tables (combo); self = combo gc*3
__device__ __half g_emb2h[9 * N_NODES * C_DIM];

// fp16 GEMM operands (single-pass fp16 mma)
__device__ __half g_xh[3 * PAD_ROWS * F_DIM];     // [view][row][k]
__device__ __half g_wt[9 * H_DIM * F_DIM];        // [combo][n][k]
__device__ __half g_hh[3 * PAD_ROWS * H_DIM];     // [gc][row][k]
__device__ __half g_wt2[9 * C_DIM * H_DIM];       // [combo][n][k]

// CSR scratch
__device__ int  g_rowptr[3 * RP_STRIDE];
__device__ int  g_cursor[3 * N_NODES];
__device__ int2 g_edge[3 * N_EDGES];              // {col, w-as-int}

// combo -> which x / adjacency feeds it. combo = gc*3 + role.
__constant__ int c_perm[9] = {0,1,2, 1,0,2, 2,0,1};

// ---------------------------------------------------------------------------
// PTX helpers (base-target only: sm_80+ features)
// ---------------------------------------------------------------------------
__device__ __forceinline__ uint32_t smem_u32(const void* p) {
    uint32_t a;
    asm("{ .reg .u64 t; cvta.to.shared.u64 t, %1; cvt.u32.u64 %0, t; }"
        : "=r"(a) : "l"(p));
    return a;
}

__device__ __forceinline__ void cp_async16(uint32_t dst, const void* src) {
    asm volatile("cp.async.cg.shared.global [%0], [%1], 16;"
                 :: "r"(dst), "l"(src) : "memory");
}
#define CP_COMMIT() asm volatile("cp.async.commit_group;" ::: "memory")
#define CP_WAIT(n)  asm volatile("cp.async.wait_group %0;" :: "n"(n) : "memory")

__device__ __forceinline__ void ldsm_x4(uint32_t& r0, uint32_t& r1,
                                        uint32_t& r2, uint32_t& r3, uint32_t addr) {
    asm volatile("ldmatrix.sync.aligned.m8n8.x4.shared.b16 {%0,%1,%2,%3}, [%4];"
                 : "=r"(r0), "=r"(r1), "=r"(r2), "=r"(r3) : "r"(addr));
}

__device__ __forceinline__ void mma_f16(float* d, const uint32_t* a,
                                        const uint32_t* b) {
    asm volatile(
        "mma.sync.aligned.m16n8k16.row.col.f32.f16.f16.f32 "
        "{%0,%1,%2,%3}, {%4,%5,%6,%7}, {%8,%9}, {%0,%1,%2,%3};"
        : "+f"(d[0]), "+f"(d[1]), "+f"(d[2]), "+f"(d[3])
        : "r"(a[0]), "r"(a[1]), "r"(a[2]), "r"(a[3]), "r"(b[0]), "r"(b[1]));
}

__device__ __forceinline__ uint32_t h2u(__half2 h) {
    return *(uint32_t*)&h;
}

// ---------------------------------------------------------------------------
// K0: csr_zero — own kernel: all cursor zeroes visible before hist atomics.
// ---------------------------------------------------------------------------
__global__ void csr_zero_kernel() {
    int i = blockIdx.x * blockDim.x + threadIdx.x;
    if (i < 3 * N_NODES) g_cursor[i] = 0;
}

// ---------------------------------------------------------------------------
// K1: fused prep — cvt_x | cvt_w | cvt_w2 | csr_hist (NO zeroing here)
// ---------------------------------------------------------------------------
#define NB_SPLITX 30000
#define NB_SPLITW 2304
#define NB_SPLITW2 288
#define NB_HIST_PER 625
#define B_SPLITW  (NB_SPLITX)
#define B_SPLITW2 (B_SPLITW + NB_SPLITW)
#define B_HIST    (B_SPLITW2 + NB_SPLITW2)
#define NB_PREP   (B_HIST + 3 * NB_HIST_PER)

__global__ void __launch_bounds__(256)
prep_kernel(const float* __restrict__ x1, const float* __restrict__ x2,
            const float* __restrict__ x3, const float* __restrict__ W1,
            const float* __restrict__ W2,
            const int* __restrict__ s0, const int* __restrict__ s1,
            const int* __restrict__ s2) {
    const int bid = blockIdx.x;
    const int tid = threadIdx.x;

    if (bid < NB_SPLITX) {
        int i = bid * 256 + tid;  // one float4 each
        const int per_view = N_NODES * (F_DIM / 4);
        const int view = i / per_view;
        const int rem  = i - view * per_view;
        const int row  = rem / (F_DIM / 4);
        const int kg   = rem - row * (F_DIM / 4);
        const float* X = (view == 0) ? x1 : (view == 1) ? x2 : x3;
        float4 f = ((const float4*)X)[rem];
        __half2 a = __float22half2_rn(make_float2(f.x, f.y));
        __half2 b = __float22half2_rn(make_float2(f.z, f.w));
        size_t off = ((size_t)view * PAD_ROWS + row) * F_DIM + kg * 4;
        *(uint2*)&g_xh[off] = make_uint2(h2u(a), h2u(b));
    } else if (bid < B_SPLITW2) {
        int i = (bid - B_SPLITW) * 256 + tid;   // over 9*512*128, n fastest
        const int b = i / (F_DIM * H_DIM);
        const int rem = i - b * (F_DIM * H_DIM);
        const int k = rem / H_DIM;
        const int n = rem - k * H_DIM;
        g_wt[((size_t)b * H_DIM + n) * F_DIM + k] = __float2half_rn(W1[i]);
    } else if (bid < B_HIST) {
        int i = (bid - B_SPLITW2) * 256 + tid;  // over 9*128*64
        const int b = i / (H_DIM * C_DIM);
        const int rem = i - b * (H_DIM * C_DIM);
        const int k = rem / C_DIM;
        const int n = rem - k * C_DIM;
        g_wt2[((size_t)b * C_DIM + n) * H_DIM + k] = __float2half_rn(W2[i]);
    } else {
        const int rel = bid - B_HIST;
        const int a = rel / NB_HIST_PER;
        const int blk = rel - a * NB_HIST_PER;
        const int* __restrict__ s = (a == 0) ? s0 : (a == 1) ? s1 : s2;
        int* __restrict__ cur = g_cursor + a * N_NODES;
        const int base = blk * 1024 + tid;
#pragma unroll
        for (int k = 0; k < 4; k++)
            atomicAdd(&cur[__ldg(&s[base + k * 256])], 1);
    }
}

// ---------------------------------------------------------------------------
// K2: csr_scan — own kernel (3 blocks, 256 threads).
// ---------------------------------------------------------------------------
__global__ void __launch_bounds__(256) csr_scan_kernel() {
    const int a = blockIdx.x;
    __shared__ int s_warp[9];
    int* cnt = g_cursor + a * N_NODES;
    int* rp  = g_rowptr + a * RP_STRIDE;
    const int tid = threadIdx.x;
    const int lane = tid & 31;
    const int w = tid >> 5;
    int carry = 0;
    for (int base = 0; base < N_NODES; base += 1024) {
        const int idx = base + tid * 4;
        int v0 = 0, v1 = 0, v2 = 0, v3 = 0;
        if (idx + 3 < N_NODES) {
            int4 t = *(const int4*)&cnt[idx];
            v0 = t.x; v1 = t.y; v2 = t.z; v3 = t.w;
        } else {
            if (idx + 0 < N_NODES) v0 = cnt[idx + 0];
            if (idx + 1 < N_NODES) v1 = cnt[idx + 1];
            if (idx + 2 < N_NODES) v2 = cnt[idx + 2];
            if (idx + 3 < N_NODES) v3 = cnt[idx + 3];
        }
        const int tsum = v0 + v1 + v2 + v3;
        int sc = tsum;
#pragma unroll
        for (int o = 1; o < 32; o <<= 1) {
            int n = __shfl_up_sync(0xffffffff, sc, o);
            if (lane >= o) sc += n;
        }
        if (lane == 31) s_warp[w] = sc;
        __syncthreads();
        if (w == 0) {
            int x = (lane < 8) ? s_warp[lane] : 0;
#pragma unroll
            for (int o = 1; o < 8; o <<= 1) {
                int n = __shfl_up_sync(0xffffffff, x, o);
                if (lane >= o) x += n;
            }
            if (lane < 8) s_warp[lane] = x;
            if (lane == 7) s_warp[8] = x;
        }
        __syncthreads();
        const int warp_off = (w == 0) ? 0 : s_warp[w - 1];
        const int excl = carry + warp_off + (sc - tsum);
        const int p0 = excl, p1 = p0 + v0, p2 = p1 + v1, p3 = p2 + v2;
        if (idx + 3 < N_NODES) {
            *(int4*)&rp[idx]  = make_int4(p0, p1, p2, p3);
            *(int4*)&cnt[idx] = make_int4(p0, p1, p2, p3);
        } else {
            if (idx + 0 < N_NODES) { rp[idx + 0] = p0; cnt[idx + 0] = p0; }
            if (idx + 1 < N_NODES) { rp[idx + 1] = p1; cnt[idx + 1] = p1; }
            if (idx + 2 < N_NODES) { rp[idx + 2] = p2; cnt[idx + 2] = p2; }
            if (idx + 3 < N_NODES) { rp[idx + 3] = p3; cnt[idx + 3] = p3; }
        }
        carry += s_warp[8];
        __syncthreads();
    }
    if (tid == 0) rp[N_NODES] = carry;
}

// ---------------------------------------------------------------------------
// K3: GEMM1 (mma.sync fp16, single pass) with csr_fill piggybacked at grid
// front. grid: 1875 fill blocks + 1413 gemm blocks. 256 threads.
// 8 K-iterations (chunks of 64 halfs), 3-stage cp.async, SW128 swizzle.
// ---------------------------------------------------------------------------
#define TILE_BYTES 16384                  // 128 rows x 128B
#define STAGE_BYTES (2 * TILE_BYTES)      // A + B
#define GSM_TOTAL (3 * STAGE_BYTES)       // 3 stages = 96KB
#define NB_GEMM1 (157 * 9)
#define NB_FILL (3 * NB_HIST_PER)

__global__ void __launch_bounds__(256)
gemm1_mma_kernel(const int* __restrict__ s0, const int* __restrict__ s1,
                 const int* __restrict__ s2, const int* __restrict__ d0,
                 const int* __restrict__ d1, const int* __restrict__ d2,
                 const float* __restrict__ v0, const float* __restrict__ v1,
                 const float* __restrict__ v2) {
    if (blockIdx.x < NB_FILL) {           // piggybacked fill blocks (run early)
        const int rel = blockIdx.x;
        const int a = rel / NB_HIST_PER;
        const int blk = rel - a * NB_HIST_PER;
        const int*   __restrict__ s = (a == 0) ? s0 : (a == 1) ? s1 : s2;
        const int*   __restrict__ d = (a == 0) ? d0 : (a == 1) ? d1 : d2;
        const float* __restrict__ v = (a == 0) ? v0 : (a == 1) ? v1 : v2;
        int* __restrict__ cur = g_cursor + a * N_NODES;
        int2* __restrict__ eo = g_edge + (size_t)a * N_EDGES;
        const int base = blk * 1024 + threadIdx.x;
#pragma unroll
        for (int k = 0; k < 4; k++) {
            const int e = base + k * 256;
            const int ss = __ldg(&s[e]);
            const int dd = __ldg(&d[e]);
            const float vv = __ldg(&v[e]);
            int pos = atomicAdd(&cur[ss], 1);
            eo[pos] = make_int2(dd, __float_as_int(vv));
        }
        return;
    }
    extern __shared__ char smem[];
    const uint32_t sb = smem_u32(smem);
    const int tid = threadIdx.x;
    const int wid = tid >> 5;
    const int lane = tid & 31;
    const int gbid = blockIdx.x - NB_FILL;
    const int tile = gbid % 157;
    const int b = gbid / 157;
    const int view = c_perm[b];
    const int rowBase = tile * 128;

    const int wm = wid >> 1;
    const int wn = wid & 1;

    const int arow_l = (lane & 15);
    const uint32_t akh = (uint32_t)(lane >> 4) * 16;
    const int brow_l = (lane & 7) + ((lane >> 4) << 3);
    const uint32_t bkh = (uint32_t)((lane >> 3) & 1) * 16;

    float cfrag[2][8][4];
#pragma unroll
    for (int mi = 0; mi < 2; mi++)
#pragma unroll
        for (int nj = 0; nj < 8; nj++)
#pragma unroll
            for (int q = 0; q < 4; q++) cfrag[mi][nj][q] = 0.f;

    const char* Abase = (const char*)(g_xh +
        ((size_t)view * PAD_ROWS + rowBase) * F_DIM);
    const char* Bbase = (const char*)(g_wt + (size_t)b * H_DIM * F_DIM);

    auto prefetch = [&](int c, int bufi) {
        const char* Asrc = Abase + c * 128;
        const char* Bsrc = Bbase + c * 128;
        const uint32_t Ab = sb + bufi * STAGE_BYTES;
        const uint32_t Bb = Ab + TILE_BYTES;
#pragma unroll
        for (int i = 0; i < 4; i++) {
            int idx = tid + i * 256;
            int row = idx >> 3;
            int ch  = idx & 7;
            uint32_t off = row * 128 + ch * 16;
            uint32_t sw = off ^ ((off >> 3) & 0x70);
            cp_async16(Ab + sw, Asrc + (size_t)row * (F_DIM * 2) + ch * 16);
            cp_async16(Bb + sw, Bsrc + (size_t)row * (F_DIM * 2) + ch * 16);
        }
        CP_COMMIT();
    };

    prefetch(0, 0);
    prefetch(1, 1);

    for (int it = 0; it < 8; it++) {
        const int bufi = it % 3;
        if (it < 6) {
            prefetch(it + 2, (it + 2) % 3);
            CP_WAIT(2);
        } else {
            CP_WAIT(0);
        }
        __syncthreads();

        const uint32_t Ab = sb + bufi * STAGE_BYTES;
        const uint32_t Bb = Ab + TILE_BYTES;

#pragma unroll
        for (int k16 = 0; k16 < 4; k16++) {
            const uint32_t kb = k16 * 32;
            uint32_t afrag[2][4];
#pragma unroll
            for (int mi = 0; mi < 2; mi++) {
                const int row = wm * 32 + mi * 16 + arow_l;
                const uint32_t addr =
                    Ab + row * 128 + ((kb + akh) ^ (uint32_t)((row & 7) << 4));
                ldsm_x4(afrag[mi][0], afrag[mi][1], afrag[mi][2], afrag[mi][3], addr);
            }
            uint32_t bfrag[8][2];
#pragma unroll
            for (int bj = 0; bj < 4; bj++) {
                const int row = wn * 64 + bj * 16 + brow_l;
                const uint32_t addr =
                    Bb + row * 128 + ((kb + bkh) ^ (uint32_t)((row & 7) << 4));
                uint32_t r0, r1, r2, r3;
                ldsm_x4(r0, r1, r2, r3, addr);
                bfrag[bj * 2 + 0][0] = r0; bfrag[bj * 2 + 0][1] = r1;
                bfrag[bj * 2 + 1][0] = r2; bfrag[bj * 2 + 1][1] = r3;
            }
#pragma unroll
            for (int mi = 0; mi < 2; mi++)
#pragma unroll
                for (int nj = 0; nj < 8; nj++)
                    mma_f16(cfrag[mi][nj], afrag[mi], bfrag[nj]);
        }
        __syncthreads();
    }

    // Epilogue: half table (self-term read from combo gc*3 in spmm1)
    __half* __restrict__ Couth = g_emb1h + (size_t)b * N_NODES * H_DIM;
    const int mrow0 = rowBase + wm * 32;
    const int ncol0 = wn * 64;
    const int lr = lane >> 2;
    const int lc = (lane & 3) * 2;
#pragma unroll
    for (int mi = 0; mi < 2; mi++) {
#pragma unroll
        for (int nj = 0; nj < 8; nj++) {
            const int r0 = mrow0 + mi * 16 + lr;
            const int cc = ncol0 + nj * 8 + lc;
            if (r0 < N_NODES)
                *(__half2*)&Couth[(size_t)r0 * H_DIM + cc] =
                    __float22half2_rn(make_float2(cfrag[mi][nj][0], cfrag[mi][nj][1]));
            if (r0 + 8 < N_NODES)
                *(__half2*)&Couth[(size_t)(r0 + 8) * H_DIM + cc] =
                    __float22half2_rn(make_float2(cfrag[mi][nj][2], cfrag[mi][nj][3]));
        }
    }
}

// ---------------------------------------------------------------------------
// GEMM2 (mma.sync fp16, single pass): emb2[b] = h[perm[b]] @ W2[b].
// 2 K-iterations, 2-stage cp.async. CTA tile 128x64.
// ---------------------------------------------------------------------------
#define T2_ABYTES 16384                   // 128 rows x 128B
#define T2_BBYTES 8192                    // 64 rows x 128B
#define T2_STAGE  (T2_ABYTES + T2_BBYTES)
#define G2SM_TOTAL (2 * T2_STAGE)         // 48KB

__global__ void __launch_bounds__(256)
gemm2_mma_kernel() {
    extern __shared__ char smem[];
    const uint32_t sb = smem_u32(smem);
    const int tid = threadIdx.x;
    const int wid = tid >> 5;
    const int lane = tid & 31;
    const int tile = blockIdx.x;
    const int b = blockIdx.y;
    const int view = c_perm[b];
    const int rowBase = tile * 128;

    const int wm = wid >> 1;
    const int wn = wid & 1;

    const int arow_l = (lane & 15);
    const uint32_t akh = (uint32_t)(lane >> 4) * 16;
    const int brow_l = (lane & 7) + ((lane >> 4) << 3);
    const uint32_t bkh = (uint32_t)((lane >> 3) & 1) * 16;

    float cfrag[2][4][4];
#pragma unroll
    for (int mi = 0; mi < 2; mi++)
#pragma unroll
        for (int nj = 0; nj < 4; nj++)
#pragma unroll
            for (int q = 0; q < 4; q++) cfrag[mi][nj][q] = 0.f;

    const char* Abase = (const char*)(g_hh +
        ((size_t)view * PAD_ROWS + rowBase) * H_DIM);
    const char* Bbase = (const char*)(g_wt2 + (size_t)b * C_DIM * H_DIM);

    auto prefetch = [&](int c, int bufi) {
        const char* Asrc = Abase + c * 128;
        const char* Bsrc = Bbase + c * 128;
        const uint32_t Ab = sb + bufi * T2_STAGE;
        const uint32_t Bb = Ab + T2_ABYTES;
#pragma unroll
        for (int i = 0; i < 4; i++) {
            int idx = tid + i * 256;
            int row = idx >> 3;
            int ch  = idx & 7;
            uint32_t off = row * 128 + ch * 16;
            uint32_t sw = off ^ ((off >> 3) & 0x70);
            cp_async16(Ab + sw, Asrc + (size_t)row * (H_DIM * 2) + ch * 16);
        }
#pragma unroll
        for (int i = 0; i < 2; i++) {
            int idx = tid + i * 256;
            int row = idx >> 3;
            int ch  = idx & 7;
            uint32_t off = row * 128 + ch * 16;
            uint32_t sw = off ^ ((off >> 3) & 0x70);
            cp_async16(Bb + sw, Bsrc + (size_t)row * (H_DIM * 2) + ch * 16);
        }
        CP_COMMIT();
    };

    prefetch(0, 0);
    prefetch(1, 1);

#pragma unroll
    for (int it = 0; it < 2; it++) {
        if (it == 0) { CP_WAIT(1); } else { CP_WAIT(0); }
        __syncthreads();

        const uint32_t Ab = sb + it * T2_STAGE;
        const uint32_t Bb = Ab + T2_ABYTES;

#pragma unroll
        for (int k16 = 0; k16 < 4; k16++) {
            const uint32_t kb = k16 * 32;
            uint32_t afrag[2][4];
#pragma unroll
            for (int mi = 0; mi < 2; mi++) {
                const int row = wm * 32 + mi * 16 + arow_l;
                const uint32_t addr =
                    Ab + row * 128 + ((kb + akh) ^ (uint32_t)((row & 7) << 4));
                ldsm_x4(afrag[mi][0], afrag[mi][1], afrag[mi][2], afrag[mi][3], addr);
            }
            uint32_t bfrag[4][2];
#pragma unroll
            for (int bj = 0; bj < 2; bj++) {
                const int row = wn * 32 + bj * 16 + brow_l;
                const uint32_t addr =
                    Bb + row * 128 + ((kb + bkh) ^ (uint32_t)((row & 7) << 4));
                uint32_t r0, r1, r2, r3;
                ldsm_x4(r0, r1, r2, r3, addr);
                bfrag[bj * 2 + 0][0] = r0; bfrag[bj * 2 + 0][1] = r1;
                bfrag[bj * 2 + 1][0] = r2; bfrag[bj * 2 + 1][1] = r3;
            }
#pragma unroll
            for (int mi = 0; mi < 2; mi++)
#pragma unroll
                for (int nj = 0; nj < 4; nj++)
                    mma_f16(cfrag[mi][nj], afrag[mi], bfrag[nj]);
        }
        __syncthreads();
    }

    __half* __restrict__ Couth = g_emb2h + (size_t)b * N_NODES * C_DIM;
    const int mrow0 = rowBase + wm * 32;
    const int ncol0 = wn * 32;
    const int lr = lane >> 2;
    const int lc = (lane & 3) * 2;
#pragma unroll
    for (int mi = 0; mi < 2; mi++) {
#pragma unroll
        for (int nj = 0; nj < 4; nj++) {
            const int r0 = mrow0 + mi * 16 + lr;
            const int cc = ncol0 + nj * 8 + lc;
            if (r0 < N_NODES)
                *(__half2*)&Couth[(size_t)r0 * C_DIM + cc] =
                    __float22half2_rn(make_float2(cfrag[mi][nj][0], cfrag[mi][nj][1]));
            if (r0 + 8 < N_NODES)
                *(__half2*)&Couth[(size_t)(r0 + 8) * C_DIM + cc] =
                    __float22half2_rn(make_float2(cfrag[mi][nj][2], cfrag[mi][nj][3]));
        }
    }
}

// ---------------------------------------------------------------------------
// Fused SpMM layer 1: block per node, 64 threads (half2 column pair each).
// Self-term from fp16 combo table (gc*3). Emits h as a single fp16 plane.
// ---------------------------------------------------------------------------
__global__ void __launch_bounds__(64) spmm1_kernel(const float* __restrict__ wv1,
                                                   const float* __restrict__ b1) {
    const int i = blockIdx.x;
    const int t = threadIdx.x;
    const int comboOf[3][3] = {{0, 1, 2}, {4, 3, 5}, {7, 8, 6}};

    float2 agg[3] = {{0.f, 0.f}, {0.f, 0.f}, {0.f, 0.f}};

#pragma unroll
    for (int a = 0; a < 3; a++) {
        const int start = g_rowptr[a * RP_STRIDE + i];
        const int end   = g_rowptr[a * RP_STRIDE + i + 1];
        const __half2* __restrict__ T0 =
            (const __half2*)g_emb1h + (size_t)comboOf[0][a] * N_NODES * (H_DIM / 2);
        const __half2* __restrict__ T1 =
            (const __half2*)g_emb1h + (size_t)comboOf[1][a] * N_NODES * (H_DIM / 2);
        const __half2* __restrict__ T2 =
            (const __half2*)g_emb1h + (size_t)comboOf[2][a] * N_NODES * (H_DIM / 2);
        const int2* __restrict__ ew = g_edge + (size_t)a * N_EDGES;

        float2 p0 = {0.f, 0.f}, p1 = {0.f, 0.f}, p2 = {0.f, 0.f};
        for (int e = start; e < end; e++) {
            const int2 cw = __ldg(&ew[e]);
            const float w = __int_as_float(cw.y);
            const size_t o = (size_t)cw.x * (H_DIM / 2) + t;
            float2 v0 = __half22float2(__ldg(&T0[o]));
            float2 v1 = __half22float2(__ldg(&T1[o]));
            float2 v2 = __half22float2(__ldg(&T2[o]));
            p0.x += w * v0.x; p0.y += w * v0.y;
            p1.x += w * v1.x; p1.y += w * v1.y;
            p2.x += w * v2.x; p2.y += w * v2.y;
        }
        float w0 = wv1[comboOf[0][a]], w1 = wv1[comboOf[1][a]], w2 = wv1[comboOf[2][a]];
        agg[0].x += w0 * p0.x; agg[0].y += w0 * p0.y;
        agg[1].x += w1 * p1.x; agg[1].y += w1 * p1.y;
        agg[2].x += w2 * p2.x; agg[2].y += w2 * p2.y;
    }

    const size_t NH2 = (size_t)N_NODES * (H_DIM / 2);
    const size_t PH = (size_t)PAD_ROWS * H_DIM;
    const size_t so = (size_t)i * (H_DIM / 2) + t;
#pragma unroll
    for (int gc = 0; gc < 3; gc++) {
        float2 self = __half22float2(
            __ldg((const __half2*)g_emb1h + (size_t)(gc * 3) * NH2 + so));
        float2 bias = *(const float2*)&b1[gc * H_DIM + 2 * t];
        float hx = fmaxf(self.x + 1.01f * agg[gc].x + bias.x, 0.f);
        float hy = fmaxf(self.y + 1.01f * agg[gc].y + bias.y, 0.f);
        const size_t base = (size_t)gc * PH + (size_t)i * H_DIM + 2 * t;
        *(uint32_t*)&g_hh[base] = h2u(__float22half2_rn(make_float2(hx, hy)));
    }
}

// ---------------------------------------------------------------------------
// Fused SpMM layer 2 + final: block per node, 32 threads.
// ---------------------------------------------------------------------------
__global__ void __launch_bounds__(32) spmm2_kernel(const float* __restrict__ wv2,
                                                   const float* __restrict__ b2,
                                                   float* __restrict__ out) {
    const int i = blockIdx.x;
    const int t = threadIdx.x;
    const int comboOf[3][3] = {{0, 1, 2}, {4, 3, 5}, {7, 8, 6}};

    float2 agg[3] = {{0.f, 0.f}, {0.f, 0.f}, {0.f, 0.f}};

#pragma unroll
    for (int a = 0; a < 3; a++) {
        const int start = g_rowptr[a * RP_STRIDE + i];
        const int end   = g_rowptr[a * RP_STRIDE + i + 1];
        const __half2* __restrict__ T0 =
            (const __half2*)g_emb2h + (size_t)comboOf[0][a] * N_NODES * (C_DIM / 2);
        const __half2* __restrict__ T1 =
            (const __half2*)g_emb2h + (size_t)comboOf[1][a] * N_NODES * (C_DIM / 2);
        const __half2* __restrict__ T2 =
            (const __half2*)g_emb2h + (size_t)comboOf[2][a] * N_NODES * (C_DIM / 2);
        const int2* __restrict__ ew = g_edge + (size_t)a * N_EDGES;

        float2 p0 = {0.f, 0.f}, p1 = {0.f, 0.f}, p2 = {0.f, 0.f};
        for (int e = start; e < end; e++) {
            const int2 cw = __ldg(&ew[e]);
            const float w = __int_as_float(cw.y);
            const size_t o = (size_t)cw.x * (C_DIM / 2) + t;
            float2 v0 = __half22float2(__ldg(&T0[o]));
            float2 v1 = __half22float2(__ldg(&T1[o]));
            float2 v2 = __half22float2(__ldg(&T2[o]));
            p0.x += w * v0.x; p0.y += w * v0.y;
            p1.x += w * v1.x; p1.y += w * v1.y;
            p2.x += w * v2.x; p2.y += w * v2.y;
        }
        float w0 = wv2[comboOf[0][a]], w1 = wv2[comboOf[1][a]], w2 = wv2[comboOf[2][a]];
        agg[0].x += w0 * p0.x; agg[0].y += w0 * p0.y;
        agg[1].x += w1 * p1.x; agg[1].y += w1 * p1.y;
        agg[2].x += w2 * p2.x; agg[2].y += w2 * p2.y;
    }

    const size_t NC2 = (size_t)N_NODES * (C_DIM / 2);
    const size_t so = (size_t)i * (C_DIM / 2) + t;
    float2 ysum = {0.f, 0.f};
#pragma unroll
    for (int gc = 0; gc < 3; gc++) {
        float2 self = __half22float2(
            __ldg((const __half2*)g_emb2h + (size_t)(gc * 3) * NC2 + so));
        float2 bias = *(const float2*)&b2[gc * C_DIM + 2 * t];
        ysum.x += fmaxf(self.x + 1.01f * agg[gc].x + bias.x, 0.f);
        ysum.y += fmaxf(self.y + 1.01f * agg[gc].y + bias.y, 0.f);
    }
    const size_t oi = (size_t)i * C_DIM + 2 * t;
    *(float2*)&out[oi] = make_float2(fabsf(ysum.x * (1.f / 3.f)),
                                     fabsf(ysum.y * (1.f / 3.f)));
}

// ---------------------------------------------------------------------------
extern "C" void kernel_launch(void* const* d_in, const int* in_sizes, int n_in,
                              void* d_out, int out_size) {
    const float* x1 = (const float*)d_in[0];
    const float* x2 = (const float*)d_in[1];
    const float* x3 = (const float*)d_in[2];
    const int*   s0 = (const int*)d_in[3];
    const int*   d0 = (const int*)d_in[4];
    const float* v0 = (const float*)d_in[5];
    const int*   s1 = (const int*)d_in[6];
    const int*   d1 = (const int*)d_in[7];
    const float* v1 = (const float*)d_in[8];
    const int*   s2 = (const int*)d_in[9];
    const int*   d2 = (const int*)d_in[10];
    const float* v2 = (const float*)d_in[11];
    const float* W1  = (const float*)d_in[12];
    const float* wv1 = (const float*)d_in[13];
    const float* b1  = (const float*)d_in[14];
    const float* W2  = (const float*)d_in[15];
    const float* wv2 = (const float*)d_in[16];
    const float* b2  = (const float*)d_in[17];
    float* out = (float*)d_out;

    cudaFuncSetAttribute(gemm1_mma_kernel,
                         cudaFuncAttributeMaxDynamicSharedMemorySize, GSM_TOTAL);
    cudaFuncSetAttribute(gemm2_mma_kernel,
                         cudaFuncAttributeMaxDynamicSharedMemorySize, G2SM_TOTAL);

    // K0: zero cursors — separate launch, MUST complete before hist atomics
    csr_zero_kernel<<<(3 * N_NODES + 255) / 256, 256>>>();
    // K1: fused converts + histogram
    prep_kernel<<<NB_PREP, 256>>>(x1, x2, x3, W1, W2, s0, s1, s2);
    // K2: scan — own kernel (must precede the fill blocks in gemm1)
    csr_scan_kernel<<<3, 256>>>();
    // K3: gemm1 with fill blocks piggybacked at grid front
    gemm1_mma_kernel<<<NB_FILL + NB_GEMM1, 256, GSM_TOTAL>>>(
        s0, s1, s2, d0, d1, d2, v0, v1, v2);
    // K4-K6
    spmm1_kernel<<<N_NODES, 64>>>(wv1, b1);
    gemm2_mma_kernel<<<dim3(157, 9), 256, G2SM_TOTAL>>>();
    spmm2_kernel<<<N_NODES, 32>>>(wv2, b2, out);
}

// round 11
// speedup vs baseline: 4.6385x; 1.0845x over previous
#include <cuda_runtime.h>
#include <cuda_bf16.h>
#include <cuda_fp16.h>
#include <cstdint>

#define N_NODES 20000
#define F_DIM   512
#define H_DIM   128
#define C_DIM   64
#define N_EDGES 640000
#define PAD_ROWS 20096       // 157 * 128
#define RP_STRIDE 20004      // N_NODES+1 padded to 4-int alignment

// ---------------------------------------------------------------------------
// Scratch (static device globals; no runtime allocation allowed)
// ---------------------------------------------------------------------------
__device__ __half g_emb1h[9 * N_NODES * H_DIM];   // fp16 tables (combo); self = combo gc*3
__device__ __half g_emb2h[9 * N_NODES * C_DIM];

// fp16 GEMM operands (single-pass fp16 mma)
__device__ __half g_xh[3 * PAD_ROWS * F_DIM];     // [view][row][k]
__device__ __half g_wt[9 * H_DIM * F_DIM];        // [combo][n][k]
__device__ __half g_hh[3 * PAD_ROWS * H_DIM];     // [gc][row][k]
__device__ __half g_wt2[9 * C_DIM * H_DIM];       // [combo][n][k]

// CSR scratch
__device__ int  g_rowptr[3 * RP_STRIDE];
__device__ int  g_cursor[3 * N_NODES];
__device__ int2 g_edge[3 * N_EDGES];              // {col, w-as-int}

// combo -> which x / adjacency feeds it. combo = gc*3 + role.
__constant__ int c_perm[9] = {0,1,2, 1,0,2, 2,0,1};

// ---------------------------------------------------------------------------
// PTX helpers (base-target only: sm_80+ features)
// ---------------------------------------------------------------------------
__device__ __forceinline__ uint32_t smem_u32(const void* p) {
    uint32_t a;
    asm("{ .reg .u64 t; cvta.to.shared.u64 t, %1; cvt.u32.u64 %0, t; }"
        : "=r"(a) : "l"(p));
    return a;
}

__device__ __forceinline__ void cp_async16(uint32_t dst, const void* src) {
    asm volatile("cp.async.cg.shared.global [%0], [%1], 16;"
                 :: "r"(dst), "l"(src) : "memory");
}
#define CP_COMMIT() asm volatile("cp.async.commit_group;" ::: "memory")
#define CP_WAIT(n)  asm volatile("cp.async.wait_group %0;" :: "n"(n) : "memory")

__device__ __forceinline__ void ldsm_x4(uint32_t& r0, uint32_t& r1,
                                        uint32_t& r2, uint32_t& r3, uint32_t addr) {
    asm volatile("ldmatrix.sync.aligned.m8n8.x4.shared.b16 {%0,%1,%2,%3}, [%4];"
                 : "=r"(r0), "=r"(r1), "=r"(r2), "=r"(r3) : "r"(addr));
}

__device__ __forceinline__ void mma_f16(float* d, const uint32_t* a,
                                        const uint32_t* b) {
    asm volatile(
        "mma.sync.aligned.m16n8k16.row.col.f32.f16.f16.f32 "
        "{%0,%1,%2,%3}, {%4,%5,%6,%7}, {%8,%9}, {%0,%1,%2,%3};"
        : "+f"(d[0]), "+f"(d[1]), "+f"(d[2]), "+f"(d[3])
        : "r"(a[0]), "r"(a[1]), "r"(a[2]), "r"(a[3]), "r"(b[0]), "r"(b[1]));
}

__device__ __forceinline__ uint32_t h2u(__half2 h) {
    return *(uint32_t*)&h;
}

// ---------------------------------------------------------------------------
// K0: csr_zero — own kernel: all cursor zeroes visible before hist atomics.
// ---------------------------------------------------------------------------
__global__ void csr_zero_kernel() {
    int i = blockIdx.x * blockDim.x + threadIdx.x;
    if (i < 3 * N_NODES) g_cursor[i] = 0;
}

// ---------------------------------------------------------------------------
// K1: fused prep — cvt_x | cvt_w | cvt_w2 | csr_hist (NO zeroing here)
// ---------------------------------------------------------------------------
#define NB_SPLITX 30000
#define NB_SPLITW 2304
#define NB_SPLITW2 288
#define NB_HIST_PER 625
#define B_SPLITW  (NB_SPLITX)
#define B_SPLITW2 (B_SPLITW + NB_SPLITW)
#define B_HIST    (B_SPLITW2 + NB_SPLITW2)
#define NB_PREP   (B_HIST + 3 * NB_HIST_PER)

__global__ void __launch_bounds__(256)
prep_kernel(const float* __restrict__ x1, const float* __restrict__ x2,
            const float* __restrict__ x3, const float* __restrict__ W1,
            const float* __restrict__ W2,
            const int* __restrict__ s0, const int* __restrict__ s1,
            const int* __restrict__ s2) {
    const int bid = blockIdx.x;
    const int tid = threadIdx.x;

    if (bid < NB_SPLITX) {
        int i = bid * 256 + tid;  // one float4 each
        const int per_view = N_NODES * (F_DIM / 4);
        const int view = i / per_view;
        const int rem  = i - view * per_view;
        const int row  = rem / (F_DIM / 4);
        const int kg   = rem - row * (F_DIM / 4);
        const float* X = (view == 0) ? x1 : (view == 1) ? x2 : x3;
        float4 f = ((const float4*)X)[rem];
        __half2 a = __float22half2_rn(make_float2(f.x, f.y));
        __half2 b = __float22half2_rn(make_float2(f.z, f.w));
        size_t off = ((size_t)view * PAD_ROWS + row) * F_DIM + kg * 4;
        *(uint2*)&g_xh[off] = make_uint2(h2u(a), h2u(b));
    } else if (bid < B_SPLITW2) {
        int i = (bid - B_SPLITW) * 256 + tid;   // over 9*512*128, n fastest
        const int b = i / (F_DIM * H_DIM);
        const int rem = i - b * (F_DIM * H_DIM);
        const int k = rem / H_DIM;
        const int n = rem - k * H_DIM;
        g_wt[((size_t)b * H_DIM + n) * F_DIM + k] = __float2half_rn(W1[i]);
    } else if (bid < B_HIST) {
        int i = (bid - B_SPLITW2) * 256 + tid;  // over 9*128*64
        const int b = i / (H_DIM * C_DIM);
        const int rem = i - b * (H_DIM * C_DIM);
        const int k = rem / C_DIM;
        const int n = rem - k * C_DIM;
        g_wt2[((size_t)b * C_DIM + n) * H_DIM + k] = __float2half_rn(W2[i]);
    } else {
        const int rel = bid - B_HIST;
        const int a = rel / NB_HIST_PER;
        const int blk = rel - a * NB_HIST_PER;
        const int* __restrict__ s = (a == 0) ? s0 : (a == 1) ? s1 : s2;
        int* __restrict__ cur = g_cursor + a * N_NODES;
        const int base = blk * 1024 + tid;
#pragma unroll
        for (int k = 0; k < 4; k++)
            atomicAdd(&cur[__ldg(&s[base + k * 256])], 1);
    }
}

// ---------------------------------------------------------------------------
// K2: csr_scan — own kernel (3 blocks, 256 threads).
// ---------------------------------------------------------------------------
__global__ void __launch_bounds__(256) csr_scan_kernel() {
    const int a = blockIdx.x;
    __shared__ int s_warp[9];
    int* cnt = g_cursor + a * N_NODES;
    int* rp  = g_rowptr + a * RP_STRIDE;
    const int tid = threadIdx.x;
    const int lane = tid & 31;
    const int w = tid >> 5;
    int carry = 0;
    for (int base = 0; base < N_NODES; base += 1024) {
        const int idx = base + tid * 4;
        int v0 = 0, v1 = 0, v2 = 0, v3 = 0;
        if (idx + 3 < N_NODES) {
            int4 t = *(const int4*)&cnt[idx];
            v0 = t.x; v1 = t.y; v2 = t.z; v3 = t.w;
        } else {
            if (idx + 0 < N_NODES) v0 = cnt[idx + 0];
            if (idx + 1 < N_NODES) v1 = cnt[idx + 1];
            if (idx + 2 < N_NODES) v2 = cnt[idx + 2];
            if (idx + 3 < N_NODES) v3 = cnt[idx + 3];
        }
        const int tsum = v0 + v1 + v2 + v3;
        int sc = tsum;
#pragma unroll
        for (int o = 1; o < 32; o <<= 1) {
            int n = __shfl_up_sync(0xffffffff, sc, o);
            if (lane >= o) sc += n;
        }
        if (lane == 31) s_warp[w] = sc;
        __syncthreads();
        if (w == 0) {
            int x = (lane < 8) ? s_warp[lane] : 0;
#pragma unroll
            for (int o = 1; o < 8; o <<= 1) {
                int n = __shfl_up_sync(0xffffffff, x, o);
                if (lane >= o) x += n;
            }
            if (lane < 8) s_warp[lane] = x;
            if (lane == 7) s_warp[8] = x;
        }
        __syncthreads();
        const int warp_off = (w == 0) ? 0 : s_warp[w - 1];
        const int excl = carry + warp_off + (sc - tsum);
        const int p0 = excl, p1 = p0 + v0, p2 = p1 + v1, p3 = p2 + v2;
        if (idx + 3 < N_NODES) {
            *(int4*)&rp[idx]  = make_int4(p0, p1, p2, p3);
            *(int4*)&cnt[idx] = make_int4(p0, p1, p2, p3);
        } else {
            if (idx + 0 < N_NODES) { rp[idx + 0] = p0; cnt[idx + 0] = p0; }
            if (idx + 1 < N_NODES) { rp[idx + 1] = p1; cnt[idx + 1] = p1; }
            if (idx + 2 < N_NODES) { rp[idx + 2] = p2; cnt[idx + 2] = p2; }
            if (idx + 3 < N_NODES) { rp[idx + 3] = p3; cnt[idx + 3] = p3; }
        }
        carry += s_warp[8];
        __syncthreads();
    }
    if (tid == 0) rp[N_NODES] = carry;
}

// ---------------------------------------------------------------------------
// K3: GEMM1 (mma.sync fp16, single pass) with csr_fill piggybacked at grid
// front. grid: 1875 fill blocks + 1413 gemm blocks. 256 threads.
// 8 K-iterations (chunks of 64 halfs), 3-stage cp.async, SW128 swizzle.
// __launch_bounds__(256, 2): cap regs at 128 -> 2 CTAs/SM (R10 hit 132 regs
// -> 1 CTA/SM -> occupancy cliff).
// ---------------------------------------------------------------------------
#define TILE_BYTES 16384                  // 128 rows x 128B
#define STAGE_BYTES (2 * TILE_BYTES)      // A + B
#define GSM_TOTAL (3 * STAGE_BYTES)       // 3 stages = 96KB
#define NB_GEMM1 (157 * 9)
#define NB_FILL (3 * NB_HIST_PER)

__global__ void __launch_bounds__(256, 2)
gemm1_mma_kernel(const int* __restrict__ s0, const int* __restrict__ s1,
                 const int* __restrict__ s2, const int* __restrict__ d0,
                 const int* __restrict__ d1, const int* __restrict__ d2,
                 const float* __restrict__ v0, const float* __restrict__ v1,
                 const float* __restrict__ v2) {
    if (blockIdx.x < NB_FILL) {           // piggybacked fill blocks (run early)
        const int rel = blockIdx.x;
        const int a = rel / NB_HIST_PER;
        const int blk = rel - a * NB_HIST_PER;
        const int*   __restrict__ s = (a == 0) ? s0 : (a == 1) ? s1 : s2;
        const int*   __restrict__ d = (a == 0) ? d0 : (a == 1) ? d1 : d2;
        const float* __restrict__ v = (a == 0) ? v0 : (a == 1) ? v1 : v2;
        int* __restrict__ cur = g_cursor + a * N_NODES;
        int2* __restrict__ eo = g_edge + (size_t)a * N_EDGES;
        const int base = blk * 1024 + threadIdx.x;
#pragma unroll
        for (int k = 0; k < 4; k++) {
            const int e = base + k * 256;
            const int ss = __ldg(&s[e]);
            const int dd = __ldg(&d[e]);
            const float vv = __ldg(&v[e]);
            int pos = atomicAdd(&cur[ss], 1);
            eo[pos] = make_int2(dd, __float_as_int(vv));
        }
        return;
    }
    extern __shared__ char smem[];
    const uint32_t sb = smem_u32(smem);
    const int tid = threadIdx.x;
    const int wid = tid >> 5;
    const int lane = tid & 31;
    const int gbid = blockIdx.x - NB_FILL;
    const int tile = gbid % 157;
    const int b = gbid / 157;
    const int view = c_perm[b];
    const int rowBase = tile * 128;

    const int wm = wid >> 1;
    const int wn = wid & 1;

    const int arow_l = (lane & 15);
    const uint32_t akh = (uint32_t)(lane >> 4) * 16;
    const int brow_l = (lane & 7) + ((lane >> 4) << 3);
    const uint32_t bkh = (uint32_t)((lane >> 3) & 1) * 16;

    float cfrag[2][8][4];
#pragma unroll
    for (int mi = 0; mi < 2; mi++)
#pragma unroll
        for (int nj = 0; nj < 8; nj++)
#pragma unroll
            for (int q = 0; q < 4; q++) cfrag[mi][nj][q] = 0.f;

    const char* Abase = (const char*)(g_xh +
        ((size_t)view * PAD_ROWS + rowBase) * F_DIM);
    const char* Bbase = (const char*)(g_wt + (size_t)b * H_DIM * F_DIM);

    auto prefetch = [&](int c, int bufi) {
        const char* Asrc = Abase + c * 128;
        const char* Bsrc = Bbase + c * 128;
        const uint32_t Ab = sb + bufi * STAGE_BYTES;
        const uint32_t Bb = Ab + TILE_BYTES;
#pragma unroll
        for (int i = 0; i < 4; i++) {
            int idx = tid + i * 256;
            int row = idx >> 3;
            int ch  = idx & 7;
            uint32_t off = row * 128 + ch * 16;
            uint32_t sw = off ^ ((off >> 3) & 0x70);
            cp_async16(Ab + sw, Asrc + (size_t)row * (F_DIM * 2) + ch * 16);
            cp_async16(Bb + sw, Bsrc + (size_t)row * (F_DIM * 2) + ch * 16);
        }
        CP_COMMIT();
    };

    prefetch(0, 0);
    prefetch(1, 1);

    for (int it = 0; it < 8; it++) {
        const int bufi = it % 3;
        if (it < 6) {
            prefetch(it + 2, (it + 2) % 3);
            CP_WAIT(2);
        } else {
            CP_WAIT(0);
        }
        __syncthreads();

        const uint32_t Ab = sb + bufi * STAGE_BYTES;
        const uint32_t Bb = Ab + TILE_BYTES;

#pragma unroll
        for (int k16 = 0; k16 < 4; k16++) {
            const uint32_t kb = k16 * 32;
            uint32_t afrag[2][4];
#pragma unroll
            for (int mi = 0; mi < 2; mi++) {
                const int row = wm * 32 + mi * 16 + arow_l;
                const uint32_t addr =
                    Ab + row * 128 + ((kb + akh) ^ (uint32_t)((row & 7) << 4));
                ldsm_x4(afrag[mi][0], afrag[mi][1], afrag[mi][2], afrag[mi][3], addr);
            }
            uint32_t bfrag[8][2];
#pragma unroll
            for (int bj = 0; bj < 4; bj++) {
                const int row = wn * 64 + bj * 16 + brow_l;
                const uint32_t addr =
                    Bb + row * 128 + ((kb + bkh) ^ (uint32_t)((row & 7) << 4));
                uint32_t r0, r1, r2, r3;
                ldsm_x4(r0, r1, r2, r3, addr);
                bfrag[bj * 2 + 0][0] = r0; bfrag[bj * 2 + 0][1] = r1;
                bfrag[bj * 2 + 1][0] = r2; bfrag[bj * 2 + 1][1] = r3;
            }
#pragma unroll
            for (int mi = 0; mi < 2; mi++)
#pragma unroll
                for (int nj = 0; nj < 8; nj++)
                    mma_f16(cfrag[mi][nj], afrag[mi], bfrag[nj]);
        }
        __syncthreads();
    }

    // Epilogue: half table (self-term read from combo gc*3 in spmm1)
    __half* __restrict__ Couth = g_emb1h + (size_t)b * N_NODES * H_DIM;
    const int mrow0 = rowBase + wm * 32;
    const int ncol0 = wn * 64;
    const int lr = lane >> 2;
    const int lc = (lane & 3) * 2;
#pragma unroll
    for (int mi = 0; mi < 2; mi++) {
#pragma unroll
        for (int nj = 0; nj < 8; nj++) {
            const int r0 = mrow0 + mi * 16 + lr;
            const int cc = ncol0 + nj * 8 + lc;
            if (r0 < N_NODES)
                *(__half2*)&Couth[(size_t)r0 * H_DIM + cc] =
                    __float22half2_rn(make_float2(cfrag[mi][nj][0], cfrag[mi][nj][1]));
            if (r0 + 8 < N_NODES)
                *(__half2*)&Couth[(size_t)(r0 + 8) * H_DIM + cc] =
                    __float22half2_rn(make_float2(cfrag[mi][nj][2], cfrag[mi][nj][3]));
        }
    }
}

// ---------------------------------------------------------------------------
// GEMM2 (mma.sync fp16, single pass): emb2[b] = h[perm[b]] @ W2[b].
// 2 K-iterations, 2-stage cp.async. CTA tile 128x64.
// ---------------------------------------------------------------------------
#define T2_ABYTES 16384                   // 128 rows x 128B
#define T2_BBYTES 8192                    // 64 rows x 128B
#define T2_STAGE  (T2_ABYTES + T2_BBYTES)
#define G2SM_TOTAL (2 * T2_STAGE)         // 48KB

__global__ void __launch_bounds__(256, 2)
gemm2_mma_kernel() {
    extern __shared__ char smem[];
    const uint32_t sb = smem_u32(smem);
    const int tid = threadIdx.x;
    const int wid = tid >> 5;
    const int lane = tid & 31;
    const int tile = blockIdx.x;
    const int b = blockIdx.y;
    const int view = c_perm[b];
    const int rowBase = tile * 128;

    const int wm = wid >> 1;
    const int wn = wid & 1;

    const int arow_l = (lane & 15);
    const uint32_t akh = (uint32_t)(lane >> 4) * 16;
    const int brow_l = (lane & 7) + ((lane >> 4) << 3);
    const uint32_t bkh = (uint32_t)((lane >> 3) & 1) * 16;

    float cfrag[2][4][4];
#pragma unroll
    for (int mi = 0; mi < 2; mi++)
#pragma unroll
        for (int nj = 0; nj < 4; nj++)
#pragma unroll
            for (int q = 0; q < 4; q++) cfrag[mi][nj][q] = 0.f;

    const char* Abase = (const char*)(g_hh +
        ((size_t)view * PAD_ROWS + rowBase) * H_DIM);
    const char* Bbase = (const char*)(g_wt2 + (size_t)b * C_DIM * H_DIM);

    auto prefetch = [&](int c, int bufi) {
        const char* Asrc = Abase + c * 128;
        const char* Bsrc = Bbase + c * 128;
        const uint32_t Ab = sb + bufi * T2_STAGE;
        const uint32_t Bb = Ab + T2_ABYTES;
#pragma unroll
        for (int i = 0; i < 4; i++) {
            int idx = tid + i * 256;
            int row = idx >> 3;
            int ch  = idx & 7;
            uint32_t off = row * 128 + ch * 16;
            uint32_t sw = off ^ ((off >> 3) & 0x70);
            cp_async16(Ab + sw, Asrc + (size_t)row * (H_DIM * 2) + ch * 16);
        }
#pragma unroll
        for (int i = 0; i < 2; i++) {
            int idx = tid + i * 256;
            int row = idx >> 3;
            int ch  = idx & 7;
            uint32_t off = row * 128 + ch * 16;
            uint32_t sw = off ^ ((off >> 3) & 0x70);
            cp_async16(Bb + sw, Bsrc + (size_t)row * (H_DIM * 2) + ch * 16);
        }
        CP_COMMIT();
    };

    prefetch(0, 0);
    prefetch(1, 1);

#pragma unroll
    for (int it = 0; it < 2; it++) {
        if (it == 0) { CP_WAIT(1); } else { CP_WAIT(0); }
        __syncthreads();

        const uint32_t Ab = sb + it * T2_STAGE;
        const uint32_t Bb = Ab + T2_ABYTES;

#pragma unroll
        for (int k16 = 0; k16 < 4; k16++) {
            const uint32_t kb = k16 * 32;
            uint32_t afrag[2][4];
#pragma unroll
            for (int mi = 0; mi < 2; mi++) {
                const int row = wm * 32 + mi * 16 + arow_l;
                const uint32_t addr =
                    Ab + row * 128 + ((kb + akh) ^ (uint32_t)((row & 7) << 4));
                ldsm_x4(afrag[mi][0], afrag[mi][1], afrag[mi][2], afrag[mi][3], addr);
            }
            uint32_t bfrag[4][2];
#pragma unroll
            for (int bj = 0; bj < 2; bj++) {
                const int row = wn * 32 + bj * 16 + brow_l;
                const uint32_t addr =
                    Bb + row * 128 + ((kb + bkh) ^ (uint32_t)((row & 7) << 4));
                uint32_t r0, r1, r2, r3;
                ldsm_x4(r0, r1, r2, r3, addr);
                bfrag[bj * 2 + 0][0] = r0; bfrag[bj * 2 + 0][1] = r1;
                bfrag[bj * 2 + 1][0] = r2; bfrag[bj * 2 + 1][1] = r3;
            }
#pragma unroll
            for (int mi = 0; mi < 2; mi++)
#pragma unroll
                for (int nj = 0; nj < 4; nj++)
                    mma_f16(cfrag[mi][nj], afrag[mi], bfrag[nj]);
        }
        __syncthreads();
    }

    __half* __restrict__ Couth = g_emb2h + (size_t)b * N_NODES * C_DIM;
    const int mrow0 = rowBase + wm * 32;
    const int ncol0 = wn * 32;
    const int lr = lane >> 2;
    const int lc = (lane & 3) * 2;
#pragma unroll
    for (int mi = 0; mi < 2; mi++) {
#pragma unroll
        for (int nj = 0; nj < 4; nj++) {
            const int r0 = mrow0 + mi * 16 + lr;
            const int cc = ncol0 + nj * 8 + lc;
            if (r0 < N_NODES)
                *(__half2*)&Couth[(size_t)r0 * C_DIM + cc] =
                    __float22half2_rn(make_float2(cfrag[mi][nj][0], cfrag[mi][nj][1]));
            if (r0 + 8 < N_NODES)
                *(__half2*)&Couth[(size_t)(r0 + 8) * C_DIM + cc] =
                    __float22half2_rn(make_float2(cfrag[mi][nj][2], cfrag[mi][nj][3]));
        }
    }
}

// ---------------------------------------------------------------------------
// Fused SpMM layer 1: block per node, 64 threads (half2 column pair each).
// Self-term from fp16 combo table (gc*3). Emits h as a single fp16 plane.
// ---------------------------------------------------------------------------
__global__ void __launch_bounds__(64) spmm1_kernel(const float* __restrict__ wv1,
                                                   const float* __restrict__ b1) {
    const int i = blockIdx.x;
    const int t = threadIdx.x;
    const int comboOf[3][3] = {{0, 1, 2}, {4, 3, 5}, {7, 8, 6}};

    float2 agg[3] = {{0.f, 0.f}, {0.f, 0.f}, {0.f, 0.f}};

#pragma unroll
    for (int a = 0; a < 3; a++) {
        const int start = g_rowptr[a * RP_STRIDE + i];
        const int end   = g_rowptr[a * RP_STRIDE + i + 1];
        const __half2* __restrict__ T0 =
            (const __half2*)g_emb1h + (size_t)comboOf[0][a] * N_NODES * (H_DIM / 2);
        const __half2* __restrict__ T1 =
            (const __half2*)g_emb1h + (size_t)comboOf[1][a] * N_NODES * (H_DIM / 2);
        const __half2* __restrict__ T2 =
            (const __half2*)g_emb1h + (size_t)comboOf[2][a] * N_NODES * (H_DIM / 2);
        const int2* __restrict__ ew = g_edge + (size_t)a * N_EDGES;

        float2 p0 = {0.f, 0.f}, p1 = {0.f, 0.f}, p2 = {0.f, 0.f};
        for (int e = start; e < end; e++) {
            const int2 cw = __ldg(&ew[e]);
            const float w = __int_as_float(cw.y);
            const size_t o = (size_t)cw.x * (H_DIM / 2) + t;
            float2 v0 = __half22float2(__ldg(&T0[o]));
            float2 v1 = __half22float2(__ldg(&T1[o]));
            float2 v2 = __half22float2(__ldg(&T2[o]));
            p0.x += w * v0.x; p0.y += w * v0.y;
            p1.x += w * v1.x; p1.y += w * v1.y;
            p2.x += w * v2.x; p2.y += w * v2.y;
        }
        float w0 = wv1[comboOf[0][a]], w1 = wv1[comboOf[1][a]], w2 = wv1[comboOf[2][a]];
        agg[0].x += w0 * p0.x; agg[0].y += w0 * p0.y;
        agg[1].x += w1 * p1.x; agg[1].y += w1 * p1.y;
        agg[2].x += w2 * p2.x; agg[2].y += w2 * p2.y;
    }

    const size_t NH2 = (size_t)N_NODES * (H_DIM / 2);
    const size_t PH = (size_t)PAD_ROWS * H_DIM;
    const size_t so = (size_t)i * (H_DIM / 2) + t;
#pragma unroll
    for (int gc = 0; gc < 3; gc++) {
        float2 self = __half22float2(
            __ldg((const __half2*)g_emb1h + (size_t)(gc * 3) * NH2 + so));
        float2 bias = *(const float2*)&b1[gc * H_DIM + 2 * t];
        float hx = fmaxf(self.x + 1.01f * agg[gc].x + bias.x, 0.f);
        float hy = fmaxf(self.y + 1.01f * agg[gc].y + bias.y, 0.f);
        const size_t base = (size_t)gc * PH + (size_t)i * H_DIM + 2 * t;
        *(uint32_t*)&g_hh[base] = h2u(__float22half2_rn(make_float2(hx, hy)));
    }
}

// ---------------------------------------------------------------------------
// Fused SpMM layer 2 + final: block per node, 32 threads.
// ---------------------------------------------------------------------------
__global__ void __launch_bounds__(32) spmm2_kernel(const float* __restrict__ wv2,
                                                   const float* __restrict__ b2,
                                                   float* __restrict__ out) {
    const int i = blockIdx.x;
    const int t = threadIdx.x;
    const int comboOf[3][3] = {{0, 1, 2}, {4, 3, 5}, {7, 8, 6}};

    float2 agg[3] = {{0.f, 0.f}, {0.f, 0.f}, {0.f, 0.f}};

#pragma unroll
    for (int a = 0; a < 3; a++) {
        const int start = g_rowptr[a * RP_STRIDE + i];
        const int end   = g_rowptr[a * RP_STRIDE + i + 1];
        const __half2* __restrict__ T0 =
            (const __half2*)g_emb2h + (size_t)comboOf[0][a] * N_NODES * (C_DIM / 2);
        const __half2* __restrict__ T1 =
            (const __half2*)g_emb2h + (size_t)comboOf[1][a] * N_NODES * (C_DIM / 2);
        const __half2* __restrict__ T2 =
            (const __half2*)g_emb2h + (size_t)comboOf[2][a] * N_NODES * (C_DIM / 2);
        const int2* __restrict__ ew = g_edge + (size_t)a * N_EDGES;

        float2 p0 = {0.f, 0.f}, p1 = {0.f, 0.f}, p2 = {0.f, 0.f};
        for (int e = start; e < end; e++) {
            const int2 cw = __ldg(&ew[e]);
            const float w = __int_as_float(cw.y);
            const size_t o = (size_t)cw.x * (C_DIM / 2) + t;
            float2 v0 = __half22float2(__ldg(&T0[o]));
            float2 v1 = __half22float2(__ldg(&T1[o]));
            float2 v2 = __half22float2(__ldg(&T2[o]));
            p0.x += w * v0.x; p0.y += w * v0.y;
            p1.x += w * v1.x; p1.y += w * v1.y;
            p2.x += w * v2.x; p2.y += w * v2.y;
        }
        float w0 = wv2[comboOf[0][a]], w1 = wv2[comboOf[1][a]], w2 = wv2[comboOf[2][a]];
        agg[0].x += w0 * p0.x; agg[0].y += w0 * p0.y;
        agg[1].x += w1 * p1.x; agg[1].y += w1 * p1.y;
        agg[2].x += w2 * p2.x; agg[2].y += w2 * p2.y;
    }

    const size_t NC2 = (size_t)N_NODES * (C_DIM / 2);
    const size_t so = (size_t)i * (C_DIM / 2) + t;
    float2 ysum = {0.f, 0.f};
#pragma unroll
    for (int gc = 0; gc < 3; gc++) {
        float2 self = __half22float2(
            __ldg((const __half2*)g_emb2h + (size_t)(gc * 3) * NC2 + so));
        float2 bias = *(const float2*)&b2[gc * C_DIM + 2 * t];
        ysum.x += fmaxf(self.x + 1.01f * agg[gc].x + bias.x, 0.f);
        ysum.y += fmaxf(self.y + 1.01f * agg[gc].y + bias.y, 0.f);
    }
    const size_t oi = (size_t)i * C_DIM + 2 * t;
    *(float2*)&out[oi] = make_float2(fabsf(ysum.x * (1.f / 3.f)),
                                     fabsf(ysum.y * (1.f / 3.f)));
}

// ---------------------------------------------------------------------------
extern "C" void kernel_launch(void* const* d_in, const int* in_sizes, int n_in,
                              void* d_out, int out_size) {
    const float* x1 = (const float*)d_in[0];
    const float* x2 = (const float*)d_in[1];
    const float* x3 = (const float*)d_in[2];
    const int*   s0 = (const int*)d_in[3];
    const int*   d0 = (const int*)d_in[4];
    const float* v0 = (const float*)d_in[5];
    const int*   s1 = (const int*)d_in[6];
    const int*   d1 = (const int*)d_in[7];
    const float* v1 = (const float*)d_in[8];
    const int*   s2 = (const int*)d_in[9];
    const int*   d2 = (const int*)d_in[10];
    const float* v2 = (const float*)d_in[11];
    const float* W1  = (const float*)d_in[12];
    const float* wv1 = (const float*)d_in[13];
    const float* b1  = (const float*)d_in[14];
    const float* W2  = (const float*)d_in[15];
    const float* wv2 = (const float*)d_in[16];
    const float* b2  = (const float*)d_in[17];
    float* out = (float*)d_out;

    cudaFuncSetAttribute(gemm1_mma_kernel,
                         cudaFuncAttributeMaxDynamicSharedMemorySize, GSM_TOTAL);
    cudaFuncSetAttribute(gemm2_mma_kernel,
                         cudaFuncAttributeMaxDynamicSharedMemorySize, G2SM_TOTAL);

    // K0: zero cursors — separate launch, MUST complete before hist atomics
    csr_zero_kernel<<<(3 * N_NODES + 255) / 256, 256>>>();
    // K1: fused converts + histogram
    prep_kernel<<<NB_PREP, 256>>>(x1, x2, x3, W1, W2, s0, s1, s2);
    // K2: scan — own kernel (must precede the fill blocks in gemm1)
    csr_scan_kernel<<<3, 256>>>();
    // K3: gemm1 with fill blocks piggybacked at grid front
    gemm1_mma_kernel<<<NB_FILL + NB_GEMM1, 256, GSM_TOTAL>>>(
        s0, s1, s2, d0, d1, d2, v0, v1, v2);
    // K4-K6
    spmm1_kernel<<<N_NODES, 64>>>(wv1, b1);
    gemm2_mma_kernel<<<dim3(157, 9), 256, G2SM_TOTAL>>>();
    spmm2_kernel<<<N_NODES, 32>>>(wv2, b2, out);
}

// round 12
// speedup vs baseline: 4.7420x; 1.0223x over previous
#include <cuda_runtime.h>
#include <cuda_bf16.h>
#include <cuda_fp16.h>
#include <cstdint>

#define N_NODES 20000
#define F_DIM   512
#define H_DIM   128
#define C_DIM   64
#define N_EDGES 640000
#define PAD_ROWS 20096       // 157 * 128
#define RP_STRIDE 20004      // N_NODES+1 padded to 4-int alignment

// ---------------------------------------------------------------------------
// Scratch (static device globals; no runtime allocation allowed)
// ---------------------------------------------------------------------------
__device__ __half g_emb1h[9 * N_NODES * H_DIM];   // fp16 tables (combo); self = combo gc*3
__device__ __half g_emb2h[9 * N_NODES * C_DIM];

// fp16 GEMM operands (single-pass fp16 mma)
__device__ __half g_xh[3 * PAD_ROWS * F_DIM];     // [view][row][k]
__device__ __half g_wt[9 * H_DIM * F_DIM];        // [combo][n][k]
__device__ __half g_hh[3 * PAD_ROWS * H_DIM];     // [gc][row][k]
__device__ __half g_wt2[9 * C_DIM * H_DIM];       // [combo][n][k]

// CSR scratch
__device__ int  g_rowptr[3 * RP_STRIDE];
__device__ int  g_cursor[3 * N_NODES];
__device__ int2 g_edge[3 * N_EDGES];              // {col, w-as-int}

// combo -> which x / adjacency feeds it. combo = gc*3 + role.
__constant__ int c_perm[9] = {0,1,2, 1,0,2, 2,0,1};

// ---------------------------------------------------------------------------
// PTX helpers (base-target only: sm_80+ features)
// ---------------------------------------------------------------------------
__device__ __forceinline__ uint32_t smem_u32(const void* p) {
    uint32_t a;
    asm("{ .reg .u64 t; cvta.to.shared.u64 t, %1; cvt.u32.u64 %0, t; }"
        : "=r"(a) : "l"(p));
    return a;
}

__device__ __forceinline__ void cp_async16(uint32_t dst, const void* src) {
    asm volatile("cp.async.cg.shared.global [%0], [%1], 16;"
                 :: "r"(dst), "l"(src) : "memory");
}
#define CP_COMMIT() asm volatile("cp.async.commit_group;" ::: "memory")
#define CP_WAIT(n)  asm volatile("cp.async.wait_group %0;" :: "n"(n) : "memory")

__device__ __forceinline__ void ldsm_x4(uint32_t& r0, uint32_t& r1,
                                        uint32_t& r2, uint32_t& r3, uint32_t addr) {
    asm volatile("ldmatrix.sync.aligned.m8n8.x4.shared.b16 {%0,%1,%2,%3}, [%4];"
                 : "=r"(r0), "=r"(r1), "=r"(r2), "=r"(r3) : "r"(addr));
}

__device__ __forceinline__ void mma_f16(float* d, const uint32_t* a,
                                        const uint32_t* b) {
    asm volatile(
        "mma.sync.aligned.m16n8k16.row.col.f32.f16.f16.f32 "
        "{%0,%1,%2,%3}, {%4,%5,%6,%7}, {%8,%9}, {%0,%1,%2,%3};"
        : "+f"(d[0]), "+f"(d[1]), "+f"(d[2]), "+f"(d[3])
        : "r"(a[0]), "r"(a[1]), "r"(a[2]), "r"(a[3]), "r"(b[0]), "r"(b[1]));
}

__device__ __forceinline__ uint32_t h2u(__half2 h) {
    return *(uint32_t*)&h;
}

// ---------------------------------------------------------------------------
// K0: csr_zero — own kernel: all cursor zeroes visible before hist atomics.
// ---------------------------------------------------------------------------
__global__ void csr_zero_kernel() {
    int i = blockIdx.x * blockDim.x + threadIdx.x;
    if (i < 3 * N_NODES) g_cursor[i] = 0;
}

// ---------------------------------------------------------------------------
// K1: fused prep — cvt_x (x2 ILP) | cvt_w | cvt_w2 | csr_hist
// ---------------------------------------------------------------------------
#define NB_SPLITX 15000                  // 2 float4 per thread (strided)
#define SPLITX_STRIDE (NB_SPLITX * 256)  // 3.84M; total f4 elems = 7.68M
#define NB_SPLITW 2304
#define NB_SPLITW2 288
#define NB_HIST_PER 625
#define B_SPLITW  (NB_SPLITX)
#define B_SPLITW2 (B_SPLITW + NB_SPLITW)
#define B_HIST    (B_SPLITW2 + NB_SPLITW2)
#define NB_PREP   (B_HIST + 3 * NB_HIST_PER)

__global__ void __launch_bounds__(256)
prep_kernel(const float* __restrict__ x1, const float* __restrict__ x2,
            const float* __restrict__ x3, const float* __restrict__ W1,
            const float* __restrict__ W2,
            const int* __restrict__ s0, const int* __restrict__ s1,
            const int* __restrict__ s2) {
    const int bid = blockIdx.x;
    const int tid = threadIdx.x;

    if (bid < NB_SPLITX) {
#pragma unroll
        for (int r = 0; r < 2; r++) {
            int i = bid * 256 + tid + r * SPLITX_STRIDE;  // one float4
            const int per_view = N_NODES * (F_DIM / 4);
            const int view = i / per_view;
            const int rem  = i - view * per_view;
            const int row  = rem / (F_DIM / 4);
            const int kg   = rem - row * (F_DIM / 4);
            const float* X = (view == 0) ? x1 : (view == 1) ? x2 : x3;
            float4 f = ((const float4*)X)[rem];
            __half2 a = __float22half2_rn(make_float2(f.x, f.y));
            __half2 b = __float22half2_rn(make_float2(f.z, f.w));
            size_t off = ((size_t)view * PAD_ROWS + row) * F_DIM + kg * 4;
            *(uint2*)&g_xh[off] = make_uint2(h2u(a), h2u(b));
        }
    } else if (bid < B_SPLITW2) {
        int i = (bid - B_SPLITW) * 256 + tid;   // over 9*512*128, n fastest
        const int b = i / (F_DIM * H_DIM);
        const int rem = i - b * (F_DIM * H_DIM);
        const int k = rem / H_DIM;
        const int n = rem - k * H_DIM;
        g_wt[((size_t)b * H_DIM + n) * F_DIM + k] = __float2half_rn(W1[i]);
    } else if (bid < B_HIST) {
        int i = (bid - B_SPLITW2) * 256 + tid;  // over 9*128*64
        const int b = i / (H_DIM * C_DIM);
        const int rem = i - b * (H_DIM * C_DIM);
        const int k = rem / C_DIM;
        const int n = rem - k * C_DIM;
        g_wt2[((size_t)b * C_DIM + n) * H_DIM + k] = __float2half_rn(W2[i]);
    } else {
        const int rel = bid - B_HIST;
        const int a = rel / NB_HIST_PER;
        const int blk = rel - a * NB_HIST_PER;
        const int* __restrict__ s = (a == 0) ? s0 : (a == 1) ? s1 : s2;
        int* __restrict__ cur = g_cursor + a * N_NODES;
        const int base = blk * 1024 + tid;
#pragma unroll
        for (int k = 0; k < 4; k++)
            atomicAdd(&cur[__ldg(&s[base + k * 256])], 1);
    }
}

// ---------------------------------------------------------------------------
// K2: csr_scan — own kernel (3 blocks, 256 threads).
// ---------------------------------------------------------------------------
__global__ void __launch_bounds__(256) csr_scan_kernel() {
    const int a = blockIdx.x;
    __shared__ int s_warp[9];
    int* cnt = g_cursor + a * N_NODES;
    int* rp  = g_rowptr + a * RP_STRIDE;
    const int tid = threadIdx.x;
    const int lane = tid & 31;
    const int w = tid >> 5;
    int carry = 0;
    for (int base = 0; base < N_NODES; base += 1024) {
        const int idx = base + tid * 4;
        int v0 = 0, v1 = 0, v2 = 0, v3 = 0;
        if (idx + 3 < N_NODES) {
            int4 t = *(const int4*)&cnt[idx];
            v0 = t.x; v1 = t.y; v2 = t.z; v3 = t.w;
        } else {
            if (idx + 0 < N_NODES) v0 = cnt[idx + 0];
            if (idx + 1 < N_NODES) v1 = cnt[idx + 1];
            if (idx + 2 < N_NODES) v2 = cnt[idx + 2];
            if (idx + 3 < N_NODES) v3 = cnt[idx + 3];
        }
        const int tsum = v0 + v1 + v2 + v3;
        int sc = tsum;
#pragma unroll
        for (int o = 1; o < 32; o <<= 1) {
            int n = __shfl_up_sync(0xffffffff, sc, o);
            if (lane >= o) sc += n;
        }
        if (lane == 31) s_warp[w] = sc;
        __syncthreads();
        if (w == 0) {
            int x = (lane < 8) ? s_warp[lane] : 0;
#pragma unroll
            for (int o = 1; o < 8; o <<= 1) {
                int n = __shfl_up_sync(0xffffffff, x, o);
                if (lane >= o) x += n;
            }
            if (lane < 8) s_warp[lane] = x;
            if (lane == 7) s_warp[8] = x;
        }
        __syncthreads();
        const int warp_off = (w == 0) ? 0 : s_warp[w - 1];
        const int excl = carry + warp_off + (sc - tsum);
        const int p0 = excl, p1 = p0 + v0, p2 = p1 + v1, p3 = p2 + v2;
        if (idx + 3 < N_NODES) {
            *(int4*)&rp[idx]  = make_int4(p0, p1, p2, p3);
            *(int4*)&cnt[idx] = make_int4(p0, p1, p2, p3);
        } else {
            if (idx + 0 < N_NODES) { rp[idx + 0] = p0; cnt[idx + 0] = p0; }
            if (idx + 1 < N_NODES) { rp[idx + 1] = p1; cnt[idx + 1] = p1; }
            if (idx + 2 < N_NODES) { rp[idx + 2] = p2; cnt[idx + 2] = p2; }
            if (idx + 3 < N_NODES) { rp[idx + 3] = p3; cnt[idx + 3] = p3; }
        }
        carry += s_warp[8];
        __syncthreads();
    }
    if (tid == 0) rp[N_NODES] = carry;
}

// ---------------------------------------------------------------------------
// K3: GEMM1 (mma.sync fp16) with csr_fill piggybacked at the END of the grid
// (R11 had fill at front: fill's 2-block/SM smem limit serialized ~25us of
// pure fill before any gemm started; at the end it backfills the drain tail).
// grid: 1413 gemm blocks + 1875 fill blocks. 256 threads.
// ---------------------------------------------------------------------------
#define TILE_BYTES 16384                  // 128 rows x 128B
#define STAGE_BYTES (2 * TILE_BYTES)      // A + B
#define GSM_TOTAL (3 * STAGE_BYTES)       // 3 stages = 96KB
#define NB_GEMM1 (157 * 9)
#define NB_FILL (3 * NB_HIST_PER)

__global__ void __launch_bounds__(256, 2)
gemm1_mma_kernel(const int* __restrict__ s0, const int* __restrict__ s1,
                 const int* __restrict__ s2, const int* __restrict__ d0,
                 const int* __restrict__ d1, const int* __restrict__ d2,
                 const float* __restrict__ v0, const float* __restrict__ v1,
                 const float* __restrict__ v2) {
    if (blockIdx.x >= NB_GEMM1) {         // piggybacked fill blocks (grid tail)
        const int rel = blockIdx.x - NB_GEMM1;
        const int a = rel / NB_HIST_PER;
        const int blk = rel - a * NB_HIST_PER;
        const int*   __restrict__ s = (a == 0) ? s0 : (a == 1) ? s1 : s2;
        const int*   __restrict__ d = (a == 0) ? d0 : (a == 1) ? d1 : d2;
        const float* __restrict__ v = (a == 0) ? v0 : (a == 1) ? v1 : v2;
        int* __restrict__ cur = g_cursor + a * N_NODES;
        int2* __restrict__ eo = g_edge + (size_t)a * N_EDGES;
        const int base = blk * 1024 + threadIdx.x;
#pragma unroll
        for (int k = 0; k < 4; k++) {
            const int e = base + k * 256;
            const int ss = __ldg(&s[e]);
            const int dd = __ldg(&d[e]);
            const float vv = __ldg(&v[e]);
            int pos = atomicAdd(&cur[ss], 1);
            eo[pos] = make_int2(dd, __float_as_int(vv));
        }
        return;
    }
    extern __shared__ char smem[];
    const uint32_t sb = smem_u32(smem);
    const int tid = threadIdx.x;
    const int wid = tid >> 5;
    const int lane = tid & 31;
    const int gbid = blockIdx.x;
    const int tile = gbid % 157;
    const int b = gbid / 157;
    const int view = c_perm[b];
    const int rowBase = tile * 128;

    const int wm = wid >> 1;
    const int wn = wid & 1;

    const int arow_l = (lane & 15);
    const uint32_t akh = (uint32_t)(lane >> 4) * 16;
    const int brow_l = (lane & 7) + ((lane >> 4) << 3);
    const uint32_t bkh = (uint32_t)((lane >> 3) & 1) * 16;

    float cfrag[2][8][4];
#pragma unroll
    for (int mi = 0; mi < 2; mi++)
#pragma unroll
        for (int nj = 0; nj < 8; nj++)
#pragma unroll
            for (int q = 0; q < 4; q++) cfrag[mi][nj][q] = 0.f;

    const char* Abase = (const char*)(g_xh +
        ((size_t)view * PAD_ROWS + rowBase) * F_DIM);
    const char* Bbase = (const char*)(g_wt + (size_t)b * H_DIM * F_DIM);

    auto prefetch = [&](int c, int bufi) {
        const char* Asrc = Abase + c * 128;
        const char* Bsrc = Bbase + c * 128;
        const uint32_t Ab = sb + bufi * STAGE_BYTES;
        const uint32_t Bb = Ab + TILE_BYTES;
#pragma unroll
        for (int i = 0; i < 4; i++) {
            int idx = tid + i * 256;
            int row = idx >> 3;
            int ch  = idx & 7;
            uint32_t off = row * 128 + ch * 16;
            uint32_t sw = off ^ ((off >> 3) & 0x70);
            cp_async16(Ab + sw, Asrc + (size_t)row * (F_DIM * 2) + ch * 16);
            cp_async16(Bb + sw, Bsrc + (size_t)row * (F_DIM * 2) + ch * 16);
        }
        CP_COMMIT();
    };

    prefetch(0, 0);
    prefetch(1, 1);

    for (int it = 0; it < 8; it++) {
        const int bufi = it % 3;
        if (it < 6) {
            prefetch(it + 2, (it + 2) % 3);
            CP_WAIT(2);
        } else {
            CP_WAIT(0);
        }
        __syncthreads();

        const uint32_t Ab = sb + bufi * STAGE_BYTES;
        const uint32_t Bb = Ab + TILE_BYTES;

#pragma unroll
        for (int k16 = 0; k16 < 4; k16++) {
            const uint32_t kb = k16 * 32;
            uint32_t afrag[2][4];
#pragma unroll
            for (int mi = 0; mi < 2; mi++) {
                const int row = wm * 32 + mi * 16 + arow_l;
                const uint32_t addr =
                    Ab + row * 128 + ((kb + akh) ^ (uint32_t)((row & 7) << 4));
                ldsm_x4(afrag[mi][0], afrag[mi][1], afrag[mi][2], afrag[mi][3], addr);
            }
            uint32_t bfrag[8][2];
#pragma unroll
            for (int bj = 0; bj < 4; bj++) {
                const int row = wn * 64 + bj * 16 + brow_l;
                const uint32_t addr =
                    Bb + row * 128 + ((kb + bkh) ^ (uint32_t)((row & 7) << 4));
                uint32_t r0, r1, r2, r3;
                ldsm_x4(r0, r1, r2, r3, addr);
                bfrag[bj * 2 + 0][0] = r0; bfrag[bj * 2 + 0][1] = r1;
                bfrag[bj * 2 + 1][0] = r2; bfrag[bj * 2 + 1][1] = r3;
            }
#pragma unroll
            for (int mi = 0; mi < 2; mi++)
#pragma unroll
                for (int nj = 0; nj < 8; nj++)
                    mma_f16(cfrag[mi][nj], afrag[mi], bfrag[nj]);
        }
        __syncthreads();
    }

    // Epilogue: half table (self-term read from combo gc*3 in spmm1)
    __half* __restrict__ Couth = g_emb1h + (size_t)b * N_NODES * H_DIM;
    const int mrow0 = rowBase + wm * 32;
    const int ncol0 = wn * 64;
    const int lr = lane >> 2;
    const int lc = (lane & 3) * 2;
#pragma unroll
    for (int mi = 0; mi < 2; mi++) {
#pragma unroll
        for (int nj = 0; nj < 8; nj++) {
            const int r0 = mrow0 + mi * 16 + lr;
            const int cc = ncol0 + nj * 8 + lc;
            if (r0 < N_NODES)
                *(__half2*)&Couth[(size_t)r0 * H_DIM + cc] =
                    __float22half2_rn(make_float2(cfrag[mi][nj][0], cfrag[mi][nj][1]));
            if (r0 + 8 < N_NODES)
                *(__half2*)&Couth[(size_t)(r0 + 8) * H_DIM + cc] =
                    __float22half2_rn(make_float2(cfrag[mi][nj][2], cfrag[mi][nj][3]));
        }
    }
}

// ---------------------------------------------------------------------------
// GEMM2 (mma.sync fp16, single pass): emb2[b] = h[perm[b]] @ W2[b].
// 2 K-iterations, 2-stage cp.async. CTA tile 128x64.
// ---------------------------------------------------------------------------
#define T2_ABYTES 16384                   // 128 rows x 128B
#define T2_BBYTES 8192                    // 64 rows x 128B
#define T2_STAGE  (T2_ABYTES + T2_BBYTES)
#define G2SM_TOTAL (2 * T2_STAGE)         // 48KB

__global__ void __launch_bounds__(256, 2)
gemm2_mma_kernel() {
    extern __shared__ char smem[];
    const uint32_t sb = smem_u32(smem);
    const int tid = threadIdx.x;
    const int wid = tid >> 5;
    const int lane = tid & 31;
    const int tile = blockIdx.x;
    const int b = blockIdx.y;
    const int view = c_perm[b];
    const int rowBase = tile * 128;

    const int wm = wid >> 1;
    const int wn = wid & 1;

    const int arow_l = (lane & 15);
    const uint32_t akh = (uint32_t)(lane >> 4) * 16;
    const int brow_l = (lane & 7) + ((lane >> 4) << 3);
    const uint32_t bkh = (uint32_t)((lane >> 3) & 1) * 16;

    float cfrag[2][4][4];
#pragma unroll
    for (int mi = 0; mi < 2; mi++)
#pragma unroll
        for (int nj = 0; nj < 4; nj++)
#pragma unroll
            for (int q = 0; q < 4; q++) cfrag[mi][nj][q] = 0.f;

    const char* Abase = (const char*)(g_hh +
        ((size_t)view * PAD_ROWS + rowBase) * H_DIM);
    const char* Bbase = (const char*)(g_wt2 + (size_t)b * C_DIM * H_DIM);

    auto prefetch = [&](int c, int bufi) {
        const char* Asrc = Abase + c * 128;
        const char* Bsrc = Bbase + c * 128;
        const uint32_t Ab = sb + bufi * T2_STAGE;
        const uint32_t Bb = Ab + T2_ABYTES;
#pragma unroll
        for (int i = 0; i < 4; i++) {
            int idx = tid + i * 256;
            int row = idx >> 3;
            int ch  = idx & 7;
            uint32_t off = row * 128 + ch * 16;
            uint32_t sw = off ^ ((off >> 3) & 0x70);
            cp_async16(Ab + sw, Asrc + (size_t)row * (H_DIM * 2) + ch * 16);
        }
#pragma unroll
        for (int i = 0; i < 2; i++) {
            int idx = tid + i * 256;
            int row = idx >> 3;
            int ch  = idx & 7;
            uint32_t off = row * 128 + ch * 16;
            uint32_t sw = off ^ ((off >> 3) & 0x70);
            cp_async16(Bb + sw, Bsrc + (size_t)row * (H_DIM * 2) + ch * 16);
        }
        CP_COMMIT();
    };

    prefetch(0, 0);
    prefetch(1, 1);

#pragma unroll
    for (int it = 0; it < 2; it++) {
        if (it == 0) { CP_WAIT(1); } else { CP_WAIT(0); }
        __syncthreads();

        const uint32_t Ab = sb + it * T2_STAGE;
        const uint32_t Bb = Ab + T2_ABYTES;

#pragma unroll
        for (int k16 = 0; k16 < 4; k16++) {
            const uint32_t kb = k16 * 32;
            uint32_t afrag[2][4];
#pragma unroll
            for (int mi = 0; mi < 2; mi++) {
                const int row = wm * 32 + mi * 16 + arow_l;
                const uint32_t addr =
                    Ab + row * 128 + ((kb + akh) ^ (uint32_t)((row & 7) << 4));
                ldsm_x4(afrag[mi][0], afrag[mi][1], afrag[mi][2], afrag[mi][3], addr);
            }
            uint32_t bfrag[4][2];
#pragma unroll
            for (int bj = 0; bj < 2; bj++) {
                const int row = wn * 32 + bj * 16 + brow_l;
                const uint32_t addr =
                    Bb + row * 128 + ((kb + bkh) ^ (uint32_t)((row & 7) << 4));
                uint32_t r0, r1, r2, r3;
                ldsm_x4(r0, r1, r2, r3, addr);
                bfrag[bj * 2 + 0][0] = r0; bfrag[bj * 2 + 0][1] = r1;
                bfrag[bj * 2 + 1][0] = r2; bfrag[bj * 2 + 1][1] = r3;
            }
#pragma unroll
            for (int mi = 0; mi < 2; mi++)
#pragma unroll
                for (int nj = 0; nj < 4; nj++)
                    mma_f16(cfrag[mi][nj], afrag[mi], bfrag[nj]);
        }
        __syncthreads();
    }

    __half* __restrict__ Couth = g_emb2h + (size_t)b * N_NODES * C_DIM;
    const int mrow0 = rowBase + wm * 32;
    const int ncol0 = wn * 32;
    const int lr = lane >> 2;
    const int lc = (lane & 3) * 2;
#pragma unroll
    for (int mi = 0; mi < 2; mi++) {
#pragma unroll
        for (int nj = 0; nj < 4; nj++) {
            const int r0 = mrow0 + mi * 16 + lr;
            const int cc = ncol0 + nj * 8 + lc;
            if (r0 < N_NODES)
                *(__half2*)&Couth[(size_t)r0 * C_DIM + cc] =
                    __float22half2_rn(make_float2(cfrag[mi][nj][0], cfrag[mi][nj][1]));
            if (r0 + 8 < N_NODES)
                *(__half2*)&Couth[(size_t)(r0 + 8) * C_DIM + cc] =
                    __float22half2_rn(make_float2(cfrag[mi][nj][2], cfrag[mi][nj][3]));
        }
    }
}

// ---------------------------------------------------------------------------
// Fused SpMM layer 1: block per node, 64 threads (half2 column pair each).
// Self-term from fp16 combo table (gc*3). Emits h as a single fp16 plane.
// ---------------------------------------------------------------------------
__global__ void __launch_bounds__(64) spmm1_kernel(const float* __restrict__ wv1,
                                                   const float* __restrict__ b1) {
    const int i = blockIdx.x;
    const int t = threadIdx.x;
    const int comboOf[3][3] = {{0, 1, 2}, {4, 3, 5}, {7, 8, 6}};

    float2 agg[3] = {{0.f, 0.f}, {0.f, 0.f}, {0.f, 0.f}};

#pragma unroll
    for (int a = 0; a < 3; a++) {
        const int start = g_rowptr[a * RP_STRIDE + i];
        const int end   = g_rowptr[a * RP_STRIDE + i + 1];
        const __half2* __restrict__ T0 =
            (const __half2*)g_emb1h + (size_t)comboOf[0][a] * N_NODES * (H_DIM / 2);
        const __half2* __restrict__ T1 =
            (const __half2*)g_emb1h + (size_t)comboOf[1][a] * N_NODES * (H_DIM / 2);
        const __half2* __restrict__ T2 =
            (const __half2*)g_emb1h + (size_t)comboOf[2][a] * N_NODES * (H_DIM / 2);
        const int2* __restrict__ ew = g_edge + (size_t)a * N_EDGES;

        float2 p0 = {0.f, 0.f}, p1 = {0.f, 0.f}, p2 = {0.f, 0.f};
        for (int e = start; e < end; e++) {
            const int2 cw = __ldg(&ew[e]);
            const float w = __int_as_float(cw.y);
            const size_t o = (size_t)cw.x * (H_DIM / 2) + t;
            float2 v0 = __half22float2(__ldg(&T0[o]));
            float2 v1 = __half22float2(__ldg(&T1[o]));
            float2 v2 = __half22float2(__ldg(&T2[o]));
            p0.x += w * v0.x; p0.y += w * v0.y;
            p1.x += w * v1.x; p1.y += w * v1.y;
            p2.x += w * v2.x; p2.y += w * v2.y;
        }
        float w0 = wv1[comboOf[0][a]], w1 = wv1[comboOf[1][a]], w2 = wv1[comboOf[2][a]];
        agg[0].x += w0 * p0.x; agg[0].y += w0 * p0.y;
        agg[1].x += w1 * p1.x; agg[1].y += w1 * p1.y;
        agg[2].x += w2 * p2.x; agg[2].y += w2 * p2.y;
    }

    const size_t NH2 = (size_t)N_NODES * (H_DIM / 2);
    const size_t PH = (size_t)PAD_ROWS * H_DIM;
    const size_t so = (size_t)i * (H_DIM / 2) + t;
#pragma unroll
    for (int gc = 0; gc < 3; gc++) {
        float2 self = __half22float2(
            __ldg((const __half2*)g_emb1h + (size_t)(gc * 3) * NH2 + so));
        float2 bias = *(const float2*)&b1[gc * H_DIM + 2 * t];
        float hx = fmaxf(self.x + 1.01f * agg[gc].x + bias.x, 0.f);
        float hy = fmaxf(self.y + 1.01f * agg[gc].y + bias.y, 0.f);
        const size_t base = (size_t)gc * PH + (size_t)i * H_DIM + 2 * t;
        *(uint32_t*)&g_hh[base] = h2u(__float22half2_rn(make_float2(hx, hy)));
    }
}

// ---------------------------------------------------------------------------
// Fused SpMM layer 2 + final: block per node, 32 threads.
// ---------------------------------------------------------------------------
__global__ void __launch_bounds__(32) spmm2_kernel(const float* __restrict__ wv2,
                                                   const float* __restrict__ b2,
                                                   float* __restrict__ out) {
    const int i = blockIdx.x;
    const int t = threadIdx.x;
    const int comboOf[3][3] = {{0, 1, 2}, {4, 3, 5}, {7, 8, 6}};

    float2 agg[3] = {{0.f, 0.f}, {0.f, 0.f}, {0.f, 0.f}};

#pragma unroll
    for (int a = 0; a < 3; a++) {
        const int start = g_rowptr[a * RP_STRIDE + i];
        const int end   = g_rowptr[a * RP_STRIDE + i + 1];
        const __half2* __restrict__ T0 =
            (const __half2*)g_emb2h + (size_t)comboOf[0][a] * N_NODES * (C_DIM / 2);
        const __half2* __restrict__ T1 =
            (const __half2*)g_emb2h + (size_t)comboOf[1][a] * N_NODES * (C_DIM / 2);
        const __half2* __restrict__ T2 =
            (const __half2*)g_emb2h + (size_t)comboOf[2][a] * N_NODES * (C_DIM / 2);
        const int2* __restrict__ ew = g_edge + (size_t)a * N_EDGES;

        float2 p0 = {0.f, 0.f}, p1 = {0.f, 0.f}, p2 = {0.f, 0.f};
        for (int e = start; e < end; e++) {
            const int2 cw = __ldg(&ew[e]);
            const float w = __int_as_float(cw.y);
            const size_t o = (size_t)cw.x * (C_DIM / 2) + t;
            float2 v0 = __half22float2(__ldg(&T0[o]));
            float2 v1 = __half22float2(__ldg(&T1[o]));
            float2 v2 = __half22float2(__ldg(&T2[o]));
            p0.x += w * v0.x; p0.y += w * v0.y;
            p1.x += w * v1.x; p1.y += w * v1.y;
            p2.x += w * v2.x; p2.y += w * v2.y;
        }
        float w0 = wv2[comboOf[0][a]], w1 = wv2[comboOf[1][a]], w2 = wv2[comboOf[2][a]];
        agg[0].x += w0 * p0.x; agg[0].y += w0 * p0.y;
        agg[1].x += w1 * p1.x; agg[1].y += w1 * p1.y;
        agg[2].x += w2 * p2.x; agg[2].y += w2 * p2.y;
    }

    const size_t NC2 = (size_t)N_NODES * (C_DIM / 2);
    const size_t so = (size_t)i * (C_DIM / 2) + t;
    float2 ysum = {0.f, 0.f};
#pragma unroll
    for (int gc = 0; gc < 3; gc++) {
        float2 self = __half22float2(
            __ldg((const __half2*)g_emb2h + (size_t)(gc * 3) * NC2 + so));
        float2 bias = *(const float2*)&b2[gc * C_DIM + 2 * t];
        ysum.x += fmaxf(self.x + 1.01f * agg[gc].x + bias.x, 0.f);
        ysum.y += fmaxf(self.y + 1.01f * agg[gc].y + bias.y, 0.f);
    }
    const size_t oi = (size_t)i * C_DIM + 2 * t;
    *(float2*)&out[oi] = make_float2(fabsf(ysum.x * (1.f / 3.f)),
                                     fabsf(ysum.y * (1.f / 3.f)));
}

// ---------------------------------------------------------------------------
extern "C" void kernel_launch(void* const* d_in, const int* in_sizes, int n_in,
                              void* d_out, int out_size) {
    const float* x1 = (const float*)d_in[0];
    const float* x2 = (const float*)d_in[1];
    const float* x3 = (const float*)d_in[2];
    const int*   s0 = (const int*)d_in[3];
    const int*   d0 = (const int*)d_in[4];
    const float* v0 = (const float*)d_in[5];
    const int*   s1 = (const int*)d_in[6];
    const int*   d1 = (const int*)d_in[7];
    const float* v1 = (const float*)d_in[8];
    const int*   s2 = (const int*)d_in[9];
    const int*   d2 = (const int*)d_in[10];
    const float* v2 = (const float*)d_in[11];
    const float* W1  = (const float*)d_in[12];
    const float* wv1 = (const float*)d_in[13];
    const float* b1  = (const float*)d_in[14];
    const float* W2  = (const float*)d_in[15];
    const float* wv2 = (const float*)d_in[16];
    const float* b2  = (const float*)d_in[17];
    float* out = (float*)d_out;

    cudaFuncSetAttribute(gemm1_mma_kernel,
                         cudaFuncAttributeMaxDynamicSharedMemorySize, GSM_TOTAL);
    cudaFuncSetAttribute(gemm2_mma_kernel,
                         cudaFuncAttributeMaxDynamicSharedMemorySize, G2SM_TOTAL);

    // K0: zero cursors — separate launch, MUST complete before hist atomics
    csr_zero_kernel<<<(3 * N_NODES + 255) / 256, 256>>>();
    // K1: fused converts + histogram
    prep_kernel<<<NB_PREP, 256>>>(x1, x2, x3, W1, W2, s0, s1, s2);
    // K2: scan — own kernel (must precede the fill blocks in gemm1)
    csr_scan_kernel<<<3, 256>>>();
    // K3: gemm1 with fill blocks piggybacked at grid tail
    gemm1_mma_kernel<<<NB_GEMM1 + NB_FILL, 256, GSM_TOTAL>>>(
        s0, s1, s2, d0, d1, d2, v0, v1, v2);
    // K4-K6
    spmm1_kernel<<<N_NODES, 64>>>(wv1, b1);
    gemm2_mma_kernel<<<dim3(157, 9), 256, G2SM_TOTAL>>>();
    spmm2_kernel<<<N_NODES, 32>>>(wv2, b2, out);
}